// round 2
// baseline (speedup 1.0000x reference)
#include <cuda_runtime.h>
#include <math.h>

#define NN   50000
#define EE   800000
#define DD   128
#define LL   3
#define OUTD 40

// ---------------- scratch (device globals; no allocation allowed) ----------------
__device__ float g_x[NN * DD];
__device__ float g_h[NN * DD];
__device__ float g_xh[NN * DD];
__device__ float g_xl[NN * DD];
__device__ float g_agg[NN * DD];
__device__ float g_xlocal[NN * DD];
__device__ float g_as[NN];
__device__ float g_ad[NN];
__device__ int   g_deg[NN];
__device__ int   g_fill[NN];
__device__ int   g_rowptr[NN + 1];
__device__ int   g_esrc[EE];
__device__ int   g_src[EE];
__device__ int   g_dst[EE];

// ---------------- edge decode: handle int32 OR int64 edge_index ----------------
// If the buffer is int64 (little-endian, values in [0, 2^31)), every odd int32
// word is 0. Random node ids make a false positive vanishingly unlikely.
__global__ void decode_k(const int* __restrict__ ei32) {
    bool is64 = (ei32[1] == 0 && ei32[3] == 0 && ei32[5] == 0 && ei32[7] == 0);
    int e = blockIdx.x * blockDim.x + threadIdx.x;
    if (e < EE) {
        int s, d;
        if (is64) {
            s = ei32[2 * (size_t)e];
            d = ei32[2 * ((size_t)EE + e)];
        } else {
            s = ei32[e];
            d = ei32[EE + e];
        }
        g_src[e] = s;
        g_dst[e] = d;
    }
}

// ---------------- CSR build ----------------
__global__ void zero_k() {
    int i = blockIdx.x * blockDim.x + threadIdx.x;
    if (i < NN) { g_deg[i] = 0; g_fill[i] = 0; }
}

__global__ void deg_k() {
    int e = blockIdx.x * blockDim.x + threadIdx.x;
    if (e < EE) atomicAdd(&g_deg[g_dst[e]], 1);
}

__global__ void scan_k() {
    __shared__ int sh[1024];
    int t = threadIdx.x;
    const int chunk = (NN + 1023) / 1024;
    int base = t * chunk;
    int s = 0;
    for (int i = 0; i < chunk; i++) {
        int idx = base + i;
        if (idx < NN) s += g_deg[idx];
    }
    sh[t] = s;
    __syncthreads();
    for (int off = 1; off < 1024; off <<= 1) {
        int add = (t >= off) ? sh[t - off] : 0;
        __syncthreads();
        sh[t] += add;
        __syncthreads();
    }
    int run = sh[t] - s;  // exclusive prefix for this chunk
    for (int i = 0; i < chunk; i++) {
        int idx = base + i;
        if (idx < NN) { g_rowptr[idx] = run; run += g_deg[idx]; }
    }
    if (t == 0) g_rowptr[NN] = EE;
}

__global__ void scat_k() {
    int e = blockIdx.x * blockDim.x + threadIdx.x;
    if (e < EE) {
        int d = g_dst[e];
        int p = g_rowptr[d] + atomicAdd(&g_fill[d], 1);
        g_esrc[p] = g_src[e];
    }
}

// ---------------- GEMM: C[N,NCOL] = A[N,128] @ W[128,NCOL] (+bias, +relu) ----------------
template <int NCOL, bool RELU, bool BIAS>
__global__ void gemm_k(const float* __restrict__ A, const float* __restrict__ W,
                       const float* __restrict__ bias, float* __restrict__ C) {
    constexpr int ROWS = 32;
    constexpr int KT   = 32;
    __shared__ float sA[ROWS][DD];
    __shared__ float sW[KT][NCOL];
    int tid  = threadIdx.x;             // 256 threads
    int row0 = blockIdx.x * ROWS;

    // Load A tile: 32 rows x 128 cols = 1024 float4, 4 per thread
    {
        const float4* Af  = (const float4*)A;
        float4*       sAf = (float4*)sA;
#pragma unroll
        for (int i = 0; i < 4; i++) {
            int idx = tid + i * 256;        // 0..1023
            int r = idx >> 5, c = idx & 31; // row in tile, float4-col
            float4 v = make_float4(0.f, 0.f, 0.f, 0.f);
            if (row0 + r < NN) v = Af[(size_t)(row0 + r) * 32 + c];
            sAf[idx] = v;
        }
    }

    int tx = tid & 31, ty = tid >> 5;   // ty: 0..7
    const int col = tx * 4;
    float acc[4][4];
#pragma unroll
    for (int i = 0; i < 4; i++)
#pragma unroll
        for (int j = 0; j < 4; j++) acc[i][j] = 0.f;

    for (int kt = 0; kt < DD; kt += KT) {
        __syncthreads();
        {
            const float4* Wf  = (const float4*)(W + kt * NCOL);
            float4*       sWf = (float4*)sW;
            constexpr int T4 = KT * NCOL / 4;
            for (int i = tid; i < T4; i += 256) sWf[i] = Wf[i];
        }
        __syncthreads();
#pragma unroll
        for (int k = 0; k < KT; k++) {
            float4 w = make_float4(0.f, 0.f, 0.f, 0.f);
            if (col < NCOL) w = *(const float4*)&sW[k][col];
#pragma unroll
            for (int i = 0; i < 4; i++) {
                float a = sA[ty + i * 8][kt + k];
                acc[i][0] += a * w.x;
                acc[i][1] += a * w.y;
                acc[i][2] += a * w.z;
                acc[i][3] += a * w.w;
            }
        }
    }

    if (col < NCOL) {
        float4 bv = make_float4(0.f, 0.f, 0.f, 0.f);
        if (BIAS) bv = *(const float4*)&bias[col];
#pragma unroll
        for (int i = 0; i < 4; i++) {
            int row = row0 + ty + i * 8;
            if (row < NN) {
                float4 o;
                o.x = acc[i][0] + bv.x;
                o.y = acc[i][1] + bv.y;
                o.z = acc[i][2] + bv.z;
                o.w = acc[i][3] + bv.w;
                if (RELU) {
                    o.x = fmaxf(o.x, 0.f); o.y = fmaxf(o.y, 0.f);
                    o.z = fmaxf(o.z, 0.f); o.w = fmaxf(o.w, 0.f);
                }
                *(float4*)&C[(size_t)row * NCOL + col] = o;
            }
        }
    }
}

// ---------------- attention logits per node ----------------
__global__ void attn_k(const float* __restrict__ xh,
                       const float* __restrict__ asv, const float* __restrict__ adv) {
    int warp = (blockIdx.x * blockDim.x + threadIdx.x) >> 5;
    int lane = threadIdx.x & 31;
    if (warp >= NN) return;
    float4 v = ((const float4*)(xh + (size_t)warp * DD))[lane];
    float4 a = ((const float4*)asv)[lane];
    float4 d = ((const float4*)adv)[lane];
    float s = v.x * a.x + v.y * a.y + v.z * a.z + v.w * a.w;
    float t = v.x * d.x + v.y * d.y + v.z * d.z + v.w * d.w;
#pragma unroll
    for (int o = 16; o; o >>= 1) {
        s += __shfl_xor_sync(0xFFFFFFFFu, s, o);
        t += __shfl_xor_sync(0xFFFFFFFFu, t, o);
    }
    if (lane == 0) { g_as[warp] = s; g_ad[warp] = t; }
}

// ---------------- GAT softmax-aggregate: warp per destination node ----------------
__global__ void agg_k(const float* __restrict__ xh) {
    int n    = (blockIdx.x * blockDim.x + threadIdx.x) >> 5;
    int lane = threadIdx.x & 31;
    if (n >= NN) return;
    int s0 = g_rowptr[n], s1 = g_rowptr[n + 1];
    float adn = g_ad[n];

    // pass 1: max logit
    float m = -1e30f;
    for (int i = s0 + lane; i < s1; i += 32) {
        int s  = g_esrc[i];
        float e = g_as[s] + adn;
        e = e > 0.f ? e : 0.2f * e;
        m = fmaxf(m, e);
    }
#pragma unroll
    for (int o = 16; o; o >>= 1) m = fmaxf(m, __shfl_xor_sync(0xFFFFFFFFu, m, o));

    // pass 2: denom
    float den = 0.f;
    for (int i = s0 + lane; i < s1; i += 32) {
        int s  = g_esrc[i];
        float e = g_as[s] + adn;
        e = e > 0.f ? e : 0.2f * e;
        den += __expf(e - m);
    }
#pragma unroll
    for (int o = 16; o; o >>= 1) den += __shfl_xor_sync(0xFFFFFFFFu, den, o);
    float inv = 1.f / (den + 1e-16f);

    // pass 3: weighted gather of xh[src]
    float4 acc = make_float4(0.f, 0.f, 0.f, 0.f);
    for (int base = s0; base < s1; base += 32) {
        int idx = base + lane;
        float w = 0.f;
        int   s = 0;
        if (idx < s1) {
            s = g_esrc[idx];
            float e = g_as[s] + adn;
            e = e > 0.f ? e : 0.2f * e;
            w = __expf(e - m) * inv;
        }
        int cnt = min(32, s1 - base);
        for (int j = 0; j < cnt; j++) {
            float wj = __shfl_sync(0xFFFFFFFFu, w, j);
            int   sj = __shfl_sync(0xFFFFFFFFu, s, j);
            float4 v = ((const float4*)(xh + (size_t)sj * DD))[lane];
            acc.x += wj * v.x; acc.y += wj * v.y;
            acc.z += wj * v.z; acc.w += wj * v.w;
        }
    }
    ((float4*)(g_agg + (size_t)n * DD))[lane] = acc;
}

// ---------------- fused pointwise: relu + gate + layernorm + residual accumulate ----------------
__global__ void fuse_k(const float* __restrict__ xlbuf, const float* __restrict__ hbuf,
                       const float* __restrict__ lng, const float* __restrict__ lnb,
                       const float* __restrict__ betas, int first) {
    int n    = (blockIdx.x * blockDim.x + threadIdx.x) >> 5;
    int lane = threadIdx.x & 31;
    if (n >= NN) return;
    size_t off = (size_t)n * DD;

    float4 ag = ((const float4*)(g_agg + off))[lane];
    float4 xl = ((const float4*)(xlbuf + off))[lane];
    float4 xn;
    xn.x = fmaxf(ag.x + xl.x, 0.f);
    xn.y = fmaxf(ag.y + xl.y, 0.f);
    xn.z = fmaxf(ag.z + xl.z, 0.f);
    xn.w = fmaxf(ag.w + xl.w, 0.f);

    float4 hh = ((const float4*)(hbuf + off))[lane];
    float4 t;
    t.x = hh.x * xn.x; t.y = hh.y * xn.y; t.z = hh.z * xn.z; t.w = hh.w * xn.w;

    float sum = t.x + t.y + t.z + t.w;
#pragma unroll
    for (int o = 16; o; o >>= 1) sum += __shfl_xor_sync(0xFFFFFFFFu, sum, o);
    float mu = sum * (1.f / 128.f);

    float4 dc;
    dc.x = t.x - mu; dc.y = t.y - mu; dc.z = t.z - mu; dc.w = t.w - mu;
    float ss = dc.x * dc.x + dc.y * dc.y + dc.z * dc.z + dc.w * dc.w;
#pragma unroll
    for (int o = 16; o; o >>= 1) ss += __shfl_xor_sync(0xFFFFFFFFu, ss, o);
    float rs = rsqrtf(ss * (1.f / 128.f) + 1e-5f);

    float4 g  = ((const float4*)lng)[lane];
    float4 b  = ((const float4*)lnb)[lane];
    float4 be = ((const float4*)betas)[lane];
    be.x = 1.f / (1.f + __expf(-be.x));
    be.y = 1.f / (1.f + __expf(-be.y));
    be.z = 1.f / (1.f + __expf(-be.z));
    be.w = 1.f / (1.f + __expf(-be.w));

    float4 y;
    y.x = dc.x * rs * g.x + b.x;
    y.y = dc.y * rs * g.y + b.y;
    y.z = dc.z * rs * g.z + b.z;
    y.w = dc.w * rs * g.w + b.w;

    float4 xo;
    xo.x = (1.f - be.x) * y.x + be.x * xn.x;
    xo.y = (1.f - be.y) * y.y + be.y * xn.y;
    xo.z = (1.f - be.z) * y.z + be.z * xn.z;
    xo.w = (1.f - be.w) * y.w + be.w * xn.w;

    ((float4*)(g_x + off))[lane] = xo;
    if (first) {
        ((float4*)(g_xlocal + off))[lane] = xo;
    } else {
        float4 p = ((const float4*)(g_xlocal + off))[lane];
        p.x += xo.x; p.y += xo.y; p.z += xo.z; p.w += xo.w;
        ((float4*)(g_xlocal + off))[lane] = p;
    }
}

// ---------------- host ----------------
extern "C" void kernel_launch(void* const* d_in, const int* in_sizes, int n_in,
                              void* d_out, int out_size) {
    const float* x       = (const float*)d_in[0];
    const int*   ei32    = (const int*)d_in[1];   // int32 or int64; decoded on device
    const float* W_in    = (const float*)d_in[2];
    const float* b_in    = (const float*)d_in[3];
    const float* W_h     = (const float*)d_in[4];
    const float* b_h     = (const float*)d_in[5];
    const float* W_gat   = (const float*)d_in[6];
    const float* att_src = (const float*)d_in[7];
    const float* att_dst = (const float*)d_in[8];
    const float* W_l     = (const float*)d_in[9];
    const float* b_l     = (const float*)d_in[10];
    const float* ln_g    = (const float*)d_in[11];
    const float* ln_b    = (const float*)d_in[12];
    const float* betas   = (const float*)d_in[13];
    const float* W_pred  = (const float*)d_in[14];
    const float* b_pred  = (const float*)d_in[15];
    float*       out     = (float*)d_out;

    float *px, *ph, *pxh, *pxl, *pxloc;
    cudaGetSymbolAddress((void**)&px,    g_x);
    cudaGetSymbolAddress((void**)&ph,    g_h);
    cudaGetSymbolAddress((void**)&pxh,   g_xh);
    cudaGetSymbolAddress((void**)&pxl,   g_xl);
    cudaGetSymbolAddress((void**)&pxloc, g_xlocal);

    dim3 gE((EE + 255) / 256);
    dim3 gN((NN + 255) / 256);
    dim3 gW((NN + 7) / 8);     // warp-per-node kernels, 256 thr = 8 warps
    dim3 gG((NN + 31) / 32);   // GEMM: 32 rows per block

    // edge decode + CSR by destination
    decode_k<<<gE, 256>>>(ei32);
    zero_k<<<gN, 256>>>();
    deg_k<<<gE, 256>>>();
    scan_k<<<1, 1024>>>();
    scat_k<<<gE, 256>>>();

    // input projection
    gemm_k<128, false, true><<<gG, 256>>>(x, W_in, b_in, px);

    for (int i = 0; i < LL; i++) {
        gemm_k<128, true,  true ><<<gG, 256>>>(px, W_h   + i * DD * DD, b_h + i * DD, ph);
        gemm_k<128, false, false><<<gG, 256>>>(px, W_gat + i * DD * DD, nullptr,      pxh);
        attn_k<<<gW, 256>>>(pxh, att_src + i * DD, att_dst + i * DD);
        gemm_k<128, false, true ><<<gG, 256>>>(px, W_l   + i * DD * DD, b_l + i * DD, pxl);
        agg_k<<<gW, 256>>>(pxh);
        fuse_k<<<gW, 256>>>(pxl, ph, ln_g + i * DD, ln_b + i * DD, betas + i * DD, i == 0);
    }

    gemm_k<OUTD, false, true><<<gG, 256>>>(pxloc, W_pred, b_pred, out);
}

// round 4
// speedup vs baseline: 1.0067x; 1.0067x over previous
#include <cuda_runtime.h>
#include <math.h>
#include <stdint.h>

#define NN   50000
#define EE   800000
#define DD   128
#define LL   3
#define OUTD 40
#define SB   512
#define NSB  ((NN + SB - 1) / SB)   // 98

// ---------------- scratch (device globals; no allocation allowed) ----------------
__device__ float g_x[NN * DD];
__device__ float g_h[NN * DD];
__device__ float g_xh[NN * DD];
__device__ float g_xl[NN * DD];
__device__ float g_agg[NN * DD];
__device__ float g_xlocal[NN * DD];
__device__ float g_as[NN];
__device__ float g_ad[NN];
__device__ int   g_deg[NN];
__device__ int   g_fill[NN];
__device__ int   g_rowptr[NN + 1];
__device__ int   g_esrc[EE];
__device__ int   g_src[EE];
__device__ int   g_dst[EE];
__device__ int   g_bsum[NSB];
__device__ int   g_boff[128];

// ---------------- edge decode: handle int32 OR int64 edge_index ----------------
__global__ void decode_k(const int* __restrict__ ei32) {
    bool is64 = (ei32[1] == 0 && ei32[3] == 0 && ei32[5] == 0 && ei32[7] == 0);
    int e = blockIdx.x * blockDim.x + threadIdx.x;
    if (e < EE) {
        int s, d;
        if (is64) {
            s = ei32[2 * (size_t)e];
            d = ei32[2 * ((size_t)EE + e)];
        } else {
            s = ei32[e];
            d = ei32[EE + e];
        }
        g_src[e] = s;
        g_dst[e] = d;
    }
}

// ---------------- CSR build ----------------
__global__ void zero_k() {
    int i = blockIdx.x * blockDim.x + threadIdx.x;
    if (i < NN) { g_deg[i] = 0; g_fill[i] = 0; }
}

__global__ void deg_k() {
    int e = blockIdx.x * blockDim.x + threadIdx.x;
    if (e < EE) atomicAdd(&g_deg[g_dst[e]], 1);
}

__global__ void pscan_k() {
    __shared__ int sh[SB];
    int t = threadIdx.x;
    int i = blockIdx.x * SB + t;
    int v = (i < NN) ? g_deg[i] : 0;
    sh[t] = v;
    __syncthreads();
    for (int o = 1; o < SB; o <<= 1) {
        int a = (t >= o) ? sh[t - o] : 0;
        __syncthreads();
        sh[t] += a;
        __syncthreads();
    }
    if (i < NN) g_rowptr[i] = sh[t] - v;
    if (t == SB - 1) g_bsum[blockIdx.x] = sh[t];
}

__global__ void bscan_k() {
    __shared__ int sh[128];
    int t = threadIdx.x;
    int v = (t < NSB) ? g_bsum[t] : 0;
    sh[t] = v;
    __syncthreads();
    for (int o = 1; o < 128; o <<= 1) {
        int a = (t >= o) ? sh[t - o] : 0;
        __syncthreads();
        sh[t] += a;
        __syncthreads();
    }
    g_boff[t] = sh[t] - v;
}

__global__ void addoff_k() {
    int i = blockIdx.x * blockDim.x + threadIdx.x;
    if (i < NN) g_rowptr[i] += g_boff[i / SB];
    if (i == 0) g_rowptr[NN] = EE;
}

__global__ void scat_k() {
    int e = blockIdx.x * blockDim.x + threadIdx.x;
    if (e < EE) {
        int d = g_dst[e];
        int p = g_rowptr[d] + atomicAdd(&g_fill[d], 1);
        g_esrc[p] = g_src[e];
    }
}

// ---------------- 3xTF32 split-precision tensor-core GEMM ----------------
// C[N,128] = A[N,128] @ W[128,128], near-fp32 accuracy:
//   A = Ah + Al, W = Wh + Wl (tf32 splits); C ≈ Ah*Wh + Ah*Wl + Al*Wh
// grid.x over 128-row tiles, grid.y over up to 3 weight matrices sharing A.
// Block: 256 threads = 8 warps (4 in M x 2 in N). Warp tile 32x64.
struct GemmArgs {
    const float* W[3];
    const float* bias[3];
    float*       out[3];
    int          epi[3];    // 0 = none, 1 = bias, 2 = bias+relu
};

__device__ __forceinline__ float to_tf32(float v) {
    uint32_t r;
    asm("cvt.rna.tf32.f32 %0, %1;" : "=r"(r) : "f"(v));
    return __uint_as_float(r);
}

__global__ __launch_bounds__(256)
void mma_gemm_k(const float* __restrict__ A, GemmArgs args) {
    constexpr int KC = 16;
    __shared__ float sAh[KC][132];   // A^T hi: [k][m]
    __shared__ float sAl[KC][132];   // A^T lo
    __shared__ float sWh[KC][132];   // W hi:   [k][n]
    __shared__ float sWl[KC][132];   // W lo

    const int tid  = threadIdx.x;
    const int lane = tid & 31;
    const int wid  = tid >> 5;
    const int wm   = (wid >> 1) * 32;
    const int wn   = (wid & 1) * 64;
    const int row0 = blockIdx.x * 128;
    const int w    = blockIdx.y;

    const float4* Af = (const float4*)A;
    const float4* Wf = (const float4*)args.W[w];

    const int ar = lane >> 2;   // 0..7
    const int ac = lane & 3;    // 0..3

    float acc[2][8][4];
#pragma unroll
    for (int i = 0; i < 2; i++)
#pragma unroll
        for (int j = 0; j < 8; j++)
#pragma unroll
            for (int c = 0; c < 4; c++) acc[i][j][c] = 0.f;

    for (int kc = 0; kc < DD; kc += KC) {
        // ---- stage A chunk transposed + split: 128 rows x 16 k ----
#pragma unroll
        for (int t = tid; t < 512; t += 256) {
            int m = t >> 2, kq = t & 3;
            int row = row0 + m;
            float4 v = make_float4(0.f, 0.f, 0.f, 0.f);
            if (row < NN) v = Af[(size_t)row * 32 + (kc >> 2) + kq];
            int kb = kq * 4;
            float h;
            h = to_tf32(v.x); sAh[kb + 0][m] = h; sAl[kb + 0][m] = to_tf32(v.x - h);
            h = to_tf32(v.y); sAh[kb + 1][m] = h; sAl[kb + 1][m] = to_tf32(v.y - h);
            h = to_tf32(v.z); sAh[kb + 2][m] = h; sAl[kb + 2][m] = to_tf32(v.z - h);
            h = to_tf32(v.w); sAh[kb + 3][m] = h; sAl[kb + 3][m] = to_tf32(v.w - h);
        }
        // ---- stage W chunk + split: 16 k x 128 n ----
#pragma unroll
        for (int t = tid; t < 512; t += 256) {
            int k = t >> 5, nq = t & 31;
            float4 v = Wf[(size_t)(kc + k) * 32 + nq];
            float4 hv, lv;
            hv.x = to_tf32(v.x); lv.x = to_tf32(v.x - hv.x);
            hv.y = to_tf32(v.y); lv.y = to_tf32(v.y - hv.y);
            hv.z = to_tf32(v.z); lv.z = to_tf32(v.z - hv.z);
            hv.w = to_tf32(v.w); lv.w = to_tf32(v.w - hv.w);
            *(float4*)&sWh[k][nq * 4] = hv;
            *(float4*)&sWl[k][nq * 4] = lv;
        }
        __syncthreads();

#pragma unroll
        for (int ks = 0; ks < KC / 8; ks++) {
            const int k0 = ks * 8;
            uint32_t ah[2][4], al[2][4];
#pragma unroll
            for (int i = 0; i < 2; i++) {
                int mb = wm + i * 16 + ar;
                ah[i][0] = __float_as_uint(sAh[k0 + ac    ][mb    ]);
                ah[i][1] = __float_as_uint(sAh[k0 + ac    ][mb + 8]);
                ah[i][2] = __float_as_uint(sAh[k0 + ac + 4][mb    ]);
                ah[i][3] = __float_as_uint(sAh[k0 + ac + 4][mb + 8]);
                al[i][0] = __float_as_uint(sAl[k0 + ac    ][mb    ]);
                al[i][1] = __float_as_uint(sAl[k0 + ac    ][mb + 8]);
                al[i][2] = __float_as_uint(sAl[k0 + ac + 4][mb    ]);
                al[i][3] = __float_as_uint(sAl[k0 + ac + 4][mb + 8]);
            }
#pragma unroll
            for (int j = 0; j < 8; j++) {
                uint32_t bh0 = __float_as_uint(sWh[k0 + ac    ][wn + j * 8 + ar]);
                uint32_t bh1 = __float_as_uint(sWh[k0 + ac + 4][wn + j * 8 + ar]);
                uint32_t bl0 = __float_as_uint(sWl[k0 + ac    ][wn + j * 8 + ar]);
                uint32_t bl1 = __float_as_uint(sWl[k0 + ac + 4][wn + j * 8 + ar]);
#pragma unroll
                for (int i = 0; i < 2; i++) {
                    // Ah*Wh
                    asm volatile(
                        "mma.sync.aligned.m16n8k8.row.col.f32.tf32.tf32.f32 "
                        "{%0,%1,%2,%3}, {%4,%5,%6,%7}, {%8,%9}, {%0,%1,%2,%3};"
                        : "+f"(acc[i][j][0]), "+f"(acc[i][j][1]),
                          "+f"(acc[i][j][2]), "+f"(acc[i][j][3])
                        : "r"(ah[i][0]), "r"(ah[i][1]), "r"(ah[i][2]), "r"(ah[i][3]),
                          "r"(bh0), "r"(bh1));
                    // Ah*Wl
                    asm volatile(
                        "mma.sync.aligned.m16n8k8.row.col.f32.tf32.tf32.f32 "
                        "{%0,%1,%2,%3}, {%4,%5,%6,%7}, {%8,%9}, {%0,%1,%2,%3};"
                        : "+f"(acc[i][j][0]), "+f"(acc[i][j][1]),
                          "+f"(acc[i][j][2]), "+f"(acc[i][j][3])
                        : "r"(ah[i][0]), "r"(ah[i][1]), "r"(ah[i][2]), "r"(ah[i][3]),
                          "r"(bl0), "r"(bl1));
                    // Al*Wh
                    asm volatile(
                        "mma.sync.aligned.m16n8k8.row.col.f32.tf32.tf32.f32 "
                        "{%0,%1,%2,%3}, {%4,%5,%6,%7}, {%8,%9}, {%0,%1,%2,%3};"
                        : "+f"(acc[i][j][0]), "+f"(acc[i][j][1]),
                          "+f"(acc[i][j][2]), "+f"(acc[i][j][3])
                        : "r"(al[i][0]), "r"(al[i][1]), "r"(al[i][2]), "r"(al[i][3]),
                          "r"(bh0), "r"(bh1));
                }
            }
        }
        __syncthreads();
    }

    // ---- epilogue ----
    const int epi = args.epi[w];
    const float* bias = args.bias[w];
    float* out = args.out[w];
#pragma unroll
    for (int i = 0; i < 2; i++) {
#pragma unroll
        for (int j = 0; j < 8; j++) {
            int cc = wn + j * 8 + ac * 2;
            float bx = 0.f, by = 0.f;
            if (epi >= 1) { bx = bias[cc]; by = bias[cc + 1]; }
            float c0 = acc[i][j][0] + bx, c1 = acc[i][j][1] + by;
            float c2 = acc[i][j][2] + bx, c3 = acc[i][j][3] + by;
            if (epi == 2) {
                c0 = fmaxf(c0, 0.f); c1 = fmaxf(c1, 0.f);
                c2 = fmaxf(c2, 0.f); c3 = fmaxf(c3, 0.f);
            }
            int r0 = row0 + wm + i * 16 + ar;
            if (r0 < NN)     *(float2*)&out[(size_t)r0 * DD + cc]       = make_float2(c0, c1);
            if (r0 + 8 < NN) *(float2*)&out[(size_t)(r0 + 8) * DD + cc] = make_float2(c2, c3);
        }
    }
}

// ---------------- small FFMA GEMM for the prediction head (NCOL=40) ----------------
template <int NCOL>
__global__ void gemm_small_k(const float* __restrict__ A, const float* __restrict__ W,
                             const float* __restrict__ bias, float* __restrict__ C) {
    constexpr int ROWS = 32;
    constexpr int KT   = 32;
    __shared__ float sA[ROWS][DD];
    __shared__ float sW[KT][NCOL];
    int tid  = threadIdx.x;
    int row0 = blockIdx.x * ROWS;

    {
        const float4* Af  = (const float4*)A;
        float4*       sAf = (float4*)sA;
#pragma unroll
        for (int i = 0; i < 4; i++) {
            int idx = tid + i * 256;
            int r = idx >> 5, c = idx & 31;
            float4 v = make_float4(0.f, 0.f, 0.f, 0.f);
            if (row0 + r < NN) v = Af[(size_t)(row0 + r) * 32 + c];
            sAf[idx] = v;
        }
    }

    int tx = tid & 31, ty = tid >> 5;
    const int col = tx * 4;
    float acc[4][4];
#pragma unroll
    for (int i = 0; i < 4; i++)
#pragma unroll
        for (int j = 0; j < 4; j++) acc[i][j] = 0.f;

    for (int kt = 0; kt < DD; kt += KT) {
        __syncthreads();
        {
            const float4* Wf  = (const float4*)(W + kt * NCOL);
            float4*       sWf = (float4*)sW;
            constexpr int T4 = KT * NCOL / 4;
            for (int i = tid; i < T4; i += 256) sWf[i] = Wf[i];
        }
        __syncthreads();
#pragma unroll
        for (int k = 0; k < KT; k++) {
            float4 wv = make_float4(0.f, 0.f, 0.f, 0.f);
            if (col < NCOL) wv = *(const float4*)&sW[k][col];
#pragma unroll
            for (int i = 0; i < 4; i++) {
                float a = sA[ty + i * 8][kt + k];
                acc[i][0] += a * wv.x;
                acc[i][1] += a * wv.y;
                acc[i][2] += a * wv.z;
                acc[i][3] += a * wv.w;
            }
        }
    }

    if (col < NCOL) {
        float4 bv = *(const float4*)&bias[col];
#pragma unroll
        for (int i = 0; i < 4; i++) {
            int row = row0 + ty + i * 8;
            if (row < NN) {
                float4 o;
                o.x = acc[i][0] + bv.x;
                o.y = acc[i][1] + bv.y;
                o.z = acc[i][2] + bv.z;
                o.w = acc[i][3] + bv.w;
                *(float4*)&C[(size_t)row * NCOL + col] = o;
            }
        }
    }
}

// ---------------- attention logits per node ----------------
__global__ void attn_k(const float* __restrict__ xh,
                       const float* __restrict__ asv, const float* __restrict__ adv) {
    int warp = (blockIdx.x * blockDim.x + threadIdx.x) >> 5;
    int lane = threadIdx.x & 31;
    if (warp >= NN) return;
    float4 v = ((const float4*)(xh + (size_t)warp * DD))[lane];
    float4 a = ((const float4*)asv)[lane];
    float4 d = ((const float4*)adv)[lane];
    float s = v.x * a.x + v.y * a.y + v.z * a.z + v.w * a.w;
    float t = v.x * d.x + v.y * d.y + v.z * d.z + v.w * d.w;
#pragma unroll
    for (int o = 16; o; o >>= 1) {
        s += __shfl_xor_sync(0xFFFFFFFFu, s, o);
        t += __shfl_xor_sync(0xFFFFFFFFu, t, o);
    }
    if (lane == 0) { g_as[warp] = s; g_ad[warp] = t; }
}

// ---------------- GAT softmax-aggregate: warp per destination node ----------------
__global__ void agg_k(const float* __restrict__ xh) {
    int n    = (blockIdx.x * blockDim.x + threadIdx.x) >> 5;
    int lane = threadIdx.x & 31;
    if (n >= NN) return;
    int s0 = g_rowptr[n], s1 = g_rowptr[n + 1];
    float adn = g_ad[n];

    float m = -1e30f;
    for (int i = s0 + lane; i < s1; i += 32) {
        int s  = g_esrc[i];
        float e = g_as[s] + adn;
        e = e > 0.f ? e : 0.2f * e;
        m = fmaxf(m, e);
    }
#pragma unroll
    for (int o = 16; o; o >>= 1) m = fmaxf(m, __shfl_xor_sync(0xFFFFFFFFu, m, o));

    float den = 0.f;
    for (int i = s0 + lane; i < s1; i += 32) {
        int s  = g_esrc[i];
        float e = g_as[s] + adn;
        e = e > 0.f ? e : 0.2f * e;
        den += __expf(e - m);
    }
#pragma unroll
    for (int o = 16; o; o >>= 1) den += __shfl_xor_sync(0xFFFFFFFFu, den, o);
    float inv = 1.f / (den + 1e-16f);

    float4 acc = make_float4(0.f, 0.f, 0.f, 0.f);
    for (int base = s0; base < s1; base += 32) {
        int idx = base + lane;
        float w = 0.f;
        int   s = 0;
        if (idx < s1) {
            s = g_esrc[idx];
            float e = g_as[s] + adn;
            e = e > 0.f ? e : 0.2f * e;
            w = __expf(e - m) * inv;
        }
        int cnt = min(32, s1 - base);
        for (int j = 0; j < cnt; j++) {
            float wj = __shfl_sync(0xFFFFFFFFu, w, j);
            int   sj = __shfl_sync(0xFFFFFFFFu, s, j);
            float4 v = ((const float4*)(xh + (size_t)sj * DD))[lane];
            acc.x += wj * v.x; acc.y += wj * v.y;
            acc.z += wj * v.z; acc.w += wj * v.w;
        }
    }
    ((float4*)(g_agg + (size_t)n * DD))[lane] = acc;
}

// ---------------- fused pointwise: relu + gate + layernorm + residual accumulate ----------------
__global__ void fuse_k(const float* __restrict__ xlbuf, const float* __restrict__ hbuf,
                       const float* __restrict__ lng, const float* __restrict__ lnb,
                       const float* __restrict__ betas, int first) {
    int n    = (blockIdx.x * blockDim.x + threadIdx.x) >> 5;
    int lane = threadIdx.x & 31;
    if (n >= NN) return;
    size_t off = (size_t)n * DD;

    float4 ag = ((const float4*)(g_agg + off))[lane];
    float4 xl = ((const float4*)(xlbuf + off))[lane];
    float4 xn;
    xn.x = fmaxf(ag.x + xl.x, 0.f);
    xn.y = fmaxf(ag.y + xl.y, 0.f);
    xn.z = fmaxf(ag.z + xl.z, 0.f);
    xn.w = fmaxf(ag.w + xl.w, 0.f);

    float4 hh = ((const float4*)(hbuf + off))[lane];
    float4 t;
    t.x = hh.x * xn.x; t.y = hh.y * xn.y; t.z = hh.z * xn.z; t.w = hh.w * xn.w;

    float sum = t.x + t.y + t.z + t.w;
#pragma unroll
    for (int o = 16; o; o >>= 1) sum += __shfl_xor_sync(0xFFFFFFFFu, sum, o);
    float mu = sum * (1.f / 128.f);

    float4 dc;
    dc.x = t.x - mu; dc.y = t.y - mu; dc.z = t.z - mu; dc.w = t.w - mu;
    float ss = dc.x * dc.x + dc.y * dc.y + dc.z * dc.z + dc.w * dc.w;
#pragma unroll
    for (int o = 16; o; o >>= 1) ss += __shfl_xor_sync(0xFFFFFFFFu, ss, o);
    float rs = rsqrtf(ss * (1.f / 128.f) + 1e-5f);

    float4 g  = ((const float4*)lng)[lane];
    float4 b  = ((const float4*)lnb)[lane];
    float4 be = ((const float4*)betas)[lane];
    be.x = 1.f / (1.f + __expf(-be.x));
    be.y = 1.f / (1.f + __expf(-be.y));
    be.z = 1.f / (1.f + __expf(-be.z));
    be.w = 1.f / (1.f + __expf(-be.w));

    float4 y;
    y.x = dc.x * rs * g.x + b.x;
    y.y = dc.y * rs * g.y + b.y;
    y.z = dc.z * rs * g.z + b.z;
    y.w = dc.w * rs * g.w + b.w;

    float4 xo;
    xo.x = (1.f - be.x) * y.x + be.x * xn.x;
    xo.y = (1.f - be.y) * y.y + be.y * xn.y;
    xo.z = (1.f - be.z) * y.z + be.z * xn.z;
    xo.w = (1.f - be.w) * y.w + be.w * xn.w;

    ((float4*)(g_x + off))[lane] = xo;
    if (first) {
        ((float4*)(g_xlocal + off))[lane] = xo;
    } else {
        float4 p = ((const float4*)(g_xlocal + off))[lane];
        p.x += xo.x; p.y += xo.y; p.z += xo.z; p.w += xo.w;
        ((float4*)(g_xlocal + off))[lane] = p;
    }
}

// ---------------- host ----------------
extern "C" void kernel_launch(void* const* d_in, const int* in_sizes, int n_in,
                              void* d_out, int out_size) {
    const float* x       = (const float*)d_in[0];
    const int*   ei32    = (const int*)d_in[1];
    const float* W_in    = (const float*)d_in[2];
    const float* b_in    = (const float*)d_in[3];
    const float* W_h     = (const float*)d_in[4];
    const float* b_h     = (const float*)d_in[5];
    const float* W_gat   = (const float*)d_in[6];
    const float* att_src = (const float*)d_in[7];
    const float* att_dst = (const float*)d_in[8];
    const float* W_l     = (const float*)d_in[9];
    const float* b_l     = (const float*)d_in[10];
    const float* ln_g    = (const float*)d_in[11];
    const float* ln_b    = (const float*)d_in[12];
    const float* betas   = (const float*)d_in[13];
    const float* W_pred  = (const float*)d_in[14];
    const float* b_pred  = (const float*)d_in[15];
    float*       out     = (float*)d_out;

    float *px, *ph, *pxh, *pxl, *pxloc;
    cudaGetSymbolAddress((void**)&px,    g_x);
    cudaGetSymbolAddress((void**)&ph,    g_h);
    cudaGetSymbolAddress((void**)&pxh,   g_xh);
    cudaGetSymbolAddress((void**)&pxl,   g_xl);
    cudaGetSymbolAddress((void**)&pxloc, g_xlocal);

    dim3 gE((EE + 255) / 256);
    dim3 gN((NN + 255) / 256);
    dim3 gW((NN + 7) / 8);
    dim3 gG((NN + 31) / 32);
    dim3 gM((NN + 127) / 128, 1);
    dim3 gM3((NN + 127) / 128, 3);

    // edge decode + CSR by destination
    decode_k<<<gE, 256>>>(ei32);
    zero_k<<<gN, 256>>>();
    deg_k<<<gE, 256>>>();
    pscan_k<<<NSB, SB>>>();
    bscan_k<<<1, 128>>>();
    addoff_k<<<gN, 256>>>();
    scat_k<<<gE, 256>>>();

    // input projection: x @ W_in + b_in
    {
        GemmArgs a{};
        a.W[0] = W_in; a.bias[0] = b_in; a.out[0] = px; a.epi[0] = 1;
        mma_gemm_k<<<gM, 256>>>(x, a);
    }

    for (int i = 0; i < LL; i++) {
        GemmArgs a{};
        a.W[0] = W_h   + (size_t)i * DD * DD; a.bias[0] = b_h + i * DD; a.out[0] = ph;  a.epi[0] = 2;
        a.W[1] = W_gat + (size_t)i * DD * DD; a.bias[1] = nullptr;      a.out[1] = pxh; a.epi[1] = 0;
        a.W[2] = W_l   + (size_t)i * DD * DD; a.bias[2] = b_l + i * DD; a.out[2] = pxl; a.epi[2] = 1;
        mma_gemm_k<<<gM3, 256>>>(px, a);

        attn_k<<<gW, 256>>>(pxh, att_src + i * DD, att_dst + i * DD);
        agg_k<<<gW, 256>>>(pxh);
        fuse_k<<<gW, 256>>>(pxl, ph, ln_g + i * DD, ln_b + i * DD, betas + i * DD, i == 0);
    }

    gemm_small_k<OUTD><<<gG, 256>>>(pxloc, W_pred, b_pred, out);
}

// round 5
// speedup vs baseline: 1.2941x; 1.2855x over previous
#include <cuda_runtime.h>
#include <cuda_bf16.h>
#include <math.h>
#include <stdint.h>

#define NN   50000
#define EE   800000
#define DD   128
#define LL   3
#define OUTD 40
#define SB   512
#define NSB  ((NN + SB - 1) / SB)   // 98

// ---------------- scratch (device globals; no allocation allowed) ----------------
__device__ float g_x[NN * DD];
__device__ float g_h[NN * DD];
__device__ float g_xh[NN * DD];
__device__ float g_xl[NN * DD];
__device__ float g_agg[NN * DD];
__device__ float g_xlocal[NN * DD];
__device__ float g_as[NN];
__device__ float g_ad[NN];
__device__ int   g_deg[NN];
__device__ int   g_fill[NN];
__device__ int   g_rowptr[NN + 1];
__device__ int   g_esrc[EE];
__device__ int   g_src[EE];
__device__ int   g_dst[EE];
__device__ int   g_bsum[NSB];
__device__ int   g_boff[128];

// ---------------- edge decode: handle int32 OR int64 edge_index ----------------
__global__ void decode_k(const int* __restrict__ ei32) {
    bool is64 = (ei32[1] == 0 && ei32[3] == 0 && ei32[5] == 0 && ei32[7] == 0);
    int e = blockIdx.x * blockDim.x + threadIdx.x;
    if (e < EE) {
        int s, d;
        if (is64) {
            s = ei32[2 * (size_t)e];
            d = ei32[2 * ((size_t)EE + e)];
        } else {
            s = ei32[e];
            d = ei32[EE + e];
        }
        g_src[e] = s;
        g_dst[e] = d;
    }
}

// ---------------- CSR build ----------------
__global__ void zero_k() {
    int i = blockIdx.x * blockDim.x + threadIdx.x;
    if (i < NN) { g_deg[i] = 0; g_fill[i] = 0; }
}

__global__ void deg_k() {
    int e = blockIdx.x * blockDim.x + threadIdx.x;
    if (e < EE) atomicAdd(&g_deg[g_dst[e]], 1);
}

__global__ void pscan_k() {
    __shared__ int sh[SB];
    int t = threadIdx.x;
    int i = blockIdx.x * SB + t;
    int v = (i < NN) ? g_deg[i] : 0;
    sh[t] = v;
    __syncthreads();
    for (int o = 1; o < SB; o <<= 1) {
        int a = (t >= o) ? sh[t - o] : 0;
        __syncthreads();
        sh[t] += a;
        __syncthreads();
    }
    if (i < NN) g_rowptr[i] = sh[t] - v;
    if (t == SB - 1) g_bsum[blockIdx.x] = sh[t];
}

__global__ void bscan_k() {
    __shared__ int sh[128];
    int t = threadIdx.x;
    int v = (t < NSB) ? g_bsum[t] : 0;
    sh[t] = v;
    __syncthreads();
    for (int o = 1; o < 128; o <<= 1) {
        int a = (t >= o) ? sh[t - o] : 0;
        __syncthreads();
        sh[t] += a;
        __syncthreads();
    }
    g_boff[t] = sh[t] - v;
}

__global__ void addoff_k() {
    int i = blockIdx.x * blockDim.x + threadIdx.x;
    if (i < NN) g_rowptr[i] += g_boff[i / SB];
    if (i == 0) g_rowptr[NN] = EE;
}

__global__ void scat_k() {
    int e = blockIdx.x * blockDim.x + threadIdx.x;
    if (e < EE) {
        int d = g_dst[e];
        int p = g_rowptr[d] + atomicAdd(&g_fill[d], 1);
        g_esrc[p] = g_src[e];
    }
}

// ---------------- bf16x3 split-precision tensor-core GEMM ----------------
// C[N,128] = A[N,128] @ W[128,128], near-fp32:
//   A = Ah + Al (bf16 split), W = Wh + Wl; C ≈ Ah*Wh + Ah*Wl + Al*Wh
// mma.m16n8k16.bf16, block tile 128x128, 8 warps (4m x 2n), warp 32x64.
// SMEM word layout: [row][20 words] (PAD=20 -> conflict-free fragment LDS).
struct GemmArgs {
    const float* W[3];
    const float* bias[3];
    float*       out[3];
    int          epi[3];    // 0 = none, 1 = bias, 2 = bias+relu
};

__device__ __forceinline__ void bsplit(float v, uint32_t& h, uint32_t& l) {
    __nv_bfloat16 bh = __float2bfloat16_rn(v);
    float r = v - __bfloat162float(bh);
    __nv_bfloat16 bl = __float2bfloat16_rn(r);
    h = (uint32_t)__bfloat16_as_ushort(bh);
    l = (uint32_t)__bfloat16_as_ushort(bl);
}

#define PADW 20

__global__ __launch_bounds__(256)
void mma_gemm_k(const float* __restrict__ A, GemmArgs args) {
    // K-chunk = 32 (16 words of bf16 pairs)
    __shared__ uint32_t sAh[128 * PADW];
    __shared__ uint32_t sAl[128 * PADW];
    __shared__ uint32_t sWh[128 * PADW];
    __shared__ uint32_t sWl[128 * PADW];

    const int tid  = threadIdx.x;
    const int lane = tid & 31;
    const int wid  = tid >> 5;
    const int wm   = (wid >> 1) * 32;       // warp m offset
    const int wn   = (wid & 1) * 64;        // warp n offset
    const int row0 = blockIdx.x * 128;
    const int w    = blockIdx.y;

    const float4* Af = (const float4*)A;
    const float* __restrict__ Wm = args.W[w];

    const int ar = lane >> 2;   // groupID 0..7
    const int ac = lane & 3;    // threadID-in-group 0..3

    float acc[2][8][4];
#pragma unroll
    for (int i = 0; i < 2; i++)
#pragma unroll
        for (int j = 0; j < 8; j++)
#pragma unroll
            for (int c = 0; c < 4; c++) acc[i][j][c] = 0.f;

    for (int kc = 0; kc < DD; kc += 32) {
        // ---- stage A: 128 rows x 32 k  (1024 float4 tasks, 4/thread) ----
#pragma unroll
        for (int t = tid; t < 1024; t += 256) {
            int m = t >> 3, q = t & 7;        // q: float4 index within 32 k
            int row = row0 + m;
            float4 v = make_float4(0.f, 0.f, 0.f, 0.f);
            if (row < NN) v = Af[(size_t)row * 32 + (kc >> 2) + q];
            uint32_t hx, lx, hy, ly, hz, lz, hw, lw;
            bsplit(v.x, hx, lx); bsplit(v.y, hy, ly);
            bsplit(v.z, hz, lz); bsplit(v.w, hw, lw);
            uint2 hvec = make_uint2(hx | (hy << 16), hz | (hw << 16));
            uint2 lvec = make_uint2(lx | (ly << 16), lz | (lw << 16));
            *(uint2*)&sAh[m * PADW + 2 * q] = hvec;
            *(uint2*)&sAl[m * PADW + 2 * q] = lvec;
        }
        // ---- stage W transposed to [n][kw]: 128 n x 16 kw (2048 tasks, 8/thread) ----
#pragma unroll
        for (int t = tid; t < 2048; t += 256) {
            int n = t & 127, kwl = t >> 7;    // kwl: 0..15
            int k = kc + 2 * kwl;
            float v0 = Wm[(size_t)k * DD + n];
            float v1 = Wm[(size_t)(k + 1) * DD + n];
            uint32_t h0, l0, h1, l1;
            bsplit(v0, h0, l0); bsplit(v1, h1, l1);
            sWh[n * PADW + kwl] = h0 | (h1 << 16);
            sWl[n * PADW + kwl] = l0 | (l1 << 16);
        }
        __syncthreads();

#pragma unroll
        for (int s = 0; s < 2; s++) {        // two k16 steps per chunk
            const int kb = s * 8;
            uint32_t ah[2][4], al[2][4];
#pragma unroll
            for (int i = 0; i < 2; i++) {
                int m = wm + i * 16 + ar;
                ah[i][0] = sAh[m * PADW + kb + ac];
                ah[i][1] = sAh[(m + 8) * PADW + kb + ac];
                ah[i][2] = sAh[m * PADW + kb + ac + 4];
                ah[i][3] = sAh[(m + 8) * PADW + kb + ac + 4];
                al[i][0] = sAl[m * PADW + kb + ac];
                al[i][1] = sAl[(m + 8) * PADW + kb + ac];
                al[i][2] = sAl[m * PADW + kb + ac + 4];
                al[i][3] = sAl[(m + 8) * PADW + kb + ac + 4];
            }
#pragma unroll
            for (int j = 0; j < 8; j++) {
                int n = wn + j * 8 + ar;
                uint32_t bh0 = sWh[n * PADW + kb + ac];
                uint32_t bh1 = sWh[n * PADW + kb + ac + 4];
                uint32_t bl0 = sWl[n * PADW + kb + ac];
                uint32_t bl1 = sWl[n * PADW + kb + ac + 4];
#pragma unroll
                for (int i = 0; i < 2; i++) {
                    asm volatile(
                        "mma.sync.aligned.m16n8k16.row.col.f32.bf16.bf16.f32 "
                        "{%0,%1,%2,%3}, {%4,%5,%6,%7}, {%8,%9}, {%0,%1,%2,%3};"
                        : "+f"(acc[i][j][0]), "+f"(acc[i][j][1]),
                          "+f"(acc[i][j][2]), "+f"(acc[i][j][3])
                        : "r"(ah[i][0]), "r"(ah[i][1]), "r"(ah[i][2]), "r"(ah[i][3]),
                          "r"(bh0), "r"(bh1));
                    asm volatile(
                        "mma.sync.aligned.m16n8k16.row.col.f32.bf16.bf16.f32 "
                        "{%0,%1,%2,%3}, {%4,%5,%6,%7}, {%8,%9}, {%0,%1,%2,%3};"
                        : "+f"(acc[i][j][0]), "+f"(acc[i][j][1]),
                          "+f"(acc[i][j][2]), "+f"(acc[i][j][3])
                        : "r"(ah[i][0]), "r"(ah[i][1]), "r"(ah[i][2]), "r"(ah[i][3]),
                          "r"(bl0), "r"(bl1));
                    asm volatile(
                        "mma.sync.aligned.m16n8k16.row.col.f32.bf16.bf16.f32 "
                        "{%0,%1,%2,%3}, {%4,%5,%6,%7}, {%8,%9}, {%0,%1,%2,%3};"
                        : "+f"(acc[i][j][0]), "+f"(acc[i][j][1]),
                          "+f"(acc[i][j][2]), "+f"(acc[i][j][3])
                        : "r"(al[i][0]), "r"(al[i][1]), "r"(al[i][2]), "r"(al[i][3]),
                          "r"(bh0), "r"(bh1));
                }
            }
        }
        __syncthreads();
    }

    // ---- epilogue ----
    const int epi = args.epi[w];
    const float* bias = args.bias[w];
    float* out = args.out[w];
#pragma unroll
    for (int i = 0; i < 2; i++) {
#pragma unroll
        for (int j = 0; j < 8; j++) {
            int cc = wn + j * 8 + ac * 2;
            float bx = 0.f, by = 0.f;
            if (epi >= 1) { bx = bias[cc]; by = bias[cc + 1]; }
            float c0 = acc[i][j][0] + bx, c1 = acc[i][j][1] + by;
            float c2 = acc[i][j][2] + bx, c3 = acc[i][j][3] + by;
            if (epi == 2) {
                c0 = fmaxf(c0, 0.f); c1 = fmaxf(c1, 0.f);
                c2 = fmaxf(c2, 0.f); c3 = fmaxf(c3, 0.f);
            }
            int r0 = row0 + wm + i * 16 + ar;
            if (r0 < NN)     *(float2*)&out[(size_t)r0 * DD + cc]       = make_float2(c0, c1);
            if (r0 + 8 < NN) *(float2*)&out[(size_t)(r0 + 8) * DD + cc] = make_float2(c2, c3);
        }
    }
}

// ---------------- small FFMA GEMM for the prediction head (NCOL=40) ----------------
template <int NCOL>
__global__ void gemm_small_k(const float* __restrict__ A, const float* __restrict__ W,
                             const float* __restrict__ bias, float* __restrict__ C) {
    constexpr int ROWS = 32;
    constexpr int KT   = 32;
    __shared__ float sA[ROWS][DD];
    __shared__ float sW[KT][NCOL];
    int tid  = threadIdx.x;
    int row0 = blockIdx.x * ROWS;

    {
        const float4* Af  = (const float4*)A;
        float4*       sAf = (float4*)sA;
#pragma unroll
        for (int i = 0; i < 4; i++) {
            int idx = tid + i * 256;
            int r = idx >> 5, c = idx & 31;
            float4 v = make_float4(0.f, 0.f, 0.f, 0.f);
            if (row0 + r < NN) v = Af[(size_t)(row0 + r) * 32 + c];
            sAf[idx] = v;
        }
    }

    int tx = tid & 31, ty = tid >> 5;
    const int col = tx * 4;
    float acc[4][4];
#pragma unroll
    for (int i = 0; i < 4; i++)
#pragma unroll
        for (int j = 0; j < 4; j++) acc[i][j] = 0.f;

    for (int kt = 0; kt < DD; kt += KT) {
        __syncthreads();
        {
            const float4* Wf  = (const float4*)(W + kt * NCOL);
            float4*       sWf = (float4*)sW;
            constexpr int T4 = KT * NCOL / 4;
            for (int i = tid; i < T4; i += 256) sWf[i] = Wf[i];
        }
        __syncthreads();
#pragma unroll
        for (int k = 0; k < KT; k++) {
            float4 wv = make_float4(0.f, 0.f, 0.f, 0.f);
            if (col < NCOL) wv = *(const float4*)&sW[k][col];
#pragma unroll
            for (int i = 0; i < 4; i++) {
                float a = sA[ty + i * 8][kt + k];
                acc[i][0] += a * wv.x;
                acc[i][1] += a * wv.y;
                acc[i][2] += a * wv.z;
                acc[i][3] += a * wv.w;
            }
        }
    }

    if (col < NCOL) {
        float4 bv = *(const float4*)&bias[col];
#pragma unroll
        for (int i = 0; i < 4; i++) {
            int row = row0 + ty + i * 8;
            if (row < NN) {
                float4 o;
                o.x = acc[i][0] + bv.x;
                o.y = acc[i][1] + bv.y;
                o.z = acc[i][2] + bv.z;
                o.w = acc[i][3] + bv.w;
                *(float4*)&C[(size_t)row * NCOL + col] = o;
            }
        }
    }
}

// ---------------- attention logits per node ----------------
__global__ void attn_k(const float* __restrict__ xh,
                       const float* __restrict__ asv, const float* __restrict__ adv) {
    int warp = (blockIdx.x * blockDim.x + threadIdx.x) >> 5;
    int lane = threadIdx.x & 31;
    if (warp >= NN) return;
    float4 v = ((const float4*)(xh + (size_t)warp * DD))[lane];
    float4 a = ((const float4*)asv)[lane];
    float4 d = ((const float4*)adv)[lane];
    float s = v.x * a.x + v.y * a.y + v.z * a.z + v.w * a.w;
    float t = v.x * d.x + v.y * d.y + v.z * d.z + v.w * d.w;
#pragma unroll
    for (int o = 16; o; o >>= 1) {
        s += __shfl_xor_sync(0xFFFFFFFFu, s, o);
        t += __shfl_xor_sync(0xFFFFFFFFu, t, o);
    }
    if (lane == 0) { g_as[warp] = s; g_ad[warp] = t; }
}

// ---------------- GAT softmax-aggregate: warp per destination node ----------------
__global__ void agg_k(const float* __restrict__ xh) {
    int n    = (blockIdx.x * blockDim.x + threadIdx.x) >> 5;
    int lane = threadIdx.x & 31;
    if (n >= NN) return;
    int s0 = g_rowptr[n], s1 = g_rowptr[n + 1];
    float adn = g_ad[n];

    float m = -1e30f;
    for (int i = s0 + lane; i < s1; i += 32) {
        int s  = g_esrc[i];
        float e = g_as[s] + adn;
        e = e > 0.f ? e : 0.2f * e;
        m = fmaxf(m, e);
    }
#pragma unroll
    for (int o = 16; o; o >>= 1) m = fmaxf(m, __shfl_xor_sync(0xFFFFFFFFu, m, o));

    float den = 0.f;
    for (int i = s0 + lane; i < s1; i += 32) {
        int s  = g_esrc[i];
        float e = g_as[s] + adn;
        e = e > 0.f ? e : 0.2f * e;
        den += __expf(e - m);
    }
#pragma unroll
    for (int o = 16; o; o >>= 1) den += __shfl_xor_sync(0xFFFFFFFFu, den, o);
    float inv = 1.f / (den + 1e-16f);

    float4 acc = make_float4(0.f, 0.f, 0.f, 0.f);
    for (int base = s0; base < s1; base += 32) {
        int idx = base + lane;
        float w = 0.f;
        int   s = 0;
        if (idx < s1) {
            s = g_esrc[idx];
            float e = g_as[s] + adn;
            e = e > 0.f ? e : 0.2f * e;
            w = __expf(e - m) * inv;
        }
        int cnt = min(32, s1 - base);
        for (int j = 0; j < cnt; j++) {
            float wj = __shfl_sync(0xFFFFFFFFu, w, j);
            int   sj = __shfl_sync(0xFFFFFFFFu, s, j);
            float4 v = ((const float4*)(xh + (size_t)sj * DD))[lane];
            acc.x += wj * v.x; acc.y += wj * v.y;
            acc.z += wj * v.z; acc.w += wj * v.w;
        }
    }
    ((float4*)(g_agg + (size_t)n * DD))[lane] = acc;
}

// ---------------- fused pointwise: relu + gate + layernorm + residual accumulate ----------------
__global__ void fuse_k(const float* __restrict__ xlbuf, const float* __restrict__ hbuf,
                       const float* __restrict__ lng, const float* __restrict__ lnb,
                       const float* __restrict__ betas, int first) {
    int n    = (blockIdx.x * blockDim.x + threadIdx.x) >> 5;
    int lane = threadIdx.x & 31;
    if (n >= NN) return;
    size_t off = (size_t)n * DD;

    float4 ag = ((const float4*)(g_agg + off))[lane];
    float4 xl = ((const float4*)(xlbuf + off))[lane];
    float4 xn;
    xn.x = fmaxf(ag.x + xl.x, 0.f);
    xn.y = fmaxf(ag.y + xl.y, 0.f);
    xn.z = fmaxf(ag.z + xl.z, 0.f);
    xn.w = fmaxf(ag.w + xl.w, 0.f);

    float4 hh = ((const float4*)(hbuf + off))[lane];
    float4 t;
    t.x = hh.x * xn.x; t.y = hh.y * xn.y; t.z = hh.z * xn.z; t.w = hh.w * xn.w;

    float sum = t.x + t.y + t.z + t.w;
#pragma unroll
    for (int o = 16; o; o >>= 1) sum += __shfl_xor_sync(0xFFFFFFFFu, sum, o);
    float mu = sum * (1.f / 128.f);

    float4 dc;
    dc.x = t.x - mu; dc.y = t.y - mu; dc.z = t.z - mu; dc.w = t.w - mu;
    float ss = dc.x * dc.x + dc.y * dc.y + dc.z * dc.z + dc.w * dc.w;
#pragma unroll
    for (int o = 16; o; o >>= 1) ss += __shfl_xor_sync(0xFFFFFFFFu, ss, o);
    float rs = rsqrtf(ss * (1.f / 128.f) + 1e-5f);

    float4 g  = ((const float4*)lng)[lane];
    float4 b  = ((const float4*)lnb)[lane];
    float4 be = ((const float4*)betas)[lane];
    be.x = 1.f / (1.f + __expf(-be.x));
    be.y = 1.f / (1.f + __expf(-be.y));
    be.z = 1.f / (1.f + __expf(-be.z));
    be.w = 1.f / (1.f + __expf(-be.w));

    float4 y;
    y.x = dc.x * rs * g.x + b.x;
    y.y = dc.y * rs * g.y + b.y;
    y.z = dc.z * rs * g.z + b.z;
    y.w = dc.w * rs * g.w + b.w;

    float4 xo;
    xo.x = (1.f - be.x) * y.x + be.x * xn.x;
    xo.y = (1.f - be.y) * y.y + be.y * xn.y;
    xo.z = (1.f - be.z) * y.z + be.z * xn.z;
    xo.w = (1.f - be.w) * y.w + be.w * xn.w;

    ((float4*)(g_x + off))[lane] = xo;
    if (first) {
        ((float4*)(g_xlocal + off))[lane] = xo;
    } else {
        float4 p = ((const float4*)(g_xlocal + off))[lane];
        p.x += xo.x; p.y += xo.y; p.z += xo.z; p.w += xo.w;
        ((float4*)(g_xlocal + off))[lane] = p;
    }
}

// ---------------- host ----------------
extern "C" void kernel_launch(void* const* d_in, const int* in_sizes, int n_in,
                              void* d_out, int out_size) {
    const float* x       = (const float*)d_in[0];
    const int*   ei32    = (const int*)d_in[1];
    const float* W_in    = (const float*)d_in[2];
    const float* b_in    = (const float*)d_in[3];
    const float* W_h     = (const float*)d_in[4];
    const float* b_h     = (const float*)d_in[5];
    const float* W_gat   = (const float*)d_in[6];
    const float* att_src = (const float*)d_in[7];
    const float* att_dst = (const float*)d_in[8];
    const float* W_l     = (const float*)d_in[9];
    const float* b_l     = (const float*)d_in[10];
    const float* ln_g    = (const float*)d_in[11];
    const float* ln_b    = (const float*)d_in[12];
    const float* betas   = (const float*)d_in[13];
    const float* W_pred  = (const float*)d_in[14];
    const float* b_pred  = (const float*)d_in[15];
    float*       out     = (float*)d_out;

    float *px, *ph, *pxh, *pxl, *pxloc;
    cudaGetSymbolAddress((void**)&px,    g_x);
    cudaGetSymbolAddress((void**)&ph,    g_h);
    cudaGetSymbolAddress((void**)&pxh,   g_xh);
    cudaGetSymbolAddress((void**)&pxl,   g_xl);
    cudaGetSymbolAddress((void**)&pxloc, g_xlocal);

    dim3 gE((EE + 255) / 256);
    dim3 gN((NN + 255) / 256);
    dim3 gW((NN + 7) / 8);
    dim3 gG((NN + 31) / 32);
    dim3 gM((NN + 127) / 128, 1);
    dim3 gM3((NN + 127) / 128, 3);

    // edge decode + CSR by destination
    decode_k<<<gE, 256>>>(ei32);
    zero_k<<<gN, 256>>>();
    deg_k<<<gE, 256>>>();
    pscan_k<<<NSB, SB>>>();
    bscan_k<<<1, 128>>>();
    addoff_k<<<gN, 256>>>();
    scat_k<<<gE, 256>>>();

    // input projection: x @ W_in + b_in
    {
        GemmArgs a{};
        a.W[0] = W_in; a.bias[0] = b_in; a.out[0] = px; a.epi[0] = 1;
        mma_gemm_k<<<gM, 256>>>(x, a);
    }

    for (int i = 0; i < LL; i++) {
        GemmArgs a{};
        a.W[0] = W_h   + (size_t)i * DD * DD; a.bias[0] = b_h + i * DD; a.out[0] = ph;  a.epi[0] = 2;
        a.W[1] = W_gat + (size_t)i * DD * DD; a.bias[1] = nullptr;      a.out[1] = pxh; a.epi[1] = 0;
        a.W[2] = W_l   + (size_t)i * DD * DD; a.bias[2] = b_l + i * DD; a.out[2] = pxl; a.epi[2] = 1;
        mma_gemm_k<<<gM3, 256>>>(px, a);

        attn_k<<<gW, 256>>>(pxh, att_src + i * DD, att_dst + i * DD);
        agg_k<<<gW, 256>>>(pxh);
        fuse_k<<<gW, 256>>>(pxl, ph, ln_g + i * DD, ln_b + i * DD, betas + i * DD, i == 0);
    }

    gemm_small_k<OUTD><<<gG, 256>>>(pxloc, W_pred, b_pred, out);
}

// round 6
// speedup vs baseline: 1.5285x; 1.1811x over previous
#include <cuda_runtime.h>
#include <cuda_bf16.h>
#include <math.h>
#include <stdint.h>

#define NN   50000
#define EE   800000
#define DD   128
#define LL   3
#define OUTD 40
#define SB   512
#define NSB  ((NN + SB - 1) / SB)   // 98
#define PADW 20

// ---------------- scratch (device globals; no allocation allowed) ----------------
__device__ float    g_h[NN * DD];
__device__ float    g_xh[NN * DD];
__device__ float    g_xl[NN * DD];
__device__ float    g_agg[NN * DD];
__device__ float    g_xlocal[NN * DD];
__device__ float    g_as[NN];
__device__ float    g_ad[NN];
__device__ int      g_deg[NN];
__device__ int      g_fill[NN];
__device__ int      g_rowptr[NN + 1];
__device__ int      g_esrc[EE];
__device__ int      g_src[EE];
__device__ int      g_dst[EE];
__device__ int      g_bsum[NSB];
__device__ int      g_boff[128];
// packed bf16 pairs (hi/lo) along k: [row][64 words]
__device__ uint32_t g_inh[NN * 64];   // split of input x (lin_in A)
__device__ uint32_t g_inl[NN * 64];
__device__ uint32_t g_ah[NN * 64];    // split of working x (layer GEMM A)
__device__ uint32_t g_al[NN * 64];
// pre-split weights: [wslot][n][64 words], 10 slots
__device__ uint32_t g_wsh[10 * 128 * 64];
__device__ uint32_t g_wsl[10 * 128 * 64];

__device__ __forceinline__ void bsplit(float v, uint32_t& h, uint32_t& l) {
    __nv_bfloat16 bh = __float2bfloat16_rn(v);
    float r = v - __bfloat162float(bh);
    __nv_bfloat16 bl = __float2bfloat16_rn(r);
    h = (uint32_t)__bfloat16_as_ushort(bh);
    l = (uint32_t)__bfloat16_as_ushort(bl);
}

// ---------------- edge decode + degree histogram (fused) ----------------
__global__ void decode_deg_k(const int* __restrict__ ei32) {
    bool is64 = (ei32[1] == 0 && ei32[3] == 0 && ei32[5] == 0 && ei32[7] == 0);
    int e = blockIdx.x * blockDim.x + threadIdx.x;
    if (e < EE) {
        int s, d;
        if (is64) {
            s = ei32[2 * (size_t)e];
            d = ei32[2 * ((size_t)EE + e)];
        } else {
            s = ei32[e];
            d = ei32[EE + e];
        }
        g_src[e] = s;
        g_dst[e] = d;
        atomicAdd(&g_deg[d], 1);
    }
}

__global__ void zero_k() {
    int i = blockIdx.x * blockDim.x + threadIdx.x;
    if (i < NN) { g_deg[i] = 0; g_fill[i] = 0; }
}

__global__ void pscan_k() {
    __shared__ int sh[SB];
    int t = threadIdx.x;
    int i = blockIdx.x * SB + t;
    int v = (i < NN) ? g_deg[i] : 0;
    sh[t] = v;
    __syncthreads();
    for (int o = 1; o < SB; o <<= 1) {
        int a = (t >= o) ? sh[t - o] : 0;
        __syncthreads();
        sh[t] += a;
        __syncthreads();
    }
    if (i < NN) g_rowptr[i] = sh[t] - v;
    if (t == SB - 1) g_bsum[blockIdx.x] = sh[t];
}

__global__ void bscan_k() {
    __shared__ int sh[128];
    int t = threadIdx.x;
    int v = (t < NSB) ? g_bsum[t] : 0;
    sh[t] = v;
    __syncthreads();
    for (int o = 1; o < 128; o <<= 1) {
        int a = (t >= o) ? sh[t - o] : 0;
        __syncthreads();
        sh[t] += a;
        __syncthreads();
    }
    g_boff[t] = sh[t] - v;
}

__global__ void addoff_k() {
    int i = blockIdx.x * blockDim.x + threadIdx.x;
    if (i < NN) g_rowptr[i] += g_boff[i / SB];
    if (i == 0) g_rowptr[NN] = EE;
}

__global__ void scat_k() {
    int e = blockIdx.x * blockDim.x + threadIdx.x;
    if (e < EE) {
        int d = g_dst[e];
        int p = g_rowptr[d] + atomicAdd(&g_fill[d], 1);
        g_esrc[p] = g_src[e];
    }
}

// ---------------- one-time weight split: [k][n] fp32 -> [n][kword] bf16 hi/lo ----------------
// wslot 0 = W_in; 1+3*L+{0,1,2} = W_h, W_gat, W_l of layer L.
__global__ void split_w_k(const float* __restrict__ W_in, const float* __restrict__ W_h,
                          const float* __restrict__ W_gat, const float* __restrict__ W_l) {
    int idx = blockIdx.x * blockDim.x + threadIdx.x;   // 10*64*128
    if (idx >= 10 * 64 * 128) return;
    int w   = idx >> 13;           // /8192
    int kw  = (idx >> 7) & 63;     // word index (k pair)
    int n   = idx & 127;
    const float* base;
    if (w == 0) base = W_in;
    else {
        int layer = (w - 1) / 3, t = (w - 1) % 3;
        base = (t == 0 ? W_h : t == 1 ? W_gat : W_l) + (size_t)layer * DD * DD;
    }
    float v0 = base[(size_t)(2 * kw) * DD + n];
    float v1 = base[(size_t)(2 * kw + 1) * DD + n];
    uint32_t h0, l0, h1, l1;
    bsplit(v0, h0, l0); bsplit(v1, h1, l1);
    g_wsh[(size_t)w * 8192 + n * 64 + kw] = h0 | (h1 << 16);
    g_wsl[(size_t)w * 8192 + n * 64 + kw] = l0 | (l1 << 16);
}

// ---------------- one-time input split: x fp32 [NN][128] -> hi/lo packed ----------------
__global__ void split_x_k(const float* __restrict__ x) {
    int t = blockIdx.x * blockDim.x + threadIdx.x;     // NN*32
    if (t >= NN * 32) return;
    int row = t >> 5, q = t & 31;
    float4 v = ((const float4*)x)[(size_t)row * 32 + q];
    uint32_t hx, lx, hy, ly, hz, lz, hw, lw;
    bsplit(v.x, hx, lx); bsplit(v.y, hy, ly);
    bsplit(v.z, hz, lz); bsplit(v.w, hw, lw);
    size_t o = (size_t)row * 64 + 2 * q;
    g_inh[o]     = hx | (hy << 16);
    g_inh[o + 1] = hz | (hw << 16);
    g_inl[o]     = lx | (ly << 16);
    g_inl[o + 1] = lz | (lw << 16);
}

// ---------------- bf16x3 tensor-core GEMM with pre-split operands ----------------
struct GemmArgs2 {
    int          wslot[3];
    const float* bias[3];
    float*       out[3];     // fp32 output (nullptr to skip)
    int          epi[3];     // 0 = none, 1 = bias, 2 = bias+relu
    int          emit_split; // write result split to g_ah/g_al
};

__global__ __launch_bounds__(256, 2)
void mma_gemm_k(const uint32_t* __restrict__ Ah, const uint32_t* __restrict__ Al,
                GemmArgs2 args) {
    __shared__ uint32_t sAh[128 * PADW];
    __shared__ uint32_t sAl[128 * PADW];
    __shared__ uint32_t sWh[128 * PADW];
    __shared__ uint32_t sWl[128 * PADW];

    const int tid  = threadIdx.x;
    const int lane = tid & 31;
    const int wid  = tid >> 5;
    const int wm   = (wid >> 1) * 32;
    const int wn   = (wid & 1) * 64;
    const int row0 = blockIdx.x * 128;
    const int w    = blockIdx.y;

    const uint32_t* Wh = g_wsh + (size_t)args.wslot[w] * 8192;
    const uint32_t* Wl = g_wsl + (size_t)args.wslot[w] * 8192;

    const int ar = lane >> 2;   // 0..7
    const int ac = lane & 3;    // 0..3

    float acc[2][8][4];
#pragma unroll
    for (int i = 0; i < 2; i++)
#pragma unroll
        for (int j = 0; j < 8; j++)
#pragma unroll
            for (int c = 0; c < 4; c++) acc[i][j][c] = 0.f;

    for (int kc = 0; kc < DD; kc += 32) {
        const int kwc = kc >> 1;      // word offset of this chunk (16 words)
        // ---- stage A hi/lo: 128 rows x 4 uint4 = 512 tasks, 2/thread ----
#pragma unroll
        for (int t = tid; t < 512; t += 256) {
            int m = t >> 2, q = t & 3;
            int row = row0 + m;
            uint4 h = make_uint4(0, 0, 0, 0), l = make_uint4(0, 0, 0, 0);
            if (row < NN) {
                size_t o = (size_t)row * 64 + kwc + 4 * q;
                h = *(const uint4*)&Ah[o];
                l = *(const uint4*)&Al[o];
            }
            *(uint4*)&sAh[m * PADW + 4 * q] = h;
            *(uint4*)&sAl[m * PADW + 4 * q] = l;
        }
        // ---- stage W hi/lo: same pattern ----
#pragma unroll
        for (int t = tid; t < 512; t += 256) {
            int n = t >> 2, q = t & 3;
            size_t o = (size_t)n * 64 + kwc + 4 * q;
            *(uint4*)&sWh[n * PADW + 4 * q] = *(const uint4*)&Wh[o];
            *(uint4*)&sWl[n * PADW + 4 * q] = *(const uint4*)&Wl[o];
        }
        __syncthreads();

#pragma unroll
        for (int s = 0; s < 2; s++) {
            const int kb = s * 8;
            uint32_t ah[2][4], al[2][4];
#pragma unroll
            for (int i = 0; i < 2; i++) {
                int m = wm + i * 16 + ar;
                ah[i][0] = sAh[m * PADW + kb + ac];
                ah[i][1] = sAh[(m + 8) * PADW + kb + ac];
                ah[i][2] = sAh[m * PADW + kb + ac + 4];
                ah[i][3] = sAh[(m + 8) * PADW + kb + ac + 4];
                al[i][0] = sAl[m * PADW + kb + ac];
                al[i][1] = sAl[(m + 8) * PADW + kb + ac];
                al[i][2] = sAl[m * PADW + kb + ac + 4];
                al[i][3] = sAl[(m + 8) * PADW + kb + ac + 4];
            }
#pragma unroll
            for (int j = 0; j < 8; j++) {
                int n = wn + j * 8 + ar;
                uint32_t bh0 = sWh[n * PADW + kb + ac];
                uint32_t bh1 = sWh[n * PADW + kb + ac + 4];
                uint32_t bl0 = sWl[n * PADW + kb + ac];
                uint32_t bl1 = sWl[n * PADW + kb + ac + 4];
#pragma unroll
                for (int i = 0; i < 2; i++) {
                    asm volatile(
                        "mma.sync.aligned.m16n8k16.row.col.f32.bf16.bf16.f32 "
                        "{%0,%1,%2,%3}, {%4,%5,%6,%7}, {%8,%9}, {%0,%1,%2,%3};"
                        : "+f"(acc[i][j][0]), "+f"(acc[i][j][1]),
                          "+f"(acc[i][j][2]), "+f"(acc[i][j][3])
                        : "r"(ah[i][0]), "r"(ah[i][1]), "r"(ah[i][2]), "r"(ah[i][3]),
                          "r"(bh0), "r"(bh1));
                    asm volatile(
                        "mma.sync.aligned.m16n8k16.row.col.f32.bf16.bf16.f32 "
                        "{%0,%1,%2,%3}, {%4,%5,%6,%7}, {%8,%9}, {%0,%1,%2,%3};"
                        : "+f"(acc[i][j][0]), "+f"(acc[i][j][1]),
                          "+f"(acc[i][j][2]), "+f"(acc[i][j][3])
                        : "r"(ah[i][0]), "r"(ah[i][1]), "r"(ah[i][2]), "r"(ah[i][3]),
                          "r"(bl0), "r"(bl1));
                    asm volatile(
                        "mma.sync.aligned.m16n8k16.row.col.f32.bf16.bf16.f32 "
                        "{%0,%1,%2,%3}, {%4,%5,%6,%7}, {%8,%9}, {%0,%1,%2,%3};"
                        : "+f"(acc[i][j][0]), "+f"(acc[i][j][1]),
                          "+f"(acc[i][j][2]), "+f"(acc[i][j][3])
                        : "r"(al[i][0]), "r"(al[i][1]), "r"(al[i][2]), "r"(al[i][3]),
                          "r"(bh0), "r"(bh1));
                }
            }
        }
        __syncthreads();
    }

    // ---- epilogue ----
    const int epi = args.epi[w];
    const float* bias = args.bias[w];
    float* out = args.out[w];
    const int emit = args.emit_split;
#pragma unroll
    for (int i = 0; i < 2; i++) {
#pragma unroll
        for (int j = 0; j < 8; j++) {
            int cc = wn + j * 8 + ac * 2;
            float bx = 0.f, by = 0.f;
            if (epi >= 1) { bx = bias[cc]; by = bias[cc + 1]; }
            float c0 = acc[i][j][0] + bx, c1 = acc[i][j][1] + by;
            float c2 = acc[i][j][2] + bx, c3 = acc[i][j][3] + by;
            if (epi == 2) {
                c0 = fmaxf(c0, 0.f); c1 = fmaxf(c1, 0.f);
                c2 = fmaxf(c2, 0.f); c3 = fmaxf(c3, 0.f);
            }
            int r0 = row0 + wm + i * 16 + ar;
            if (out) {
                if (r0 < NN)     *(float2*)&out[(size_t)r0 * DD + cc]       = make_float2(c0, c1);
                if (r0 + 8 < NN) *(float2*)&out[(size_t)(r0 + 8) * DD + cc] = make_float2(c2, c3);
            }
            if (emit) {
                uint32_t h0, l0, h1, l1;
                if (r0 < NN) {
                    bsplit(c0, h0, l0); bsplit(c1, h1, l1);
                    g_ah[(size_t)r0 * 64 + (cc >> 1)] = h0 | (h1 << 16);
                    g_al[(size_t)r0 * 64 + (cc >> 1)] = l0 | (l1 << 16);
                }
                if (r0 + 8 < NN) {
                    bsplit(c2, h0, l0); bsplit(c3, h1, l1);
                    g_ah[(size_t)(r0 + 8) * 64 + (cc >> 1)] = h0 | (h1 << 16);
                    g_al[(size_t)(r0 + 8) * 64 + (cc >> 1)] = l0 | (l1 << 16);
                }
            }
        }
    }
}

// ---------------- small FFMA GEMM for the prediction head (NCOL=40) ----------------
template <int NCOL>
__global__ void gemm_small_k(const float* __restrict__ A, const float* __restrict__ W,
                             const float* __restrict__ bias, float* __restrict__ C) {
    constexpr int ROWS = 32;
    constexpr int KT   = 32;
    __shared__ float sA[ROWS][DD];
    __shared__ float sW[KT][NCOL];
    int tid  = threadIdx.x;
    int row0 = blockIdx.x * ROWS;

    {
        const float4* Af  = (const float4*)A;
        float4*       sAf = (float4*)sA;
#pragma unroll
        for (int i = 0; i < 4; i++) {
            int idx = tid + i * 256;
            int r = idx >> 5, c = idx & 31;
            float4 v = make_float4(0.f, 0.f, 0.f, 0.f);
            if (row0 + r < NN) v = Af[(size_t)(row0 + r) * 32 + c];
            sAf[idx] = v;
        }
    }

    int tx = tid & 31, ty = tid >> 5;
    const int col = tx * 4;
    float acc[4][4];
#pragma unroll
    for (int i = 0; i < 4; i++)
#pragma unroll
        for (int j = 0; j < 4; j++) acc[i][j] = 0.f;

    for (int kt = 0; kt < DD; kt += KT) {
        __syncthreads();
        {
            const float4* Wf  = (const float4*)(W + kt * NCOL);
            float4*       sWf = (float4*)sW;
            constexpr int T4 = KT * NCOL / 4;
            for (int i = tid; i < T4; i += 256) sWf[i] = Wf[i];
        }
        __syncthreads();
#pragma unroll
        for (int k = 0; k < KT; k++) {
            float4 wv = make_float4(0.f, 0.f, 0.f, 0.f);
            if (col < NCOL) wv = *(const float4*)&sW[k][col];
#pragma unroll
            for (int i = 0; i < 4; i++) {
                float a = sA[ty + i * 8][kt + k];
                acc[i][0] += a * wv.x;
                acc[i][1] += a * wv.y;
                acc[i][2] += a * wv.z;
                acc[i][3] += a * wv.w;
            }
        }
    }

    if (col < NCOL) {
        float4 bv = *(const float4*)&bias[col];
#pragma unroll
        for (int i = 0; i < 4; i++) {
            int row = row0 + ty + i * 8;
            if (row < NN) {
                float4 o;
                o.x = acc[i][0] + bv.x;
                o.y = acc[i][1] + bv.y;
                o.z = acc[i][2] + bv.z;
                o.w = acc[i][3] + bv.w;
                *(float4*)&C[(size_t)row * NCOL + col] = o;
            }
        }
    }
}

// ---------------- attention logits per node ----------------
__global__ void attn_k(const float* __restrict__ xh,
                       const float* __restrict__ asv, const float* __restrict__ adv) {
    int warp = (blockIdx.x * blockDim.x + threadIdx.x) >> 5;
    int lane = threadIdx.x & 31;
    if (warp >= NN) return;
    float4 v = ((const float4*)(xh + (size_t)warp * DD))[lane];
    float4 a = ((const float4*)asv)[lane];
    float4 d = ((const float4*)adv)[lane];
    float s = v.x * a.x + v.y * a.y + v.z * a.z + v.w * a.w;
    float t = v.x * d.x + v.y * d.y + v.z * d.z + v.w * d.w;
#pragma unroll
    for (int o = 16; o; o >>= 1) {
        s += __shfl_xor_sync(0xFFFFFFFFu, s, o);
        t += __shfl_xor_sync(0xFFFFFFFFu, t, o);
    }
    if (lane == 0) { g_as[warp] = s; g_ad[warp] = t; }
}

// ---------------- GAT softmax-aggregate: warp per destination node ----------------
__global__ void agg_k(const float* __restrict__ xh) {
    int n    = (blockIdx.x * blockDim.x + threadIdx.x) >> 5;
    int lane = threadIdx.x & 31;
    if (n >= NN) return;
    int s0 = g_rowptr[n], s1 = g_rowptr[n + 1];
    float adn = g_ad[n];

    float m = -1e30f;
    for (int i = s0 + lane; i < s1; i += 32) {
        int s  = g_esrc[i];
        float e = g_as[s] + adn;
        e = e > 0.f ? e : 0.2f * e;
        m = fmaxf(m, e);
    }
#pragma unroll
    for (int o = 16; o; o >>= 1) m = fmaxf(m, __shfl_xor_sync(0xFFFFFFFFu, m, o));

    float den = 0.f;
    for (int i = s0 + lane; i < s1; i += 32) {
        int s  = g_esrc[i];
        float e = g_as[s] + adn;
        e = e > 0.f ? e : 0.2f * e;
        den += __expf(e - m);
    }
#pragma unroll
    for (int o = 16; o; o >>= 1) den += __shfl_xor_sync(0xFFFFFFFFu, den, o);
    float inv = 1.f / (den + 1e-16f);

    float4 acc = make_float4(0.f, 0.f, 0.f, 0.f);
    for (int base = s0; base < s1; base += 32) {
        int idx = base + lane;
        float w = 0.f;
        int   s = 0;
        if (idx < s1) {
            s = g_esrc[idx];
            float e = g_as[s] + adn;
            e = e > 0.f ? e : 0.2f * e;
            w = __expf(e - m) * inv;
        }
        int cnt = min(32, s1 - base);
        for (int j = 0; j < cnt; j++) {
            float wj = __shfl_sync(0xFFFFFFFFu, w, j);
            int   sj = __shfl_sync(0xFFFFFFFFu, s, j);
            float4 v = ((const float4*)(xh + (size_t)sj * DD))[lane];
            acc.x += wj * v.x; acc.y += wj * v.y;
            acc.z += wj * v.z; acc.w += wj * v.w;
        }
    }
    ((float4*)(g_agg + (size_t)n * DD))[lane] = acc;
}

// ---------------- fused pointwise + emit bf16 split of new x ----------------
__global__ void fuse_k(const float* __restrict__ xlbuf, const float* __restrict__ hbuf,
                       const float* __restrict__ lng, const float* __restrict__ lnb,
                       const float* __restrict__ betas, int first) {
    int n    = (blockIdx.x * blockDim.x + threadIdx.x) >> 5;
    int lane = threadIdx.x & 31;
    if (n >= NN) return;
    size_t off = (size_t)n * DD;

    float4 ag = ((const float4*)(g_agg + off))[lane];
    float4 xl = ((const float4*)(xlbuf + off))[lane];
    float4 xn;
    xn.x = fmaxf(ag.x + xl.x, 0.f);
    xn.y = fmaxf(ag.y + xl.y, 0.f);
    xn.z = fmaxf(ag.z + xl.z, 0.f);
    xn.w = fmaxf(ag.w + xl.w, 0.f);

    float4 hh = ((const float4*)(hbuf + off))[lane];
    float4 t;
    t.x = hh.x * xn.x; t.y = hh.y * xn.y; t.z = hh.z * xn.z; t.w = hh.w * xn.w;

    float sum = t.x + t.y + t.z + t.w;
#pragma unroll
    for (int o = 16; o; o >>= 1) sum += __shfl_xor_sync(0xFFFFFFFFu, sum, o);
    float mu = sum * (1.f / 128.f);

    float4 dc;
    dc.x = t.x - mu; dc.y = t.y - mu; dc.z = t.z - mu; dc.w = t.w - mu;
    float ss = dc.x * dc.x + dc.y * dc.y + dc.z * dc.z + dc.w * dc.w;
#pragma unroll
    for (int o = 16; o; o >>= 1) ss += __shfl_xor_sync(0xFFFFFFFFu, ss, o);
    float rs = rsqrtf(ss * (1.f / 128.f) + 1e-5f);

    float4 g  = ((const float4*)lng)[lane];
    float4 b  = ((const float4*)lnb)[lane];
    float4 be = ((const float4*)betas)[lane];
    be.x = 1.f / (1.f + __expf(-be.x));
    be.y = 1.f / (1.f + __expf(-be.y));
    be.z = 1.f / (1.f + __expf(-be.z));
    be.w = 1.f / (1.f + __expf(-be.w));

    float4 y;
    y.x = dc.x * rs * g.x + b.x;
    y.y = dc.y * rs * g.y + b.y;
    y.z = dc.z * rs * g.z + b.z;
    y.w = dc.w * rs * g.w + b.w;

    float4 xo;
    xo.x = (1.f - be.x) * y.x + be.x * xn.x;
    xo.y = (1.f - be.y) * y.y + be.y * xn.y;
    xo.z = (1.f - be.z) * y.z + be.z * xn.z;
    xo.w = (1.f - be.w) * y.w + be.w * xn.w;

    // emit bf16 split of new x (next layer's GEMM A operand)
    {
        uint32_t hx, lx, hy, ly, hz, lz, hw, lw;
        bsplit(xo.x, hx, lx); bsplit(xo.y, hy, ly);
        bsplit(xo.z, hz, lz); bsplit(xo.w, hw, lw);
        size_t o2 = (size_t)n * 64 + 2 * lane;
        g_ah[o2]     = hx | (hy << 16);
        g_ah[o2 + 1] = hz | (hw << 16);
        g_al[o2]     = lx | (ly << 16);
        g_al[o2 + 1] = lz | (lw << 16);
    }

    if (first) {
        ((float4*)(g_xlocal + off))[lane] = xo;
    } else {
        float4 p = ((const float4*)(g_xlocal + off))[lane];
        p.x += xo.x; p.y += xo.y; p.z += xo.z; p.w += xo.w;
        ((float4*)(g_xlocal + off))[lane] = p;
    }
}

// ---------------- host ----------------
extern "C" void kernel_launch(void* const* d_in, const int* in_sizes, int n_in,
                              void* d_out, int out_size) {
    const float* x       = (const float*)d_in[0];
    const int*   ei32    = (const int*)d_in[1];
    const float* W_in    = (const float*)d_in[2];
    const float* b_in    = (const float*)d_in[3];
    const float* W_h     = (const float*)d_in[4];
    const float* b_h     = (const float*)d_in[5];
    const float* W_gat   = (const float*)d_in[6];
    const float* att_src = (const float*)d_in[7];
    const float* att_dst = (const float*)d_in[8];
    const float* W_l     = (const float*)d_in[9];
    const float* b_l     = (const float*)d_in[10];
    const float* ln_g    = (const float*)d_in[11];
    const float* ln_b    = (const float*)d_in[12];
    const float* betas   = (const float*)d_in[13];
    const float* W_pred  = (const float*)d_in[14];
    const float* b_pred  = (const float*)d_in[15];
    float*       out     = (float*)d_out;

    float *ph, *pxh, *pxl, *pxloc;
    uint32_t *pinh, *pinl, *pah, *pal;
    cudaGetSymbolAddress((void**)&ph,    g_h);
    cudaGetSymbolAddress((void**)&pxh,   g_xh);
    cudaGetSymbolAddress((void**)&pxl,   g_xl);
    cudaGetSymbolAddress((void**)&pxloc, g_xlocal);
    cudaGetSymbolAddress((void**)&pinh,  g_inh);
    cudaGetSymbolAddress((void**)&pinl,  g_inl);
    cudaGetSymbolAddress((void**)&pah,   g_ah);
    cudaGetSymbolAddress((void**)&pal,   g_al);

    dim3 gE((EE + 255) / 256);
    dim3 gN((NN + 255) / 256);
    dim3 gW((NN + 7) / 8);
    dim3 gG((NN + 31) / 32);
    dim3 gM((NN + 127) / 128, 1);
    dim3 gM3((NN + 127) / 128, 3);

    // CSR + one-time splits
    zero_k<<<gN, 256>>>();
    decode_deg_k<<<gE, 256>>>(ei32);
    split_w_k<<<(10 * 64 * 128 + 255) / 256, 256>>>(W_in, W_h, W_gat, W_l);
    split_x_k<<<(NN * 32 + 255) / 256, 256>>>(x);
    pscan_k<<<NSB, SB>>>();
    bscan_k<<<1, 128>>>();
    addoff_k<<<gN, 256>>>();
    scat_k<<<gE, 256>>>();

    // input projection: x @ W_in + b_in -> split only
    {
        GemmArgs2 a{};
        a.wslot[0] = 0; a.bias[0] = b_in; a.out[0] = nullptr; a.epi[0] = 1;
        a.emit_split = 1;
        mma_gemm_k<<<gM, 256>>>(pinh, pinl, a);
    }

    for (int i = 0; i < LL; i++) {
        GemmArgs2 a{};
        a.wslot[0] = 1 + 3 * i;     a.bias[0] = b_h + i * DD; a.out[0] = ph;  a.epi[0] = 2;
        a.wslot[1] = 1 + 3 * i + 1; a.bias[1] = nullptr;      a.out[1] = pxh; a.epi[1] = 0;
        a.wslot[2] = 1 + 3 * i + 2; a.bias[2] = b_l + i * DD; a.out[2] = pxl; a.epi[2] = 1;
        a.emit_split = 0;
        mma_gemm_k<<<gM3, 256>>>(pah, pal, a);

        attn_k<<<gW, 256>>>(pxh, att_src + i * DD, att_dst + i * DD);
        agg_k<<<gW, 256>>>(pxh);
        fuse_k<<<gW, 256>>>(pxl, ph, ln_g + i * DD, ln_b + i * DD, betas + i * DD, i == 0);
    }

    gemm_small_k<OUTD><<<gG, 256>>>(pxloc, W_pred, b_pred, out);
}

// round 7
// speedup vs baseline: 1.6303x; 1.0666x over previous
#include <cuda_runtime.h>
#include <cuda_bf16.h>
#include <math.h>
#include <stdint.h>

#define NN   50000
#define EE   800000
#define DD   128
#define LL   3
#define OUTD 40
#define SB   512
#define NSB  ((NN + SB - 1) / SB)   // 98
#define PADW 20
#define SZW  (128 * PADW)           // words per smem tile (2560)

// ---------------- scratch (device globals; no allocation allowed) ----------------
__device__ float    g_h[NN * DD];
__device__ float    g_xh[NN * DD];
__device__ float    g_xl[NN * DD];
__device__ float    g_agg[NN * DD];
__device__ float    g_xlocal[NN * DD];
__device__ float    g_as[NN];
__device__ float    g_ad[NN];
__device__ int      g_deg[NN];
__device__ int      g_fill[NN];
__device__ int      g_rowptr[NN + 1];
__device__ int      g_esrc[EE];
__device__ int      g_src[EE];
__device__ int      g_dst[EE];
__device__ int      g_bsum[NSB];
__device__ int      g_boff[128];
// packed bf16 pairs (hi/lo) along k: [row][64 words]
__device__ uint32_t g_inh[NN * 64];
__device__ uint32_t g_inl[NN * 64];
__device__ uint32_t g_ah[NN * 64];
__device__ uint32_t g_al[NN * 64];
// pre-split weights: [wslot][n][64 words], 10 slots
__device__ uint32_t g_wsh[10 * 128 * 64];
__device__ uint32_t g_wsl[10 * 128 * 64];

__device__ __forceinline__ void bsplit(float v, uint32_t& h, uint32_t& l) {
    __nv_bfloat16 bh = __float2bfloat16_rn(v);
    float r = v - __bfloat162float(bh);
    __nv_bfloat16 bl = __float2bfloat16_rn(r);
    h = (uint32_t)__bfloat16_as_ushort(bh);
    l = (uint32_t)__bfloat16_as_ushort(bl);
}

__device__ __forceinline__ void cp16(uint32_t* dst_s, const uint32_t* src_g) {
    uint32_t d = (uint32_t)__cvta_generic_to_shared(dst_s);
    asm volatile("cp.async.cg.shared.global [%0], [%1], 16;" :: "r"(d), "l"(src_g));
}

// ---------------- edge decode + degree histogram (fused) ----------------
__global__ void decode_deg_k(const int* __restrict__ ei32) {
    bool is64 = (ei32[1] == 0 && ei32[3] == 0 && ei32[5] == 0 && ei32[7] == 0);
    int e = blockIdx.x * blockDim.x + threadIdx.x;
    if (e < EE) {
        int s, d;
        if (is64) {
            s = ei32[2 * (size_t)e];
            d = ei32[2 * ((size_t)EE + e)];
        } else {
            s = ei32[e];
            d = ei32[EE + e];
        }
        g_src[e] = s;
        g_dst[e] = d;
        atomicAdd(&g_deg[d], 1);
    }
}

__global__ void zero_k() {
    int i = blockIdx.x * blockDim.x + threadIdx.x;
    if (i < NN) { g_deg[i] = 0; g_fill[i] = 0; }
}

__global__ void pscan_k() {
    __shared__ int sh[SB];
    int t = threadIdx.x;
    int i = blockIdx.x * SB + t;
    int v = (i < NN) ? g_deg[i] : 0;
    sh[t] = v;
    __syncthreads();
    for (int o = 1; o < SB; o <<= 1) {
        int a = (t >= o) ? sh[t - o] : 0;
        __syncthreads();
        sh[t] += a;
        __syncthreads();
    }
    if (i < NN) g_rowptr[i] = sh[t] - v;
    if (t == SB - 1) g_bsum[blockIdx.x] = sh[t];
}

__global__ void bscan_k() {
    __shared__ int sh[128];
    int t = threadIdx.x;
    int v = (t < NSB) ? g_bsum[t] : 0;
    sh[t] = v;
    __syncthreads();
    for (int o = 1; o < 128; o <<= 1) {
        int a = (t >= o) ? sh[t - o] : 0;
        __syncthreads();
        sh[t] += a;
        __syncthreads();
    }
    g_boff[t] = sh[t] - v;
}

__global__ void addoff_k() {
    int i = blockIdx.x * blockDim.x + threadIdx.x;
    if (i < NN) g_rowptr[i] += g_boff[i / SB];
    if (i == 0) g_rowptr[NN] = EE;
}

__global__ void scat_k() {
    int e = blockIdx.x * blockDim.x + threadIdx.x;
    if (e < EE) {
        int d = g_dst[e];
        int p = g_rowptr[d] + atomicAdd(&g_fill[d], 1);
        g_esrc[p] = g_src[e];
    }
}

// ---------------- one-time weight split ----------------
__global__ void split_w_k(const float* __restrict__ W_in, const float* __restrict__ W_h,
                          const float* __restrict__ W_gat, const float* __restrict__ W_l) {
    int idx = blockIdx.x * blockDim.x + threadIdx.x;   // 10*64*128
    if (idx >= 10 * 64 * 128) return;
    int w   = idx >> 13;
    int kw  = (idx >> 7) & 63;
    int n   = idx & 127;
    const float* base;
    if (w == 0) base = W_in;
    else {
        int layer = (w - 1) / 3, t = (w - 1) % 3;
        base = (t == 0 ? W_h : t == 1 ? W_gat : W_l) + (size_t)layer * DD * DD;
    }
    float v0 = base[(size_t)(2 * kw) * DD + n];
    float v1 = base[(size_t)(2 * kw + 1) * DD + n];
    uint32_t h0, l0, h1, l1;
    bsplit(v0, h0, l0); bsplit(v1, h1, l1);
    g_wsh[(size_t)w * 8192 + n * 64 + kw] = h0 | (h1 << 16);
    g_wsl[(size_t)w * 8192 + n * 64 + kw] = l0 | (l1 << 16);
}

// ---------------- one-time input split ----------------
__global__ void split_x_k(const float* __restrict__ x) {
    int t = blockIdx.x * blockDim.x + threadIdx.x;     // NN*32
    if (t >= NN * 32) return;
    int row = t >> 5, q = t & 31;
    float4 v = ((const float4*)x)[(size_t)row * 32 + q];
    uint32_t hx, lx, hy, ly, hz, lz, hw, lw;
    bsplit(v.x, hx, lx); bsplit(v.y, hy, ly);
    bsplit(v.z, hz, lz); bsplit(v.w, hw, lw);
    size_t o = (size_t)row * 64 + 2 * q;
    g_inh[o]     = hx | (hy << 16);
    g_inh[o + 1] = hz | (hw << 16);
    g_inl[o]     = lx | (ly << 16);
    g_inl[o + 1] = lz | (lw << 16);
}

// ---------------- bf16x3 GEMM, cp.async double-buffered ----------------
struct GemmArgs2 {
    int          wslot[3];
    const float* bias[3];
    float*       out[3];
    int          epi[3];     // 0 none, 1 bias, 2 bias+relu
    int          emit_split;
};

extern __shared__ uint32_t smem_dyn[];

__global__ __launch_bounds__(256, 2)
void mma_gemm_k(const uint32_t* __restrict__ Ah, const uint32_t* __restrict__ Al,
                GemmArgs2 args) {
    const int tid  = threadIdx.x;
    const int lane = tid & 31;
    const int wid  = tid >> 5;
    const int wm   = (wid >> 1) * 32;
    const int wn   = (wid & 1) * 64;
    const int row0 = blockIdx.x * 128;
    const int w    = blockIdx.y;

    const uint32_t* Wh = g_wsh + (size_t)args.wslot[w] * 8192;
    const uint32_t* Wl = g_wsl + (size_t)args.wslot[w] * 8192;

    const int ar = lane >> 2;
    const int ac = lane & 3;

    float acc[2][8][4];
#pragma unroll
    for (int i = 0; i < 2; i++)
#pragma unroll
        for (int j = 0; j < 8; j++)
#pragma unroll
            for (int c = 0; c < 4; c++) acc[i][j][c] = 0.f;

    // async-stage one 32-k chunk into stage buffer s
    auto stage = [&](int kc, int s) {
        uint32_t* bAh = smem_dyn + s * 4 * SZW;
        uint32_t* bAl = bAh + SZW;
        uint32_t* bWh = bAl + SZW;
        uint32_t* bWl = bWh + SZW;
        const int kwc = kc >> 1;
#pragma unroll
        for (int t = tid; t < 512; t += 256) {
            int m = t >> 2, q = t & 3;
            int row = row0 + m;
            uint32_t* dh = &bAh[m * PADW + 4 * q];
            uint32_t* dl = &bAl[m * PADW + 4 * q];
            if (row < NN) {
                size_t o = (size_t)row * 64 + kwc + 4 * q;
                cp16(dh, &Ah[o]);
                cp16(dl, &Al[o]);
            } else {
                *(uint4*)dh = make_uint4(0, 0, 0, 0);
                *(uint4*)dl = make_uint4(0, 0, 0, 0);
            }
        }
#pragma unroll
        for (int t = tid; t < 512; t += 256) {
            int n = t >> 2, q = t & 3;
            size_t o = (size_t)n * 64 + kwc + 4 * q;
            cp16(&bWh[n * PADW + 4 * q], &Wh[o]);
            cp16(&bWl[n * PADW + 4 * q], &Wl[o]);
        }
        asm volatile("cp.async.commit_group;");
    };

    stage(0, 0);

#pragma unroll
    for (int c = 0; c < 4; c++) {
        if (c < 3) stage((c + 1) * 32, (c + 1) & 1);
        if (c < 3) asm volatile("cp.async.wait_group 1;");
        else       asm volatile("cp.async.wait_group 0;");
        __syncthreads();

        const uint32_t* bAh = smem_dyn + (c & 1) * 4 * SZW;
        const uint32_t* bAl = bAh + SZW;
        const uint32_t* bWh = bAl + SZW;
        const uint32_t* bWl = bWh + SZW;

#pragma unroll
        for (int s = 0; s < 2; s++) {
            const int kb = s * 8;
            uint32_t ah[2][4], al[2][4];
#pragma unroll
            for (int i = 0; i < 2; i++) {
                int m = wm + i * 16 + ar;
                ah[i][0] = bAh[m * PADW + kb + ac];
                ah[i][1] = bAh[(m + 8) * PADW + kb + ac];
                ah[i][2] = bAh[m * PADW + kb + ac + 4];
                ah[i][3] = bAh[(m + 8) * PADW + kb + ac + 4];
                al[i][0] = bAl[m * PADW + kb + ac];
                al[i][1] = bAl[(m + 8) * PADW + kb + ac];
                al[i][2] = bAl[m * PADW + kb + ac + 4];
                al[i][3] = bAl[(m + 8) * PADW + kb + ac + 4];
            }
#pragma unroll
            for (int j = 0; j < 8; j++) {
                int n = wn + j * 8 + ar;
                uint32_t bh0 = bWh[n * PADW + kb + ac];
                uint32_t bh1 = bWh[n * PADW + kb + ac + 4];
                uint32_t bl0 = bWl[n * PADW + kb + ac];
                uint32_t bl1 = bWl[n * PADW + kb + ac + 4];
#pragma unroll
                for (int i = 0; i < 2; i++) {
                    asm volatile(
                        "mma.sync.aligned.m16n8k16.row.col.f32.bf16.bf16.f32 "
                        "{%0,%1,%2,%3}, {%4,%5,%6,%7}, {%8,%9}, {%0,%1,%2,%3};"
                        : "+f"(acc[i][j][0]), "+f"(acc[i][j][1]),
                          "+f"(acc[i][j][2]), "+f"(acc[i][j][3])
                        : "r"(ah[i][0]), "r"(ah[i][1]), "r"(ah[i][2]), "r"(ah[i][3]),
                          "r"(bh0), "r"(bh1));
                    asm volatile(
                        "mma.sync.aligned.m16n8k16.row.col.f32.bf16.bf16.f32 "
                        "{%0,%1,%2,%3}, {%4,%5,%6,%7}, {%8,%9}, {%0,%1,%2,%3};"
                        : "+f"(acc[i][j][0]), "+f"(acc[i][j][1]),
                          "+f"(acc[i][j][2]), "+f"(acc[i][j][3])
                        : "r"(ah[i][0]), "r"(ah[i][1]), "r"(ah[i][2]), "r"(ah[i][3]),
                          "r"(bl0), "r"(bl1));
                    asm volatile(
                        "mma.sync.aligned.m16n8k16.row.col.f32.bf16.bf16.f32 "
                        "{%0,%1,%2,%3}, {%4,%5,%6,%7}, {%8,%9}, {%0,%1,%2,%3};"
                        : "+f"(acc[i][j][0]), "+f"(acc[i][j][1]),
                          "+f"(acc[i][j][2]), "+f"(acc[i][j][3])
                        : "r"(al[i][0]), "r"(al[i][1]), "r"(al[i][2]), "r"(al[i][3]),
                          "r"(bh0), "r"(bh1));
                }
            }
        }
        __syncthreads();
    }

    // ---- epilogue ----
    const int epi = args.epi[w];
    const float* bias = args.bias[w];
    float* out = args.out[w];
    const int emit = args.emit_split;
#pragma unroll
    for (int i = 0; i < 2; i++) {
#pragma unroll
        for (int j = 0; j < 8; j++) {
            int cc = wn + j * 8 + ac * 2;
            float bx = 0.f, by = 0.f;
            if (epi >= 1) { bx = bias[cc]; by = bias[cc + 1]; }
            float c0 = acc[i][j][0] + bx, c1 = acc[i][j][1] + by;
            float c2 = acc[i][j][2] + bx, c3 = acc[i][j][3] + by;
            if (epi == 2) {
                c0 = fmaxf(c0, 0.f); c1 = fmaxf(c1, 0.f);
                c2 = fmaxf(c2, 0.f); c3 = fmaxf(c3, 0.f);
            }
            int r0 = row0 + wm + i * 16 + ar;
            if (out) {
                if (r0 < NN)     *(float2*)&out[(size_t)r0 * DD + cc]       = make_float2(c0, c1);
                if (r0 + 8 < NN) *(float2*)&out[(size_t)(r0 + 8) * DD + cc] = make_float2(c2, c3);
            }
            if (emit) {
                uint32_t h0, l0, h1, l1;
                if (r0 < NN) {
                    bsplit(c0, h0, l0); bsplit(c1, h1, l1);
                    g_ah[(size_t)r0 * 64 + (cc >> 1)] = h0 | (h1 << 16);
                    g_al[(size_t)r0 * 64 + (cc >> 1)] = l0 | (l1 << 16);
                }
                if (r0 + 8 < NN) {
                    bsplit(c2, h0, l0); bsplit(c3, h1, l1);
                    g_ah[(size_t)(r0 + 8) * 64 + (cc >> 1)] = h0 | (h1 << 16);
                    g_al[(size_t)(r0 + 8) * 64 + (cc >> 1)] = l0 | (l1 << 16);
                }
            }
        }
    }
}

// ---------------- small FFMA GEMM for the prediction head (NCOL=40) ----------------
template <int NCOL>
__global__ void gemm_small_k(const float* __restrict__ A, const float* __restrict__ W,
                             const float* __restrict__ bias, float* __restrict__ C) {
    constexpr int ROWS = 32;
    constexpr int KT   = 32;
    __shared__ float sA[ROWS][DD];
    __shared__ float sW[KT][NCOL];
    int tid  = threadIdx.x;
    int row0 = blockIdx.x * ROWS;

    {
        const float4* Af  = (const float4*)A;
        float4*       sAf = (float4*)sA;
#pragma unroll
        for (int i = 0; i < 4; i++) {
            int idx = tid + i * 256;
            int r = idx >> 5, c = idx & 31;
            float4 v = make_float4(0.f, 0.f, 0.f, 0.f);
            if (row0 + r < NN) v = Af[(size_t)(row0 + r) * 32 + c];
            sAf[idx] = v;
        }
    }

    int tx = tid & 31, ty = tid >> 5;
    const int col = tx * 4;
    float acc[4][4];
#pragma unroll
    for (int i = 0; i < 4; i++)
#pragma unroll
        for (int j = 0; j < 4; j++) acc[i][j] = 0.f;

    for (int kt = 0; kt < DD; kt += KT) {
        __syncthreads();
        {
            const float4* Wf  = (const float4*)(W + kt * NCOL);
            float4*       sWf = (float4*)sW;
            constexpr int T4 = KT * NCOL / 4;
            for (int i = tid; i < T4; i += 256) sWf[i] = Wf[i];
        }
        __syncthreads();
#pragma unroll
        for (int k = 0; k < KT; k++) {
            float4 wv = make_float4(0.f, 0.f, 0.f, 0.f);
            if (col < NCOL) wv = *(const float4*)&sW[k][col];
#pragma unroll
            for (int i = 0; i < 4; i++) {
                float a = sA[ty + i * 8][kt + k];
                acc[i][0] += a * wv.x;
                acc[i][1] += a * wv.y;
                acc[i][2] += a * wv.z;
                acc[i][3] += a * wv.w;
            }
        }
    }

    if (col < NCOL) {
        float4 bv = *(const float4*)&bias[col];
#pragma unroll
        for (int i = 0; i < 4; i++) {
            int row = row0 + ty + i * 8;
            if (row < NN) {
                float4 o;
                o.x = acc[i][0] + bv.x;
                o.y = acc[i][1] + bv.y;
                o.z = acc[i][2] + bv.z;
                o.w = acc[i][3] + bv.w;
                *(float4*)&C[(size_t)row * NCOL + col] = o;
            }
        }
    }
}

// ---------------- attention logits per node ----------------
__global__ void attn_k(const float* __restrict__ xh,
                       const float* __restrict__ asv, const float* __restrict__ adv) {
    int warp = (blockIdx.x * blockDim.x + threadIdx.x) >> 5;
    int lane = threadIdx.x & 31;
    if (warp >= NN) return;
    float4 v = ((const float4*)(xh + (size_t)warp * DD))[lane];
    float4 a = ((const float4*)asv)[lane];
    float4 d = ((const float4*)adv)[lane];
    float s = v.x * a.x + v.y * a.y + v.z * a.z + v.w * a.w;
    float t = v.x * d.x + v.y * d.y + v.z * d.z + v.w * d.w;
#pragma unroll
    for (int o = 16; o; o >>= 1) {
        s += __shfl_xor_sync(0xFFFFFFFFu, s, o);
        t += __shfl_xor_sync(0xFFFFFFFFu, t, o);
    }
    if (lane == 0) { g_as[warp] = s; g_ad[warp] = t; }
}

// ---------------- GAT softmax-aggregate: warp per destination node ----------------
__global__ void agg_k(const float* __restrict__ xh) {
    int n    = (blockIdx.x * blockDim.x + threadIdx.x) >> 5;
    int lane = threadIdx.x & 31;
    if (n >= NN) return;
    int s0 = g_rowptr[n], s1 = g_rowptr[n + 1];
    float adn = g_ad[n];

    float m = -1e30f;
    for (int i = s0 + lane; i < s1; i += 32) {
        int s  = g_esrc[i];
        float e = g_as[s] + adn;
        e = e > 0.f ? e : 0.2f * e;
        m = fmaxf(m, e);
    }
#pragma unroll
    for (int o = 16; o; o >>= 1) m = fmaxf(m, __shfl_xor_sync(0xFFFFFFFFu, m, o));

    float den = 0.f;
    for (int i = s0 + lane; i < s1; i += 32) {
        int s  = g_esrc[i];
        float e = g_as[s] + adn;
        e = e > 0.f ? e : 0.2f * e;
        den += __expf(e - m);
    }
#pragma unroll
    for (int o = 16; o; o >>= 1) den += __shfl_xor_sync(0xFFFFFFFFu, den, o);
    float inv = 1.f / (den + 1e-16f);

    float4 acc = make_float4(0.f, 0.f, 0.f, 0.f);
    for (int base = s0; base < s1; base += 32) {
        int idx = base + lane;
        float w = 0.f;
        int   s = 0;
        if (idx < s1) {
            s = g_esrc[idx];
            float e = g_as[s] + adn;
            e = e > 0.f ? e : 0.2f * e;
            w = __expf(e - m) * inv;
        }
        int cnt = min(32, s1 - base);
        for (int j = 0; j < cnt; j++) {
            float wj = __shfl_sync(0xFFFFFFFFu, w, j);
            int   sj = __shfl_sync(0xFFFFFFFFu, s, j);
            float4 v = ((const float4*)(xh + (size_t)sj * DD))[lane];
            acc.x += wj * v.x; acc.y += wj * v.y;
            acc.z += wj * v.z; acc.w += wj * v.w;
        }
    }
    ((float4*)(g_agg + (size_t)n * DD))[lane] = acc;
}

// ---------------- fused pointwise + emit bf16 split of new x ----------------
__global__ void fuse_k(const float* __restrict__ xlbuf, const float* __restrict__ hbuf,
                       const float* __restrict__ lng, const float* __restrict__ lnb,
                       const float* __restrict__ betas, int first) {
    int n    = (blockIdx.x * blockDim.x + threadIdx.x) >> 5;
    int lane = threadIdx.x & 31;
    if (n >= NN) return;
    size_t off = (size_t)n * DD;

    float4 ag = ((const float4*)(g_agg + off))[lane];
    float4 xl = ((const float4*)(xlbuf + off))[lane];
    float4 xn;
    xn.x = fmaxf(ag.x + xl.x, 0.f);
    xn.y = fmaxf(ag.y + xl.y, 0.f);
    xn.z = fmaxf(ag.z + xl.z, 0.f);
    xn.w = fmaxf(ag.w + xl.w, 0.f);

    float4 hh = ((const float4*)(hbuf + off))[lane];
    float4 t;
    t.x = hh.x * xn.x; t.y = hh.y * xn.y; t.z = hh.z * xn.z; t.w = hh.w * xn.w;

    float sum = t.x + t.y + t.z + t.w;
#pragma unroll
    for (int o = 16; o; o >>= 1) sum += __shfl_xor_sync(0xFFFFFFFFu, sum, o);
    float mu = sum * (1.f / 128.f);

    float4 dc;
    dc.x = t.x - mu; dc.y = t.y - mu; dc.z = t.z - mu; dc.w = t.w - mu;
    float ss = dc.x * dc.x + dc.y * dc.y + dc.z * dc.z + dc.w * dc.w;
#pragma unroll
    for (int o = 16; o; o >>= 1) ss += __shfl_xor_sync(0xFFFFFFFFu, ss, o);
    float rs = rsqrtf(ss * (1.f / 128.f) + 1e-5f);

    float4 g  = ((const float4*)lng)[lane];
    float4 b  = ((const float4*)lnb)[lane];
    float4 be = ((const float4*)betas)[lane];
    be.x = 1.f / (1.f + __expf(-be.x));
    be.y = 1.f / (1.f + __expf(-be.y));
    be.z = 1.f / (1.f + __expf(-be.z));
    be.w = 1.f / (1.f + __expf(-be.w));

    float4 y;
    y.x = dc.x * rs * g.x + b.x;
    y.y = dc.y * rs * g.y + b.y;
    y.z = dc.z * rs * g.z + b.z;
    y.w = dc.w * rs * g.w + b.w;

    float4 xo;
    xo.x = (1.f - be.x) * y.x + be.x * xn.x;
    xo.y = (1.f - be.y) * y.y + be.y * xn.y;
    xo.z = (1.f - be.z) * y.z + be.z * xn.z;
    xo.w = (1.f - be.w) * y.w + be.w * xn.w;

    {
        uint32_t hx, lx, hy, ly, hz, lz, hw, lw;
        bsplit(xo.x, hx, lx); bsplit(xo.y, hy, ly);
        bsplit(xo.z, hz, lz); bsplit(xo.w, hw, lw);
        size_t o2 = (size_t)n * 64 + 2 * lane;
        g_ah[o2]     = hx | (hy << 16);
        g_ah[o2 + 1] = hz | (hw << 16);
        g_al[o2]     = lx | (ly << 16);
        g_al[o2 + 1] = lz | (lw << 16);
    }

    if (first) {
        ((float4*)(g_xlocal + off))[lane] = xo;
    } else {
        float4 p = ((const float4*)(g_xlocal + off))[lane];
        p.x += xo.x; p.y += xo.y; p.z += xo.z; p.w += xo.w;
        ((float4*)(g_xlocal + off))[lane] = p;
    }
}

// ---------------- host ----------------
extern "C" void kernel_launch(void* const* d_in, const int* in_sizes, int n_in,
                              void* d_out, int out_size) {
    const float* x       = (const float*)d_in[0];
    const int*   ei32    = (const int*)d_in[1];
    const float* W_in    = (const float*)d_in[2];
    const float* b_in    = (const float*)d_in[3];
    const float* W_h     = (const float*)d_in[4];
    const float* b_h     = (const float*)d_in[5];
    const float* W_gat   = (const float*)d_in[6];
    const float* att_src = (const float*)d_in[7];
    const float* att_dst = (const float*)d_in[8];
    const float* W_l     = (const float*)d_in[9];
    const float* b_l     = (const float*)d_in[10];
    const float* ln_g    = (const float*)d_in[11];
    const float* ln_b    = (const float*)d_in[12];
    const float* betas   = (const float*)d_in[13];
    const float* W_pred  = (const float*)d_in[14];
    const float* b_pred  = (const float*)d_in[15];
    float*       out     = (float*)d_out;

    float *ph, *pxh, *pxl, *pxloc;
    uint32_t *pinh, *pinl, *pah, *pal;
    cudaGetSymbolAddress((void**)&ph,    g_h);
    cudaGetSymbolAddress((void**)&pxh,   g_xh);
    cudaGetSymbolAddress((void**)&pxl,   g_xl);
    cudaGetSymbolAddress((void**)&pxloc, g_xlocal);
    cudaGetSymbolAddress((void**)&pinh,  g_inh);
    cudaGetSymbolAddress((void**)&pinl,  g_inl);
    cudaGetSymbolAddress((void**)&pah,   g_ah);
    cudaGetSymbolAddress((void**)&pal,   g_al);

    const int dynsmem = 2 * 4 * SZW * 4;   // 81920 bytes
    static int attr_set = 0;
    if (!attr_set) {
        cudaFuncSetAttribute(mma_gemm_k, cudaFuncAttributeMaxDynamicSharedMemorySize, dynsmem);
        attr_set = 1;
    }

    dim3 gE((EE + 255) / 256);
    dim3 gN((NN + 255) / 256);
    dim3 gW((NN + 7) / 8);
    dim3 gG((NN + 31) / 32);
    dim3 gM((NN + 127) / 128, 1);
    dim3 gM3((NN + 127) / 128, 3);

    // CSR + one-time splits
    zero_k<<<gN, 256>>>();
    decode_deg_k<<<gE, 256>>>(ei32);
    split_w_k<<<(10 * 64 * 128 + 255) / 256, 256>>>(W_in, W_h, W_gat, W_l);
    split_x_k<<<(NN * 32 + 255) / 256, 256>>>(x);
    pscan_k<<<NSB, SB>>>();
    bscan_k<<<1, 128>>>();
    addoff_k<<<gN, 256>>>();
    scat_k<<<gE, 256>>>();

    // input projection: x @ W_in + b_in -> split only
    {
        GemmArgs2 a{};
        a.wslot[0] = 0; a.bias[0] = b_in; a.out[0] = nullptr; a.epi[0] = 1;
        a.emit_split = 1;
        mma_gemm_k<<<gM, 256, dynsmem>>>(pinh, pinl, a);
    }

    for (int i = 0; i < LL; i++) {
        GemmArgs2 a{};
        a.wslot[0] = 1 + 3 * i;     a.bias[0] = b_h + i * DD; a.out[0] = ph;  a.epi[0] = 2;
        a.wslot[1] = 1 + 3 * i + 1; a.bias[1] = nullptr;      a.out[1] = pxh; a.epi[1] = 0;
        a.wslot[2] = 1 + 3 * i + 2; a.bias[2] = b_l + i * DD; a.out[2] = pxl; a.epi[2] = 1;
        a.emit_split = 0;
        mma_gemm_k<<<gM3, 256, dynsmem>>>(pah, pal, a);

        attn_k<<<gW, 256>>>(pxh, att_src + i * DD, att_dst + i * DD);
        agg_k<<<gW, 256>>>(pxh);
        fuse_k<<<gW, 256>>>(pxl, ph, ln_g + i * DD, ln_b + i * DD, betas + i * DD, i == 0);
    }

    gemm_small_k<OUTD><<<gG, 256>>>(pxloc, W_pred, b_pred, out);
}

// round 8
// speedup vs baseline: 1.6495x; 1.0118x over previous
#include <cuda_runtime.h>
#include <cuda_bf16.h>
#include <math.h>
#include <stdint.h>

#define NN   50000
#define EE   800000
#define DD   128
#define LL   3
#define OUTD 40
#define SB   512
#define NSB  ((NN + SB - 1) / SB)   // 98
#define PADW 20
#define SZW  (128 * PADW)           // words per smem tile (2560)

// ---------------- scratch (device globals; no allocation allowed) ----------------
__device__ float    g_h[NN * DD];
__device__ float    g_xh[NN * DD];
__device__ float    g_xl[NN * DD];
__device__ float    g_agg[NN * DD];
__device__ float    g_xlocal[NN * DD];
__device__ float    g_as[NN];
__device__ float    g_ad[NN];
__device__ float    g_ew[EE];
__device__ int      g_deg[NN];
__device__ int      g_fill[NN];
__device__ int      g_rowptr[NN + 1];
__device__ int      g_esrc[EE];
__device__ int      g_src[EE];
__device__ int      g_dst[EE];
__device__ int      g_bsum[NSB];
__device__ int      g_boff[128];
// packed bf16 pairs (hi/lo) along k: [row][64 words]
__device__ uint32_t g_inh[NN * 64];
__device__ uint32_t g_inl[NN * 64];
__device__ uint32_t g_ah[NN * 64];
__device__ uint32_t g_al[NN * 64];
// pre-split weights: [wslot][n][64 words], 10 slots
__device__ uint32_t g_wsh[10 * 128 * 64];
__device__ uint32_t g_wsl[10 * 128 * 64];

__device__ __forceinline__ void bsplit(float v, uint32_t& h, uint32_t& l) {
    __nv_bfloat16 bh = __float2bfloat16_rn(v);
    float r = v - __bfloat162float(bh);
    __nv_bfloat16 bl = __float2bfloat16_rn(r);
    h = (uint32_t)__bfloat16_as_ushort(bh);
    l = (uint32_t)__bfloat16_as_ushort(bl);
}

__device__ __forceinline__ void cp16(uint32_t* dst_s, const uint32_t* src_g) {
    uint32_t d = (uint32_t)__cvta_generic_to_shared(dst_s);
    asm volatile("cp.async.cg.shared.global [%0], [%1], 16;" :: "r"(d), "l"(src_g));
}

// ---------------- edge decode + degree histogram (fused) ----------------
__global__ void decode_deg_k(const int* __restrict__ ei32) {
    bool is64 = (ei32[1] == 0 && ei32[3] == 0 && ei32[5] == 0 && ei32[7] == 0);
    int e = blockIdx.x * blockDim.x + threadIdx.x;
    if (e < EE) {
        int s, d;
        if (is64) {
            s = ei32[2 * (size_t)e];
            d = ei32[2 * ((size_t)EE + e)];
        } else {
            s = ei32[e];
            d = ei32[EE + e];
        }
        g_src[e] = s;
        g_dst[e] = d;
        atomicAdd(&g_deg[d], 1);
    }
}

__global__ void zero_k() {
    int i = blockIdx.x * blockDim.x + threadIdx.x;
    if (i < NN) { g_deg[i] = 0; g_fill[i] = 0; g_as[i] = 0.f; g_ad[i] = 0.f; }
}

__global__ void pscan_k() {
    __shared__ int sh[SB];
    int t = threadIdx.x;
    int i = blockIdx.x * SB + t;
    int v = (i < NN) ? g_deg[i] : 0;
    sh[t] = v;
    __syncthreads();
    for (int o = 1; o < SB; o <<= 1) {
        int a = (t >= o) ? sh[t - o] : 0;
        __syncthreads();
        sh[t] += a;
        __syncthreads();
    }
    if (i < NN) g_rowptr[i] = sh[t] - v;
    if (t == SB - 1) g_bsum[blockIdx.x] = sh[t];
}

__global__ void bscan_k() {
    __shared__ int sh[128];
    int t = threadIdx.x;
    int v = (t < NSB) ? g_bsum[t] : 0;
    sh[t] = v;
    __syncthreads();
    for (int o = 1; o < 128; o <<= 1) {
        int a = (t >= o) ? sh[t - o] : 0;
        __syncthreads();
        sh[t] += a;
        __syncthreads();
    }
    g_boff[t] = sh[t] - v;
}

__global__ void addoff_k() {
    int i = blockIdx.x * blockDim.x + threadIdx.x;
    if (i < NN) g_rowptr[i] += g_boff[i / SB];
    if (i == 0) g_rowptr[NN] = EE;
}

__global__ void scat_k() {
    int e = blockIdx.x * blockDim.x + threadIdx.x;
    if (e < EE) {
        int d = g_dst[e];
        int p = g_rowptr[d] + atomicAdd(&g_fill[d], 1);
        g_esrc[p] = g_src[e];
    }
}

// ---------------- one-time weight split ----------------
__global__ void split_w_k(const float* __restrict__ W_in, const float* __restrict__ W_h,
                          const float* __restrict__ W_gat, const float* __restrict__ W_l) {
    int idx = blockIdx.x * blockDim.x + threadIdx.x;   // 10*64*128
    if (idx >= 10 * 64 * 128) return;
    int w   = idx >> 13;
    int kw  = (idx >> 7) & 63;
    int n   = idx & 127;
    const float* base;
    if (w == 0) base = W_in;
    else {
        int layer = (w - 1) / 3, t = (w - 1) % 3;
        base = (t == 0 ? W_h : t == 1 ? W_gat : W_l) + (size_t)layer * DD * DD;
    }
    float v0 = base[(size_t)(2 * kw) * DD + n];
    float v1 = base[(size_t)(2 * kw + 1) * DD + n];
    uint32_t h0, l0, h1, l1;
    bsplit(v0, h0, l0); bsplit(v1, h1, l1);
    g_wsh[(size_t)w * 8192 + n * 64 + kw] = h0 | (h1 << 16);
    g_wsl[(size_t)w * 8192 + n * 64 + kw] = l0 | (l1 << 16);
}

// ---------------- one-time input split ----------------
__global__ void split_x_k(const float* __restrict__ x) {
    int t = blockIdx.x * blockDim.x + threadIdx.x;     // NN*32
    if (t >= NN * 32) return;
    int row = t >> 5, q = t & 31;
    float4 v = ((const float4*)x)[(size_t)row * 32 + q];
    uint32_t hx, lx, hy, ly, hz, lz, hw, lw;
    bsplit(v.x, hx, lx); bsplit(v.y, hy, ly);
    bsplit(v.z, hz, lz); bsplit(v.w, hw, lw);
    size_t o = (size_t)row * 64 + 2 * q;
    g_inh[o]     = hx | (hy << 16);
    g_inh[o + 1] = hz | (hw << 16);
    g_inl[o]     = lx | (ly << 16);
    g_inl[o + 1] = lz | (lw << 16);
}

// ---------------- bf16x3 GEMM, cp.async double-buffered, fused attn logits ----------------
struct GemmArgs2 {
    int          wslot[3];
    const float* bias[3];
    float*       out[3];
    int          epi[3];     // 0 none, 1 bias, 2 bias+relu
    int          emit_split;
    int          attn_w;     // which w computes attention logits (-1 = none)
    const float* attn_a;     // att_src [128]
    const float* attn_d;     // att_dst [128]
};

extern __shared__ uint32_t smem_dyn[];

__global__ __launch_bounds__(256, 2)
void mma_gemm_k(const uint32_t* __restrict__ Ah, const uint32_t* __restrict__ Al,
                GemmArgs2 args) {
    const int tid  = threadIdx.x;
    const int lane = tid & 31;
    const int wid  = tid >> 5;
    const int wm   = (wid >> 1) * 32;
    const int wn   = (wid & 1) * 64;
    const int row0 = blockIdx.x * 128;
    const int w    = blockIdx.y;

    const uint32_t* Wh = g_wsh + (size_t)args.wslot[w] * 8192;
    const uint32_t* Wl = g_wsl + (size_t)args.wslot[w] * 8192;

    const int ar = lane >> 2;
    const int ac = lane & 3;

    float acc[2][8][4];
#pragma unroll
    for (int i = 0; i < 2; i++)
#pragma unroll
        for (int j = 0; j < 8; j++)
#pragma unroll
            for (int c = 0; c < 4; c++) acc[i][j][c] = 0.f;

    auto stage = [&](int kc, int s) {
        uint32_t* bAh = smem_dyn + s * 4 * SZW;
        uint32_t* bAl = bAh + SZW;
        uint32_t* bWh = bAl + SZW;
        uint32_t* bWl = bWh + SZW;
        const int kwc = kc >> 1;
#pragma unroll
        for (int t = tid; t < 512; t += 256) {
            int m = t >> 2, q = t & 3;
            int row = row0 + m;
            uint32_t* dh = &bAh[m * PADW + 4 * q];
            uint32_t* dl = &bAl[m * PADW + 4 * q];
            if (row < NN) {
                size_t o = (size_t)row * 64 + kwc + 4 * q;
                cp16(dh, &Ah[o]);
                cp16(dl, &Al[o]);
            } else {
                *(uint4*)dh = make_uint4(0, 0, 0, 0);
                *(uint4*)dl = make_uint4(0, 0, 0, 0);
            }
        }
#pragma unroll
        for (int t = tid; t < 512; t += 256) {
            int n = t >> 2, q = t & 3;
            size_t o = (size_t)n * 64 + kwc + 4 * q;
            cp16(&bWh[n * PADW + 4 * q], &Wh[o]);
            cp16(&bWl[n * PADW + 4 * q], &Wl[o]);
        }
        asm volatile("cp.async.commit_group;");
    };

    stage(0, 0);

#pragma unroll
    for (int c = 0; c < 4; c++) {
        if (c < 3) stage((c + 1) * 32, (c + 1) & 1);
        if (c < 3) asm volatile("cp.async.wait_group 1;");
        else       asm volatile("cp.async.wait_group 0;");
        __syncthreads();

        const uint32_t* bAh = smem_dyn + (c & 1) * 4 * SZW;
        const uint32_t* bAl = bAh + SZW;
        const uint32_t* bWh = bAl + SZW;
        const uint32_t* bWl = bWh + SZW;

#pragma unroll
        for (int s = 0; s < 2; s++) {
            const int kb = s * 8;
            uint32_t ah[2][4], al[2][4];
#pragma unroll
            for (int i = 0; i < 2; i++) {
                int m = wm + i * 16 + ar;
                ah[i][0] = bAh[m * PADW + kb + ac];
                ah[i][1] = bAh[(m + 8) * PADW + kb + ac];
                ah[i][2] = bAh[m * PADW + kb + ac + 4];
                ah[i][3] = bAh[(m + 8) * PADW + kb + ac + 4];
                al[i][0] = bAl[m * PADW + kb + ac];
                al[i][1] = bAl[(m + 8) * PADW + kb + ac];
                al[i][2] = bAl[m * PADW + kb + ac + 4];
                al[i][3] = bAl[(m + 8) * PADW + kb + ac + 4];
            }
#pragma unroll
            for (int j = 0; j < 8; j++) {
                int n = wn + j * 8 + ar;
                uint32_t bh0 = bWh[n * PADW + kb + ac];
                uint32_t bh1 = bWh[n * PADW + kb + ac + 4];
                uint32_t bl0 = bWl[n * PADW + kb + ac];
                uint32_t bl1 = bWl[n * PADW + kb + ac + 4];
#pragma unroll
                for (int i = 0; i < 2; i++) {
                    asm volatile(
                        "mma.sync.aligned.m16n8k16.row.col.f32.bf16.bf16.f32 "
                        "{%0,%1,%2,%3}, {%4,%5,%6,%7}, {%8,%9}, {%0,%1,%2,%3};"
                        : "+f"(acc[i][j][0]), "+f"(acc[i][j][1]),
                          "+f"(acc[i][j][2]), "+f"(acc[i][j][3])
                        : "r"(ah[i][0]), "r"(ah[i][1]), "r"(ah[i][2]), "r"(ah[i][3]),
                          "r"(bh0), "r"(bh1));
                    asm volatile(
                        "mma.sync.aligned.m16n8k16.row.col.f32.bf16.bf16.f32 "
                        "{%0,%1,%2,%3}, {%4,%5,%6,%7}, {%8,%9}, {%0,%1,%2,%3};"
                        : "+f"(acc[i][j][0]), "+f"(acc[i][j][1]),
                          "+f"(acc[i][j][2]), "+f"(acc[i][j][3])
                        : "r"(ah[i][0]), "r"(ah[i][1]), "r"(ah[i][2]), "r"(ah[i][3]),
                          "r"(bl0), "r"(bl1));
                    asm volatile(
                        "mma.sync.aligned.m16n8k16.row.col.f32.bf16.bf16.f32 "
                        "{%0,%1,%2,%3}, {%4,%5,%6,%7}, {%8,%9}, {%0,%1,%2,%3};"
                        : "+f"(acc[i][j][0]), "+f"(acc[i][j][1]),
                          "+f"(acc[i][j][2]), "+f"(acc[i][j][3])
                        : "r"(al[i][0]), "r"(al[i][1]), "r"(al[i][2]), "r"(al[i][3]),
                          "r"(bh0), "r"(bh1));
                }
            }
        }
        __syncthreads();
    }

    // ---- epilogue ----
    const int epi = args.epi[w];
    const float* bias = args.bias[w];
    float* out = args.out[w];
    const int emit = args.emit_split;
    const bool do_attn = (w == args.attn_w);
    float ps[2] = {0.f, 0.f}, pd[2] = {0.f, 0.f};   // attn partials for rows r0, r0+8 (per i)
    float ps2[2] = {0.f, 0.f}, pd2[2] = {0.f, 0.f};

#pragma unroll
    for (int i = 0; i < 2; i++) {
#pragma unroll
        for (int j = 0; j < 8; j++) {
            int cc = wn + j * 8 + ac * 2;
            float bx = 0.f, by = 0.f;
            if (epi >= 1) { bx = bias[cc]; by = bias[cc + 1]; }
            float c0 = acc[i][j][0] + bx, c1 = acc[i][j][1] + by;
            float c2 = acc[i][j][2] + bx, c3 = acc[i][j][3] + by;
            if (epi == 2) {
                c0 = fmaxf(c0, 0.f); c1 = fmaxf(c1, 0.f);
                c2 = fmaxf(c2, 0.f); c3 = fmaxf(c3, 0.f);
            }
            if (do_attn) {
                float a0 = args.attn_a[cc], a1 = args.attn_a[cc + 1];
                float d0 = args.attn_d[cc], d1 = args.attn_d[cc + 1];
                ps[i]  += c0 * a0 + c1 * a1;
                pd[i]  += c0 * d0 + c1 * d1;
                ps2[i] += c2 * a0 + c3 * a1;
                pd2[i] += c2 * d0 + c3 * d1;
            }
            int r0 = row0 + wm + i * 16 + ar;
            if (out) {
                if (r0 < NN)     *(float2*)&out[(size_t)r0 * DD + cc]       = make_float2(c0, c1);
                if (r0 + 8 < NN) *(float2*)&out[(size_t)(r0 + 8) * DD + cc] = make_float2(c2, c3);
            }
            if (emit) {
                uint32_t h0, l0, h1, l1;
                if (r0 < NN) {
                    bsplit(c0, h0, l0); bsplit(c1, h1, l1);
                    g_ah[(size_t)r0 * 64 + (cc >> 1)] = h0 | (h1 << 16);
                    g_al[(size_t)r0 * 64 + (cc >> 1)] = l0 | (l1 << 16);
                }
                if (r0 + 8 < NN) {
                    bsplit(c2, h0, l0); bsplit(c3, h1, l1);
                    g_ah[(size_t)(r0 + 8) * 64 + (cc >> 1)] = h0 | (h1 << 16);
                    g_al[(size_t)(r0 + 8) * 64 + (cc >> 1)] = l0 | (l1 << 16);
                }
            }
        }
    }

    if (do_attn) {
        // reduce over the 4 ac lanes (xor 1 and 2 in lane space)
#pragma unroll
        for (int i = 0; i < 2; i++) {
#pragma unroll
            for (int o = 1; o <= 2; o <<= 1) {
                ps[i]  += __shfl_xor_sync(0xFFFFFFFFu, ps[i],  o);
                pd[i]  += __shfl_xor_sync(0xFFFFFFFFu, pd[i],  o);
                ps2[i] += __shfl_xor_sync(0xFFFFFFFFu, ps2[i], o);
                pd2[i] += __shfl_xor_sync(0xFFFFFFFFu, pd2[i], o);
            }
            if (ac == 0) {
                int r0 = row0 + wm + i * 16 + ar;
                if (r0 < NN) {
                    atomicAdd(&g_as[r0], ps[i]);
                    atomicAdd(&g_ad[r0], pd[i]);
                }
                if (r0 + 8 < NN) {
                    atomicAdd(&g_as[r0 + 8], ps2[i]);
                    atomicAdd(&g_ad[r0 + 8], pd2[i]);
                }
            }
        }
    }
}

// ---------------- small FFMA GEMM for the prediction head (NCOL=40) ----------------
template <int NCOL>
__global__ void gemm_small_k(const float* __restrict__ A, const float* __restrict__ W,
                             const float* __restrict__ bias, float* __restrict__ C) {
    constexpr int ROWS = 32;
    constexpr int KT   = 32;
    __shared__ float sA[ROWS][DD];
    __shared__ float sW[KT][NCOL];
    int tid  = threadIdx.x;
    int row0 = blockIdx.x * ROWS;

    {
        const float4* Af  = (const float4*)A;
        float4*       sAf = (float4*)sA;
#pragma unroll
        for (int i = 0; i < 4; i++) {
            int idx = tid + i * 256;
            int r = idx >> 5, c = idx & 31;
            float4 v = make_float4(0.f, 0.f, 0.f, 0.f);
            if (row0 + r < NN) v = Af[(size_t)(row0 + r) * 32 + c];
            sAf[idx] = v;
        }
    }

    int tx = tid & 31, ty = tid >> 5;
    const int col = tx * 4;
    float acc[4][4];
#pragma unroll
    for (int i = 0; i < 4; i++)
#pragma unroll
        for (int j = 0; j < 4; j++) acc[i][j] = 0.f;

    for (int kt = 0; kt < DD; kt += KT) {
        __syncthreads();
        {
            const float4* Wf  = (const float4*)(W + kt * NCOL);
            float4*       sWf = (float4*)sW;
            constexpr int T4 = KT * NCOL / 4;
            for (int i = tid; i < T4; i += 256) sWf[i] = Wf[i];
        }
        __syncthreads();
#pragma unroll
        for (int k = 0; k < KT; k++) {
            float4 wv = make_float4(0.f, 0.f, 0.f, 0.f);
            if (col < NCOL) wv = *(const float4*)&sW[k][col];
#pragma unroll
            for (int i = 0; i < 4; i++) {
                float a = sA[ty + i * 8][kt + k];
                acc[i][0] += a * wv.x;
                acc[i][1] += a * wv.y;
                acc[i][2] += a * wv.z;
                acc[i][3] += a * wv.w;
            }
        }
    }

    if (col < NCOL) {
        float4 bv = *(const float4*)&bias[col];
#pragma unroll
        for (int i = 0; i < 4; i++) {
            int row = row0 + ty + i * 8;
            if (row < NN) {
                float4 o;
                o.x = acc[i][0] + bv.x;
                o.y = acc[i][1] + bv.y;
                o.z = acc[i][2] + bv.z;
                o.w = acc[i][3] + bv.w;
                *(float4*)&C[(size_t)row * NCOL + col] = o;
            }
        }
    }
}

// ---------------- GAT softmax-aggregate: warp per destination node ----------------
// pass 1: online max/denom + store post-leaky logits to g_ew
// pass 2: weight = exp(e - m) * inv; gather xh rows
__global__ void agg_k(const float* __restrict__ xh) {
    int n    = (blockIdx.x * blockDim.x + threadIdx.x) >> 5;
    int lane = threadIdx.x & 31;
    if (n >= NN) return;
    int s0 = g_rowptr[n], s1 = g_rowptr[n + 1];
    float adn = g_ad[n];

    // online softmax over this lane's strided edges
    float m = -1e30f, d = 0.f;
    for (int i = s0 + lane; i < s1; i += 32) {
        int s  = g_esrc[i];
        float e = g_as[s] + adn;
        e = e > 0.f ? e : 0.2f * e;
        g_ew[i] = e;
        if (e > m) { d = d * __expf(m - e) + 1.f; m = e; }
        else       { d += __expf(e - m); }
    }
    // combine lanes: global max, then rescale denoms
#pragma unroll
    for (int o = 16; o; o >>= 1) {
        float mo = __shfl_xor_sync(0xFFFFFFFFu, m, o);
        float do_ = __shfl_xor_sync(0xFFFFFFFFu, d, o);
        if (mo > m) { d = d * __expf(m - mo) + do_; m = mo; }
        else        { d += do_ * __expf(mo - m); }
    }
    float inv = 1.f / (d + 1e-16f);

    float4 acc = make_float4(0.f, 0.f, 0.f, 0.f);
    for (int base = s0; base < s1; base += 32) {
        int idx = base + lane;
        float w = 0.f;
        int   s = 0;
        if (idx < s1) {
            s = g_esrc[idx];
            w = __expf(g_ew[idx] - m) * inv;
        }
        int cnt = min(32, s1 - base);
        for (int j = 0; j < cnt; j++) {
            float wj = __shfl_sync(0xFFFFFFFFu, w, j);
            int   sj = __shfl_sync(0xFFFFFFFFu, s, j);
            float4 v = ((const float4*)(xh + (size_t)sj * DD))[lane];
            acc.x += wj * v.x; acc.y += wj * v.y;
            acc.z += wj * v.z; acc.w += wj * v.w;
        }
    }
    ((float4*)(g_agg + (size_t)n * DD))[lane] = acc;
}

// ---------------- fused pointwise + emit bf16 split of new x + zero attn accumulators ----------------
__global__ void fuse_k(const float* __restrict__ xlbuf, const float* __restrict__ hbuf,
                       const float* __restrict__ lng, const float* __restrict__ lnb,
                       const float* __restrict__ betas, int first) {
    int n    = (blockIdx.x * blockDim.x + threadIdx.x) >> 5;
    int lane = threadIdx.x & 31;
    if (n >= NN) return;
    size_t off = (size_t)n * DD;

    float4 ag = ((const float4*)(g_agg + off))[lane];
    float4 xl = ((const float4*)(xlbuf + off))[lane];
    float4 xn;
    xn.x = fmaxf(ag.x + xl.x, 0.f);
    xn.y = fmaxf(ag.y + xl.y, 0.f);
    xn.z = fmaxf(ag.z + xl.z, 0.f);
    xn.w = fmaxf(ag.w + xl.w, 0.f);

    float4 hh = ((const float4*)(hbuf + off))[lane];
    float4 t;
    t.x = hh.x * xn.x; t.y = hh.y * xn.y; t.z = hh.z * xn.z; t.w = hh.w * xn.w;

    float sum = t.x + t.y + t.z + t.w;
#pragma unroll
    for (int o = 16; o; o >>= 1) sum += __shfl_xor_sync(0xFFFFFFFFu, sum, o);
    float mu = sum * (1.f / 128.f);

    float4 dc;
    dc.x = t.x - mu; dc.y = t.y - mu; dc.z = t.z - mu; dc.w = t.w - mu;
    float ss = dc.x * dc.x + dc.y * dc.y + dc.z * dc.z + dc.w * dc.w;
#pragma unroll
    for (int o = 16; o; o >>= 1) ss += __shfl_xor_sync(0xFFFFFFFFu, ss, o);
    float rs = rsqrtf(ss * (1.f / 128.f) + 1e-5f);

    float4 g  = ((const float4*)lng)[lane];
    float4 b  = ((const float4*)lnb)[lane];
    float4 be = ((const float4*)betas)[lane];
    be.x = 1.f / (1.f + __expf(-be.x));
    be.y = 1.f / (1.f + __expf(-be.y));
    be.z = 1.f / (1.f + __expf(-be.z));
    be.w = 1.f / (1.f + __expf(-be.w));

    float4 y;
    y.x = dc.x * rs * g.x + b.x;
    y.y = dc.y * rs * g.y + b.y;
    y.z = dc.z * rs * g.z + b.z;
    y.w = dc.w * rs * g.w + b.w;

    float4 xo;
    xo.x = (1.f - be.x) * y.x + be.x * xn.x;
    xo.y = (1.f - be.y) * y.y + be.y * xn.y;
    xo.z = (1.f - be.z) * y.z + be.z * xn.z;
    xo.w = (1.f - be.w) * y.w + be.w * xn.w;

    {
        uint32_t hx, lx, hy, ly, hz, lz, hw, lw;
        bsplit(xo.x, hx, lx); bsplit(xo.y, hy, ly);
        bsplit(xo.z, hz, lz); bsplit(xo.w, hw, lw);
        size_t o2 = (size_t)n * 64 + 2 * lane;
        g_ah[o2]     = hx | (hy << 16);
        g_ah[o2 + 1] = hz | (hw << 16);
        g_al[o2]     = lx | (ly << 16);
        g_al[o2 + 1] = lz | (lw << 16);
    }

    if (first) {
        ((float4*)(g_xlocal + off))[lane] = xo;
    } else {
        float4 p = ((const float4*)(g_xlocal + off))[lane];
        p.x += xo.x; p.y += xo.y; p.z += xo.z; p.w += xo.w;
        ((float4*)(g_xlocal + off))[lane] = p;
    }

    // zero attn accumulators for the next layer's fused-attn GEMM
    if (lane == 0) { g_as[n] = 0.f; g_ad[n] = 0.f; }
}

// ---------------- host ----------------
extern "C" void kernel_launch(void* const* d_in, const int* in_sizes, int n_in,
                              void* d_out, int out_size) {
    const float* x       = (const float*)d_in[0];
    const int*   ei32    = (const int*)d_in[1];
    const float* W_in    = (const float*)d_in[2];
    const float* b_in    = (const float*)d_in[3];
    const float* W_h     = (const float*)d_in[4];
    const float* b_h     = (const float*)d_in[5];
    const float* W_gat   = (const float*)d_in[6];
    const float* att_src = (const float*)d_in[7];
    const float* att_dst = (const float*)d_in[8];
    const float* W_l     = (const float*)d_in[9];
    const float* b_l     = (const float*)d_in[10];
    const float* ln_g    = (const float*)d_in[11];
    const float* ln_b    = (const float*)d_in[12];
    const float* betas   = (const float*)d_in[13];
    const float* W_pred  = (const float*)d_in[14];
    const float* b_pred  = (const float*)d_in[15];
    float*       out     = (float*)d_out;

    float *ph, *pxh, *pxl, *pxloc;
    uint32_t *pinh, *pinl, *pah, *pal;
    cudaGetSymbolAddress((void**)&ph,    g_h);
    cudaGetSymbolAddress((void**)&pxh,   g_xh);
    cudaGetSymbolAddress((void**)&pxl,   g_xl);
    cudaGetSymbolAddress((void**)&pxloc, g_xlocal);
    cudaGetSymbolAddress((void**)&pinh,  g_inh);
    cudaGetSymbolAddress((void**)&pinl,  g_inl);
    cudaGetSymbolAddress((void**)&pah,   g_ah);
    cudaGetSymbolAddress((void**)&pal,   g_al);

    const int dynsmem = 2 * 4 * SZW * 4;   // 81920 bytes
    static int attr_set = 0;
    if (!attr_set) {
        cudaFuncSetAttribute(mma_gemm_k, cudaFuncAttributeMaxDynamicSharedMemorySize, dynsmem);
        attr_set = 1;
    }

    dim3 gE((EE + 255) / 256);
    dim3 gN((NN + 255) / 256);
    dim3 gW((NN + 7) / 8);
    dim3 gG((NN + 31) / 32);
    dim3 gM((NN + 127) / 128, 1);
    dim3 gM3((NN + 127) / 128, 3);

    // CSR + one-time splits
    zero_k<<<gN, 256>>>();
    decode_deg_k<<<gE, 256>>>(ei32);
    split_w_k<<<(10 * 64 * 128 + 255) / 256, 256>>>(W_in, W_h, W_gat, W_l);
    split_x_k<<<(NN * 32 + 255) / 256, 256>>>(x);
    pscan_k<<<NSB, SB>>>();
    bscan_k<<<1, 128>>>();
    addoff_k<<<gN, 256>>>();
    scat_k<<<gE, 256>>>();

    // input projection: x @ W_in + b_in -> split only
    {
        GemmArgs2 a{};
        a.wslot[0] = 0; a.bias[0] = b_in; a.out[0] = nullptr; a.epi[0] = 1;
        a.emit_split = 1; a.attn_w = -1;
        mma_gemm_k<<<gM, 256, dynsmem>>>(pinh, pinl, a);
    }

    for (int i = 0; i < LL; i++) {
        GemmArgs2 a{};
        a.wslot[0] = 1 + 3 * i;     a.bias[0] = b_h + i * DD; a.out[0] = ph;  a.epi[0] = 2;
        a.wslot[1] = 1 + 3 * i + 1; a.bias[1] = nullptr;      a.out[1] = pxh; a.epi[1] = 0;
        a.wslot[2] = 1 + 3 * i + 2; a.bias[2] = b_l + i * DD; a.out[2] = pxl; a.epi[2] = 1;
        a.emit_split = 0;
        a.attn_w = 1; a.attn_a = att_src + i * DD; a.attn_d = att_dst + i * DD;
        mma_gemm_k<<<gM3, 256, dynsmem>>>(pah, pal, a);

        agg_k<<<gW, 256>>>(pxh);
        fuse_k<<<gW, 256>>>(pxl, ph, ln_g + i * DD, ln_b + i * DD, betas + i * DD, i == 0);
    }

    gemm_small_k<OUTD><<<gG, 256>>>(pxloc, W_pred, b_pred, out);
}

// round 11
// speedup vs baseline: 1.7540x; 1.0634x over previous
#include <cuda_runtime.h>
#include <cuda_bf16.h>
#include <math.h>
#include <stdint.h>

#define NN   50000
#define EE   800000
#define DD   128
#define LL   3
#define OUTD 40
#define SB   512
#define NSB  ((NN + SB - 1) / SB)   // 98
#define PADW 20
#define SZW  (128 * PADW)           // words per smem tile (2560)

// ---------------- scratch (device globals; no allocation allowed) ----------------
__device__ float    g_h[NN * DD];
__device__ float    g_xh[NN * DD];
__device__ float    g_xl[NN * DD];
__device__ float    g_xlocal[NN * DD];
__device__ float    g_as[2 * NN];   // double-buffered attention logit accumulators
__device__ float    g_ad[2 * NN];
__device__ float    g_ew[EE];
__device__ int      g_deg[NN];
__device__ int      g_fill[NN];
__device__ int      g_rowptr[NN + 1];
__device__ int      g_esrc[EE];
__device__ int      g_src[EE];
__device__ int      g_dst[EE];
__device__ int      g_bsum[NSB];
__device__ int      g_boff[128];
// packed bf16 pairs (hi/lo) along k: [row][64 words]
__device__ uint32_t g_inh[NN * 64];
__device__ uint32_t g_inl[NN * 64];
__device__ uint32_t g_ah[NN * 64];
__device__ uint32_t g_al[NN * 64];
// pre-split weights: [wslot][n][64 words], 10 slots
__device__ uint32_t g_wsh[10 * 128 * 64];
__device__ uint32_t g_wsl[10 * 128 * 64];

__device__ __forceinline__ void bsplit(float v, uint32_t& h, uint32_t& l) {
    __nv_bfloat16 bh = __float2bfloat16_rn(v);
    float r = v - __bfloat162float(bh);
    __nv_bfloat16 bl = __float2bfloat16_rn(r);
    h = (uint32_t)__bfloat16_as_ushort(bh);
    l = (uint32_t)__bfloat16_as_ushort(bl);
}

__device__ __forceinline__ void cp16(void* dst_s, const void* src_g) {
    uint32_t d = (uint32_t)__cvta_generic_to_shared(dst_s);
    asm volatile("cp.async.cg.shared.global [%0], [%1], 16;" :: "r"(d), "l"(src_g));
}

// ---------------- edge decode + degree histogram (fused) ----------------
__global__ void decode_deg_k(const int* __restrict__ ei32) {
    bool is64 = (ei32[1] == 0 && ei32[3] == 0 && ei32[5] == 0 && ei32[7] == 0);
    int e = blockIdx.x * blockDim.x + threadIdx.x;
    if (e < EE) {
        int s, d;
        if (is64) {
            s = ei32[2 * (size_t)e];
            d = ei32[2 * ((size_t)EE + e)];
        } else {
            s = ei32[e];
            d = ei32[EE + e];
        }
        g_src[e] = s;
        g_dst[e] = d;
        atomicAdd(&g_deg[d], 1);
    }
}

__global__ void zero_k() {
    int i = blockIdx.x * blockDim.x + threadIdx.x;
    if (i < NN) {
        g_deg[i] = 0; g_fill[i] = 0;
        g_as[i] = 0.f; g_ad[i] = 0.f;
        g_as[NN + i] = 0.f; g_ad[NN + i] = 0.f;
    }
}

__global__ void pscan_k() {
    __shared__ int sh[SB];
    int t = threadIdx.x;
    int i = blockIdx.x * SB + t;
    int v = (i < NN) ? g_deg[i] : 0;
    sh[t] = v;
    __syncthreads();
    for (int o = 1; o < SB; o <<= 1) {
        int a = (t >= o) ? sh[t - o] : 0;
        __syncthreads();
        sh[t] += a;
        __syncthreads();
    }
    if (i < NN) g_rowptr[i] = sh[t] - v;
    if (t == SB - 1) g_bsum[blockIdx.x] = sh[t];
}

__global__ void bscan_k() {
    __shared__ int sh[128];
    int t = threadIdx.x;
    int v = (t < NSB) ? g_bsum[t] : 0;
    sh[t] = v;
    __syncthreads();
    for (int o = 1; o < 128; o <<= 1) {
        int a = (t >= o) ? sh[t - o] : 0;
        __syncthreads();
        sh[t] += a;
        __syncthreads();
    }
    g_boff[t] = sh[t] - v;
}

__global__ void addoff_k() {
    int i = blockIdx.x * blockDim.x + threadIdx.x;
    if (i < NN) g_rowptr[i] += g_boff[i / SB];
    if (i == 0) g_rowptr[NN] = EE;
}

__global__ void scat_k() {
    int e = blockIdx.x * blockDim.x + threadIdx.x;
    if (e < EE) {
        int d = g_dst[e];
        int p = g_rowptr[d] + atomicAdd(&g_fill[d], 1);
        g_esrc[p] = g_src[e];
    }
}

// ---------------- one-time weight split ----------------
__global__ void split_w_k(const float* __restrict__ W_in, const float* __restrict__ W_h,
                          const float* __restrict__ W_gat, const float* __restrict__ W_l) {
    int idx = blockIdx.x * blockDim.x + threadIdx.x;   // 10*64*128
    if (idx >= 10 * 64 * 128) return;
    int w   = idx >> 13;
    int kw  = (idx >> 7) & 63;
    int n   = idx & 127;
    const float* base;
    if (w == 0) base = W_in;
    else {
        int layer = (w - 1) / 3, t = (w - 1) % 3;
        base = (t == 0 ? W_h : t == 1 ? W_gat : W_l) + (size_t)layer * DD * DD;
    }
    float v0 = base[(size_t)(2 * kw) * DD + n];
    float v1 = base[(size_t)(2 * kw + 1) * DD + n];
    uint32_t h0, l0, h1, l1;
    bsplit(v0, h0, l0); bsplit(v1, h1, l1);
    g_wsh[(size_t)w * 8192 + n * 64 + kw] = h0 | (h1 << 16);
    g_wsl[(size_t)w * 8192 + n * 64 + kw] = l0 | (l1 << 16);
}

// ---------------- one-time input split ----------------
__global__ void split_x_k(const float* __restrict__ x) {
    int t = blockIdx.x * blockDim.x + threadIdx.x;     // NN*32
    if (t >= NN * 32) return;
    int row = t >> 5, q = t & 31;
    float4 v = ((const float4*)x)[(size_t)row * 32 + q];
    uint32_t hx, lx, hy, ly, hz, lz, hw, lw;
    bsplit(v.x, hx, lx); bsplit(v.y, hy, ly);
    bsplit(v.z, hz, lz); bsplit(v.w, hw, lw);
    size_t o = (size_t)row * 64 + 2 * q;
    g_inh[o]     = hx | (hy << 16);
    g_inh[o + 1] = hz | (hw << 16);
    g_inl[o]     = lx | (ly << 16);
    g_inl[o + 1] = lz | (lw << 16);
}

// ---------------- bf16x3 GEMM, cp.async double-buffered, fused attn logits ----------------
struct GemmArgs2 {
    int          wslot[3];
    const float* bias[3];
    float*       out[3];
    int          epi[3];     // 0 none, 1 bias, 2 bias+relu
    int          emit_split;
    int          attn_w;     // which w computes attention logits (-1 = none)
    int          attn_slot;  // accumulator slot (0/1)
    const float* attn_a;
    const float* attn_d;
};

extern __shared__ uint32_t smem_dyn[];

__global__ __launch_bounds__(256, 2)
void mma_gemm_k(const uint32_t* __restrict__ Ah, const uint32_t* __restrict__ Al,
                GemmArgs2 args) {
    const int tid  = threadIdx.x;
    const int lane = tid & 31;
    const int wid  = tid >> 5;
    const int wm   = (wid >> 1) * 32;
    const int wn   = (wid & 1) * 64;
    const int row0 = blockIdx.x * 128;
    const int w    = blockIdx.y;

    const uint32_t* Wh = g_wsh + (size_t)args.wslot[w] * 8192;
    const uint32_t* Wl = g_wsl + (size_t)args.wslot[w] * 8192;

    const int ar = lane >> 2;
    const int ac = lane & 3;

    float acc[2][8][4];
#pragma unroll
    for (int i = 0; i < 2; i++)
#pragma unroll
        for (int j = 0; j < 8; j++)
#pragma unroll
            for (int c = 0; c < 4; c++) acc[i][j][c] = 0.f;

    auto stage = [&](int kc, int s) {
        uint32_t* bAh = smem_dyn + s * 4 * SZW;
        uint32_t* bAl = bAh + SZW;
        uint32_t* bWh = bAl + SZW;
        uint32_t* bWl = bWh + SZW;
        const int kwc = kc >> 1;
#pragma unroll
        for (int t = tid; t < 512; t += 256) {
            int m = t >> 2, q = t & 3;
            int row = row0 + m;
            uint32_t* dh = &bAh[m * PADW + 4 * q];
            uint32_t* dl = &bAl[m * PADW + 4 * q];
            if (row < NN) {
                size_t o = (size_t)row * 64 + kwc + 4 * q;
                cp16(dh, &Ah[o]);
                cp16(dl, &Al[o]);
            } else {
                *(uint4*)dh = make_uint4(0, 0, 0, 0);
                *(uint4*)dl = make_uint4(0, 0, 0, 0);
            }
        }
#pragma unroll
        for (int t = tid; t < 512; t += 256) {
            int n = t >> 2, q = t & 3;
            size_t o = (size_t)n * 64 + kwc + 4 * q;
            cp16(&bWh[n * PADW + 4 * q], &Wh[o]);
            cp16(&bWl[n * PADW + 4 * q], &Wl[o]);
        }
        asm volatile("cp.async.commit_group;");
    };

    stage(0, 0);

#pragma unroll
    for (int c = 0; c < 4; c++) {
        if (c < 3) stage((c + 1) * 32, (c + 1) & 1);
        if (c < 3) asm volatile("cp.async.wait_group 1;");
        else       asm volatile("cp.async.wait_group 0;");
        __syncthreads();

        const uint32_t* bAh = smem_dyn + (c & 1) * 4 * SZW;
        const uint32_t* bAl = bAh + SZW;
        const uint32_t* bWh = bAl + SZW;
        const uint32_t* bWl = bWh + SZW;

#pragma unroll
        for (int s = 0; s < 2; s++) {
            const int kb = s * 8;
            uint32_t ah[2][4], al[2][4];
#pragma unroll
            for (int i = 0; i < 2; i++) {
                int m = wm + i * 16 + ar;
                ah[i][0] = bAh[m * PADW + kb + ac];
                ah[i][1] = bAh[(m + 8) * PADW + kb + ac];
                ah[i][2] = bAh[m * PADW + kb + ac + 4];
                ah[i][3] = bAh[(m + 8) * PADW + kb + ac + 4];
                al[i][0] = bAl[m * PADW + kb + ac];
                al[i][1] = bAl[(m + 8) * PADW + kb + ac];
                al[i][2] = bAl[m * PADW + kb + ac + 4];
                al[i][3] = bAl[(m + 8) * PADW + kb + ac + 4];
            }
#pragma unroll
            for (int j = 0; j < 8; j++) {
                int n = wn + j * 8 + ar;
                uint32_t bh0 = bWh[n * PADW + kb + ac];
                uint32_t bh1 = bWh[n * PADW + kb + ac + 4];
                uint32_t bl0 = bWl[n * PADW + kb + ac];
                uint32_t bl1 = bWl[n * PADW + kb + ac + 4];
#pragma unroll
                for (int i = 0; i < 2; i++) {
                    asm volatile(
                        "mma.sync.aligned.m16n8k16.row.col.f32.bf16.bf16.f32 "
                        "{%0,%1,%2,%3}, {%4,%5,%6,%7}, {%8,%9}, {%0,%1,%2,%3};"
                        : "+f"(acc[i][j][0]), "+f"(acc[i][j][1]),
                          "+f"(acc[i][j][2]), "+f"(acc[i][j][3])
                        : "r"(ah[i][0]), "r"(ah[i][1]), "r"(ah[i][2]), "r"(ah[i][3]),
                          "r"(bh0), "r"(bh1));
                    asm volatile(
                        "mma.sync.aligned.m16n8k16.row.col.f32.bf16.bf16.f32 "
                        "{%0,%1,%2,%3}, {%4,%5,%6,%7}, {%8,%9}, {%0,%1,%2,%3};"
                        : "+f"(acc[i][j][0]), "+f"(acc[i][j][1]),
                          "+f"(acc[i][j][2]), "+f"(acc[i][j][3])
                        : "r"(ah[i][0]), "r"(ah[i][1]), "r"(ah[i][2]), "r"(ah[i][3]),
                          "r"(bl0), "r"(bl1));
                    asm volatile(
                        "mma.sync.aligned.m16n8k16.row.col.f32.bf16.bf16.f32 "
                        "{%0,%1,%2,%3}, {%4,%5,%6,%7}, {%8,%9}, {%0,%1,%2,%3};"
                        : "+f"(acc[i][j][0]), "+f"(acc[i][j][1]),
                          "+f"(acc[i][j][2]), "+f"(acc[i][j][3])
                        : "r"(al[i][0]), "r"(al[i][1]), "r"(al[i][2]), "r"(al[i][3]),
                          "r"(bh0), "r"(bh1));
                }
            }
        }
        __syncthreads();
    }

    // ---- epilogue ----
    const int epi = args.epi[w];
    const float* bias = args.bias[w];
    float* out = args.out[w];
    const int emit = args.emit_split;
    const bool do_attn = (w == args.attn_w);
    float* asb = g_as + (size_t)args.attn_slot * NN;
    float* adb = g_ad + (size_t)args.attn_slot * NN;
    float ps[2] = {0.f, 0.f}, pd[2] = {0.f, 0.f};
    float ps2[2] = {0.f, 0.f}, pd2[2] = {0.f, 0.f};

#pragma unroll
    for (int i = 0; i < 2; i++) {
#pragma unroll
        for (int j = 0; j < 8; j++) {
            int cc = wn + j * 8 + ac * 2;
            float bx = 0.f, by = 0.f;
            if (epi >= 1) { bx = bias[cc]; by = bias[cc + 1]; }
            float c0 = acc[i][j][0] + bx, c1 = acc[i][j][1] + by;
            float c2 = acc[i][j][2] + bx, c3 = acc[i][j][3] + by;
            if (epi == 2) {
                c0 = fmaxf(c0, 0.f); c1 = fmaxf(c1, 0.f);
                c2 = fmaxf(c2, 0.f); c3 = fmaxf(c3, 0.f);
            }
            if (do_attn) {
                float a0 = args.attn_a[cc], a1 = args.attn_a[cc + 1];
                float d0 = args.attn_d[cc], d1 = args.attn_d[cc + 1];
                ps[i]  += c0 * a0 + c1 * a1;
                pd[i]  += c0 * d0 + c1 * d1;
                ps2[i] += c2 * a0 + c3 * a1;
                pd2[i] += c2 * d0 + c3 * d1;
            }
            int r0 = row0 + wm + i * 16 + ar;
            if (out) {
                if (r0 < NN)     *(float2*)&out[(size_t)r0 * DD + cc]       = make_float2(c0, c1);
                if (r0 + 8 < NN) *(float2*)&out[(size_t)(r0 + 8) * DD + cc] = make_float2(c2, c3);
            }
            if (emit) {
                uint32_t h0, l0, h1, l1;
                if (r0 < NN) {
                    bsplit(c0, h0, l0); bsplit(c1, h1, l1);
                    g_ah[(size_t)r0 * 64 + (cc >> 1)] = h0 | (h1 << 16);
                    g_al[(size_t)r0 * 64 + (cc >> 1)] = l0 | (l1 << 16);
                }
                if (r0 + 8 < NN) {
                    bsplit(c2, h0, l0); bsplit(c3, h1, l1);
                    g_ah[(size_t)(r0 + 8) * 64 + (cc >> 1)] = h0 | (h1 << 16);
                    g_al[(size_t)(r0 + 8) * 64 + (cc >> 1)] = l0 | (l1 << 16);
                }
            }
        }
    }

    if (do_attn) {
#pragma unroll
        for (int i = 0; i < 2; i++) {
#pragma unroll
            for (int o = 1; o <= 2; o <<= 1) {
                ps[i]  += __shfl_xor_sync(0xFFFFFFFFu, ps[i],  o);
                pd[i]  += __shfl_xor_sync(0xFFFFFFFFu, pd[i],  o);
                ps2[i] += __shfl_xor_sync(0xFFFFFFFFu, ps2[i], o);
                pd2[i] += __shfl_xor_sync(0xFFFFFFFFu, pd2[i], o);
            }
            if (ac == 0) {
                int r0 = row0 + wm + i * 16 + ar;
                if (r0 < NN) {
                    atomicAdd(&asb[r0], ps[i]);
                    atomicAdd(&adb[r0], pd[i]);
                }
                if (r0 + 8 < NN) {
                    atomicAdd(&asb[r0 + 8], ps2[i]);
                    atomicAdd(&adb[r0 + 8], pd2[i]);
                }
            }
        }
    }
}

// ---------------- small FFMA GEMM for the prediction head (NCOL=40) ----------------
template <int NCOL>
__global__ void gemm_small_k(const float* __restrict__ A, const float* __restrict__ W,
                             const float* __restrict__ bias, float* __restrict__ C) {
    constexpr int ROWS = 32;
    constexpr int KT   = 32;
    __shared__ float sA[ROWS][DD];
    __shared__ float sW[KT][NCOL];
    int tid  = threadIdx.x;
    int row0 = blockIdx.x * ROWS;

    {
        const float4* Af  = (const float4*)A;
        float4*       sAf = (float4*)sA;
#pragma unroll
        for (int i = 0; i < 4; i++) {
            int idx = tid + i * 256;
            int r = idx >> 5, c = idx & 31;
            float4 v = make_float4(0.f, 0.f, 0.f, 0.f);
            if (row0 + r < NN) v = Af[(size_t)(row0 + r) * 32 + c];
            sAf[idx] = v;
        }
    }

    int tx = tid & 31, ty = tid >> 5;
    const int col = tx * 4;
    float acc[4][4];
#pragma unroll
    for (int i = 0; i < 4; i++)
#pragma unroll
        for (int j = 0; j < 4; j++) acc[i][j] = 0.f;

    for (int kt = 0; kt < DD; kt += KT) {
        __syncthreads();
        {
            const float4* Wf  = (const float4*)(W + kt * NCOL);
            float4*       sWf = (float4*)sW;
            constexpr int T4 = KT * NCOL / 4;
            for (int i = tid; i < T4; i += 256) sWf[i] = Wf[i];
        }
        __syncthreads();
#pragma unroll
        for (int k = 0; k < KT; k++) {
            float4 wv = make_float4(0.f, 0.f, 0.f, 0.f);
            if (col < NCOL) wv = *(const float4*)&sW[k][col];
#pragma unroll
            for (int i = 0; i < 4; i++) {
                float a = sA[ty + i * 8][kt + k];
                acc[i][0] += a * wv.x;
                acc[i][1] += a * wv.y;
                acc[i][2] += a * wv.z;
                acc[i][3] += a * wv.w;
            }
        }
    }

    if (col < NCOL) {
        float4 bv = *(const float4*)&bias[col];
#pragma unroll
        for (int i = 0; i < 4; i++) {
            int row = row0 + ty + i * 8;
            if (row < NN) {
                float4 o;
                o.x = acc[i][0] + bv.x;
                o.y = acc[i][1] + bv.y;
                o.z = acc[i][2] + bv.z;
                o.w = acc[i][3] + bv.w;
                *(float4*)&C[(size_t)row * NCOL + col] = o;
            }
        }
    }
}

// ---------------- fused GAT aggregate + pointwise + emit split ----------------
// warp per destination node; slot = attention buffer of this layer,
// zeroes the OTHER slot for the next layer's GEMM accumulation.
__global__ void aggfuse_k(const float* __restrict__ xh,
                          const float* __restrict__ xlbuf, const float* __restrict__ hbuf,
                          const float* __restrict__ lng, const float* __restrict__ lnb,
                          const float* __restrict__ betas, int first, int slot) {
    int n    = (blockIdx.x * blockDim.x + threadIdx.x) >> 5;
    int lane = threadIdx.x & 31;
    if (n >= NN) return;
    const float* asb = g_as + (size_t)slot * NN;
    const float* adb = g_ad + (size_t)slot * NN;
    int s0 = g_rowptr[n], s1 = g_rowptr[n + 1];
    float adn = adb[n];

    // online softmax over this lane's strided edges; cache post-leaky logits
    float m = -1e30f, d = 0.f;
    for (int i = s0 + lane; i < s1; i += 32) {
        int s  = g_esrc[i];
        float e = asb[s] + adn;
        e = e > 0.f ? e : 0.2f * e;
        g_ew[i] = e;
        if (e > m) { d = d * __expf(m - e) + 1.f; m = e; }
        else       { d += __expf(e - m); }
    }
#pragma unroll
    for (int o = 16; o; o >>= 1) {
        float mo = __shfl_xor_sync(0xFFFFFFFFu, m, o);
        float do_ = __shfl_xor_sync(0xFFFFFFFFu, d, o);
        if (mo > m) { d = d * __expf(m - mo) + do_; m = mo; }
        else        { d += do_ * __expf(mo - m); }
    }
    float inv = 1.f / (d + 1e-16f);

    float4 ag = make_float4(0.f, 0.f, 0.f, 0.f);
    for (int base = s0; base < s1; base += 32) {
        int idx = base + lane;
        float w = 0.f;
        int   s = 0;
        if (idx < s1) {
            s = g_esrc[idx];
            w = __expf(g_ew[idx] - m) * inv;
        }
        int cnt = min(32, s1 - base);
        for (int j = 0; j < cnt; j++) {
            float wj = __shfl_sync(0xFFFFFFFFu, w, j);
            int   sj = __shfl_sync(0xFFFFFFFFu, s, j);
            float4 v = ((const float4*)(xh + (size_t)sj * DD))[lane];
            ag.x += wj * v.x; ag.y += wj * v.y;
            ag.z += wj * v.z; ag.w += wj * v.w;
        }
    }

    // ---- pointwise (agg stays in registers) ----
    size_t off = (size_t)n * DD;
    float4 xl = ((const float4*)(xlbuf + off))[lane];
    float4 xn;
    xn.x = fmaxf(ag.x + xl.x, 0.f);
    xn.y = fmaxf(ag.y + xl.y, 0.f);
    xn.z = fmaxf(ag.z + xl.z, 0.f);
    xn.w = fmaxf(ag.w + xl.w, 0.f);

    float4 hh = ((const float4*)(hbuf + off))[lane];
    float4 t;
    t.x = hh.x * xn.x; t.y = hh.y * xn.y; t.z = hh.z * xn.z; t.w = hh.w * xn.w;

    float sum = t.x + t.y + t.z + t.w;
#pragma unroll
    for (int o = 16; o; o >>= 1) sum += __shfl_xor_sync(0xFFFFFFFFu, sum, o);
    float mu = sum * (1.f / 128.f);

    float4 dc;
    dc.x = t.x - mu; dc.y = t.y - mu; dc.z = t.z - mu; dc.w = t.w - mu;
    float ss = dc.x * dc.x + dc.y * dc.y + dc.z * dc.z + dc.w * dc.w;
#pragma unroll
    for (int o = 16; o; o >>= 1) ss += __shfl_xor_sync(0xFFFFFFFFu, ss, o);
    float rs = rsqrtf(ss * (1.f / 128.f) + 1e-5f);

    float4 g  = ((const float4*)lng)[lane];
    float4 b  = ((const float4*)lnb)[lane];
    float4 be = ((const float4*)betas)[lane];
    be.x = 1.f / (1.f + __expf(-be.x));
    be.y = 1.f / (1.f + __expf(-be.y));
    be.z = 1.f / (1.f + __expf(-be.z));
    be.w = 1.f / (1.f + __expf(-be.w));

    float4 y;
    y.x = dc.x * rs * g.x + b.x;
    y.y = dc.y * rs * g.y + b.y;
    y.z = dc.z * rs * g.z + b.z;
    y.w = dc.w * rs * g.w + b.w;

    float4 xo;
    xo.x = (1.f - be.x) * y.x + be.x * xn.x;
    xo.y = (1.f - be.y) * y.y + be.y * xn.y;
    xo.z = (1.f - be.z) * y.z + be.z * xn.z;
    xo.w = (1.f - be.w) * y.w + be.w * xn.w;

    // emit bf16 split of new x
    {
        uint32_t hx, lx, hy, ly, hz, lz, hw, lw;
        bsplit(xo.x, hx, lx); bsplit(xo.y, hy, ly);
        bsplit(xo.z, hz, lz); bsplit(xo.w, hw, lw);
        size_t o2 = (size_t)n * 64 + 2 * lane;
        g_ah[o2]     = hx | (hy << 16);
        g_ah[o2 + 1] = hz | (hw << 16);
        g_al[o2]     = lx | (ly << 16);
        g_al[o2 + 1] = lz | (lw << 16);
    }

    if (first) {
        ((float4*)(g_xlocal + off))[lane] = xo;
    } else {
        float4 p = ((const float4*)(g_xlocal + off))[lane];
        p.x += xo.x; p.y += xo.y; p.z += xo.z; p.w += xo.w;
        ((float4*)(g_xlocal + off))[lane] = p;
    }

    // zero the OTHER attention slot (used by the next layer's GEMM)
    if (lane == 0) {
        int os = slot ^ 1;
        g_as[(size_t)os * NN + n] = 0.f;
        g_ad[(size_t)os * NN + n] = 0.f;
    }
}

// ---------------- host ----------------
extern "C" void kernel_launch(void* const* d_in, const int* in_sizes, int n_in,
                              void* d_out, int out_size) {
    const float* x       = (const float*)d_in[0];
    const int*   ei32    = (const int*)d_in[1];
    const float* W_in    = (const float*)d_in[2];
    const float* b_in    = (const float*)d_in[3];
    const float* W_h     = (const float*)d_in[4];
    const float* b_h     = (const float*)d_in[5];
    const float* W_gat   = (const float*)d_in[6];
    const float* att_src = (const float*)d_in[7];
    const float* att_dst = (const float*)d_in[8];
    const float* W_l     = (const float*)d_in[9];
    const float* b_l     = (const float*)d_in[10];
    const float* ln_g    = (const float*)d_in[11];
    const float* ln_b    = (const float*)d_in[12];
    const float* betas   = (const float*)d_in[13];
    const float* W_pred  = (const float*)d_in[14];
    const float* b_pred  = (const float*)d_in[15];
    float*       out     = (float*)d_out;

    float *ph, *pxh, *pxl, *pxloc;
    uint32_t *pinh, *pinl, *pah, *pal;
    cudaGetSymbolAddress((void**)&ph,    g_h);
    cudaGetSymbolAddress((void**)&pxh,   g_xh);
    cudaGetSymbolAddress((void**)&pxl,   g_xl);
    cudaGetSymbolAddress((void**)&pxloc, g_xlocal);
    cudaGetSymbolAddress((void**)&pinh,  g_inh);
    cudaGetSymbolAddress((void**)&pinl,  g_inl);
    cudaGetSymbolAddress((void**)&pah,   g_ah);
    cudaGetSymbolAddress((void**)&pal,   g_al);

    const int dynsmem = 2 * 4 * SZW * 4;   // 81920 bytes
    static int attr_set = 0;
    if (!attr_set) {
        cudaFuncSetAttribute(mma_gemm_k, cudaFuncAttributeMaxDynamicSharedMemorySize, dynsmem);
        attr_set = 1;
    }

    dim3 gE((EE + 255) / 256);
    dim3 gN((NN + 255) / 256);
    dim3 gW((NN + 7) / 8);
    dim3 gG((NN + 31) / 32);
    dim3 gM((NN + 127) / 128, 1);
    dim3 gM3((NN + 127) / 128, 3);

    // CSR + one-time splits
    zero_k<<<gN, 256>>>();
    decode_deg_k<<<gE, 256>>>(ei32);
    split_w_k<<<(10 * 64 * 128 + 255) / 256, 256>>>(W_in, W_h, W_gat, W_l);
    split_x_k<<<(NN * 32 + 255) / 256, 256>>>(x);
    pscan_k<<<NSB, SB>>>();
    bscan_k<<<1, 128>>>();
    addoff_k<<<gN, 256>>>();
    scat_k<<<gE, 256>>>();

    // input projection: x @ W_in + b_in -> split only
    {
        GemmArgs2 a{};
        a.wslot[0] = 0; a.bias[0] = b_in; a.out[0] = nullptr; a.epi[0] = 1;
        a.emit_split = 1; a.attn_w = -1;
        mma_gemm_k<<<gM, 256, dynsmem>>>(pinh, pinl, a);
    }

    for (int i = 0; i < LL; i++) {
        GemmArgs2 a{};
        a.wslot[0] = 1 + 3 * i;     a.bias[0] = b_h + i * DD; a.out[0] = ph;  a.epi[0] = 2;
        a.wslot[1] = 1 + 3 * i + 1; a.bias[1] = nullptr;      a.out[1] = pxh; a.epi[1] = 0;
        a.wslot[2] = 1 + 3 * i + 2; a.bias[2] = b_l + i * DD; a.out[2] = pxl; a.epi[2] = 1;
        a.emit_split = 0;
        a.attn_w = 1; a.attn_slot = i & 1;
        a.attn_a = att_src + i * DD; a.attn_d = att_dst + i * DD;
        mma_gemm_k<<<gM3, 256, dynsmem>>>(pah, pal, a);

        aggfuse_k<<<gW, 256>>>(pxh, pxl, ph,
                               ln_g + i * DD, ln_b + i * DD, betas + i * DD,
                               i == 0, i & 1);
    }

    gemm_small_k<OUTD><<<gG, 256>>>(pxloc, W_pred, b_pred, out);
}

// round 12
// speedup vs baseline: 1.7997x; 1.0260x over previous
#include <cuda_runtime.h>
#include <cuda_bf16.h>
#include <math.h>
#include <stdint.h>

#define NN   50000
#define EE   800000
#define DD   128
#define LL   3
#define OUTD 40
#define SB   512
#define NSB  ((NN + SB - 1) / SB)   // 98
#define PADW 20
#define SZW  (128 * PADW)           // words per smem tile (2560)

// ---------------- scratch (device globals; no allocation allowed) ----------------
__device__ float    g_h[NN * DD];
__device__ float    g_xh[NN * DD];
__device__ float    g_xl[NN * DD];
__device__ float    g_xlocal[NN * DD];
__device__ float    g_as[2 * NN];   // double-buffered attention logit accumulators
__device__ float    g_ad[2 * NN];
__device__ float    g_ew[EE];
__device__ int      g_deg[NN];
__device__ int      g_fill[NN];
__device__ int      g_rowptr[NN + 1];
__device__ int      g_esrc[EE];
__device__ int      g_src[EE];
__device__ int      g_dst[EE];
__device__ int      g_bsum[NSB];
__device__ int      g_boff[128];
// packed bf16 pairs (hi/lo) along k: [row][64 words]
__device__ uint32_t g_inh[NN * 64];
__device__ uint32_t g_inl[NN * 64];
__device__ uint32_t g_ah[NN * 64];
__device__ uint32_t g_al[NN * 64];
// pre-split weights: [wslot][n][64 words], 10 slots
__device__ uint32_t g_wsh[10 * 128 * 64];
__device__ uint32_t g_wsl[10 * 128 * 64];

__device__ __forceinline__ void bsplit(float v, uint32_t& h, uint32_t& l) {
    __nv_bfloat16 bh = __float2bfloat16_rn(v);
    float r = v - __bfloat162float(bh);
    __nv_bfloat16 bl = __float2bfloat16_rn(r);
    h = (uint32_t)__bfloat16_as_ushort(bh);
    l = (uint32_t)__bfloat16_as_ushort(bl);
}

__device__ __forceinline__ void cp16(void* dst_s, const void* src_g) {
    uint32_t d = (uint32_t)__cvta_generic_to_shared(dst_s);
    asm volatile("cp.async.cg.shared.global [%0], [%1], 16;" :: "r"(d), "l"(src_g));
}

// ---------------- edge decode + degree histogram (fused) ----------------
__global__ void decode_deg_k(const int* __restrict__ ei32) {
    bool is64 = (ei32[1] == 0 && ei32[3] == 0 && ei32[5] == 0 && ei32[7] == 0);
    int e = blockIdx.x * blockDim.x + threadIdx.x;
    if (e < EE) {
        int s, d;
        if (is64) {
            s = ei32[2 * (size_t)e];
            d = ei32[2 * ((size_t)EE + e)];
        } else {
            s = ei32[e];
            d = ei32[EE + e];
        }
        g_src[e] = s;
        g_dst[e] = d;
        atomicAdd(&g_deg[d], 1);
    }
}

__global__ void zero_k() {
    int i = blockIdx.x * blockDim.x + threadIdx.x;
    if (i < NN) {
        g_deg[i] = 0; g_fill[i] = 0;
        g_as[i] = 0.f; g_ad[i] = 0.f;
        g_as[NN + i] = 0.f; g_ad[NN + i] = 0.f;
    }
}

__global__ void pscan_k() {
    __shared__ int sh[SB];
    int t = threadIdx.x;
    int i = blockIdx.x * SB + t;
    int v = (i < NN) ? g_deg[i] : 0;
    sh[t] = v;
    __syncthreads();
    for (int o = 1; o < SB; o <<= 1) {
        int a = (t >= o) ? sh[t - o] : 0;
        __syncthreads();
        sh[t] += a;
        __syncthreads();
    }
    if (i < NN) g_rowptr[i] = sh[t] - v;
    if (t == SB - 1) g_bsum[blockIdx.x] = sh[t];
}

__global__ void bscan_k() {
    __shared__ int sh[128];
    int t = threadIdx.x;
    int v = (t < NSB) ? g_bsum[t] : 0;
    sh[t] = v;
    __syncthreads();
    for (int o = 1; o < 128; o <<= 1) {
        int a = (t >= o) ? sh[t - o] : 0;
        __syncthreads();
        sh[t] += a;
        __syncthreads();
    }
    g_boff[t] = sh[t] - v;
}

__global__ void addoff_k() {
    int i = blockIdx.x * blockDim.x + threadIdx.x;
    if (i < NN) g_rowptr[i] += g_boff[i / SB];
    if (i == 0) g_rowptr[NN] = EE;
}

__global__ void scat_k() {
    int e = blockIdx.x * blockDim.x + threadIdx.x;
    if (e < EE) {
        int d = g_dst[e];
        int p = g_rowptr[d] + atomicAdd(&g_fill[d], 1);
        g_esrc[p] = g_src[e];
    }
}

// ---------------- one-time weight split ----------------
__global__ void split_w_k(const float* __restrict__ W_in, const float* __restrict__ W_h,
                          const float* __restrict__ W_gat, const float* __restrict__ W_l) {
    int idx = blockIdx.x * blockDim.x + threadIdx.x;   // 10*64*128
    if (idx >= 10 * 64 * 128) return;
    int w   = idx >> 13;
    int kw  = (idx >> 7) & 63;
    int n   = idx & 127;
    const float* base;
    if (w == 0) base = W_in;
    else {
        int layer = (w - 1) / 3, t = (w - 1) % 3;
        base = (t == 0 ? W_h : t == 1 ? W_gat : W_l) + (size_t)layer * DD * DD;
    }
    float v0 = base[(size_t)(2 * kw) * DD + n];
    float v1 = base[(size_t)(2 * kw + 1) * DD + n];
    uint32_t h0, l0, h1, l1;
    bsplit(v0, h0, l0); bsplit(v1, h1, l1);
    g_wsh[(size_t)w * 8192 + n * 64 + kw] = h0 | (h1 << 16);
    g_wsl[(size_t)w * 8192 + n * 64 + kw] = l0 | (l1 << 16);
}

// ---------------- one-time input split ----------------
__global__ void split_x_k(const float* __restrict__ x) {
    int t = blockIdx.x * blockDim.x + threadIdx.x;     // NN*32
    if (t >= NN * 32) return;
    int row = t >> 5, q = t & 31;
    float4 v = ((const float4*)x)[(size_t)row * 32 + q];
    uint32_t hx, lx, hy, ly, hz, lz, hw, lw;
    bsplit(v.x, hx, lx); bsplit(v.y, hy, ly);
    bsplit(v.z, hz, lz); bsplit(v.w, hw, lw);
    size_t o = (size_t)row * 64 + 2 * q;
    g_inh[o]     = hx | (hy << 16);
    g_inh[o + 1] = hz | (hw << 16);
    g_inl[o]     = lx | (ly << 16);
    g_inl[o + 1] = lz | (lw << 16);
}

// ---------------- bf16x3 GEMM, cp.async double-buffered, fused attn logits ----------------
struct GemmArgs2 {
    int          wslot[3];
    const float* bias[3];
    float*       out[3];
    int          epi[3];     // 0 none, 1 bias, 2 bias+relu
    int          emit_split;
    int          attn_w;     // which w computes attention logits (-1 = none)
    int          attn_slot;  // accumulator slot (0/1)
    const float* attn_a;
    const float* attn_d;
};

extern __shared__ uint32_t smem_dyn[];

__global__ __launch_bounds__(256, 2)
void mma_gemm_k(const uint32_t* __restrict__ Ah, const uint32_t* __restrict__ Al,
                GemmArgs2 args) {
    const int tid  = threadIdx.x;
    const int lane = tid & 31;
    const int wid  = tid >> 5;
    const int wm   = (wid >> 1) * 32;
    const int wn   = (wid & 1) * 64;
    const int row0 = blockIdx.x * 128;
    const int w    = blockIdx.y;

    const uint32_t* Wh = g_wsh + (size_t)args.wslot[w] * 8192;
    const uint32_t* Wl = g_wsl + (size_t)args.wslot[w] * 8192;

    const int ar = lane >> 2;
    const int ac = lane & 3;

    float acc[2][8][4];
#pragma unroll
    for (int i = 0; i < 2; i++)
#pragma unroll
        for (int j = 0; j < 8; j++)
#pragma unroll
            for (int c = 0; c < 4; c++) acc[i][j][c] = 0.f;

    auto stage = [&](int kc, int s) {
        uint32_t* bAh = smem_dyn + s * 4 * SZW;
        uint32_t* bAl = bAh + SZW;
        uint32_t* bWh = bAl + SZW;
        uint32_t* bWl = bWh + SZW;
        const int kwc = kc >> 1;
#pragma unroll
        for (int t = tid; t < 512; t += 256) {
            int m = t >> 2, q = t & 3;
            int row = row0 + m;
            uint32_t* dh = &bAh[m * PADW + 4 * q];
            uint32_t* dl = &bAl[m * PADW + 4 * q];
            if (row < NN) {
                size_t o = (size_t)row * 64 + kwc + 4 * q;
                cp16(dh, &Ah[o]);
                cp16(dl, &Al[o]);
            } else {
                *(uint4*)dh = make_uint4(0, 0, 0, 0);
                *(uint4*)dl = make_uint4(0, 0, 0, 0);
            }
        }
#pragma unroll
        for (int t = tid; t < 512; t += 256) {
            int n = t >> 2, q = t & 3;
            size_t o = (size_t)n * 64 + kwc + 4 * q;
            cp16(&bWh[n * PADW + 4 * q], &Wh[o]);
            cp16(&bWl[n * PADW + 4 * q], &Wl[o]);
        }
        asm volatile("cp.async.commit_group;");
    };

    stage(0, 0);

#pragma unroll
    for (int c = 0; c < 4; c++) {
        if (c < 3) stage((c + 1) * 32, (c + 1) & 1);
        if (c < 3) asm volatile("cp.async.wait_group 1;");
        else       asm volatile("cp.async.wait_group 0;");
        __syncthreads();

        const uint32_t* bAh = smem_dyn + (c & 1) * 4 * SZW;
        const uint32_t* bAl = bAh + SZW;
        const uint32_t* bWh = bAl + SZW;
        const uint32_t* bWl = bWh + SZW;

#pragma unroll
        for (int s = 0; s < 2; s++) {
            const int kb = s * 8;
            uint32_t ah[2][4], al[2][4];
#pragma unroll
            for (int i = 0; i < 2; i++) {
                int m = wm + i * 16 + ar;
                ah[i][0] = bAh[m * PADW + kb + ac];
                ah[i][1] = bAh[(m + 8) * PADW + kb + ac];
                ah[i][2] = bAh[m * PADW + kb + ac + 4];
                ah[i][3] = bAh[(m + 8) * PADW + kb + ac + 4];
                al[i][0] = bAl[m * PADW + kb + ac];
                al[i][1] = bAl[(m + 8) * PADW + kb + ac];
                al[i][2] = bAl[m * PADW + kb + ac + 4];
                al[i][3] = bAl[(m + 8) * PADW + kb + ac + 4];
            }
#pragma unroll
            for (int j = 0; j < 8; j++) {
                int n = wn + j * 8 + ar;
                uint32_t bh0 = bWh[n * PADW + kb + ac];
                uint32_t bh1 = bWh[n * PADW + kb + ac + 4];
                uint32_t bl0 = bWl[n * PADW + kb + ac];
                uint32_t bl1 = bWl[n * PADW + kb + ac + 4];
#pragma unroll
                for (int i = 0; i < 2; i++) {
                    asm volatile(
                        "mma.sync.aligned.m16n8k16.row.col.f32.bf16.bf16.f32 "
                        "{%0,%1,%2,%3}, {%4,%5,%6,%7}, {%8,%9}, {%0,%1,%2,%3};"
                        : "+f"(acc[i][j][0]), "+f"(acc[i][j][1]),
                          "+f"(acc[i][j][2]), "+f"(acc[i][j][3])
                        : "r"(ah[i][0]), "r"(ah[i][1]), "r"(ah[i][2]), "r"(ah[i][3]),
                          "r"(bh0), "r"(bh1));
                    asm volatile(
                        "mma.sync.aligned.m16n8k16.row.col.f32.bf16.bf16.f32 "
                        "{%0,%1,%2,%3}, {%4,%5,%6,%7}, {%8,%9}, {%0,%1,%2,%3};"
                        : "+f"(acc[i][j][0]), "+f"(acc[i][j][1]),
                          "+f"(acc[i][j][2]), "+f"(acc[i][j][3])
                        : "r"(ah[i][0]), "r"(ah[i][1]), "r"(ah[i][2]), "r"(ah[i][3]),
                          "r"(bl0), "r"(bl1));
                    asm volatile(
                        "mma.sync.aligned.m16n8k16.row.col.f32.bf16.bf16.f32 "
                        "{%0,%1,%2,%3}, {%4,%5,%6,%7}, {%8,%9}, {%0,%1,%2,%3};"
                        : "+f"(acc[i][j][0]), "+f"(acc[i][j][1]),
                          "+f"(acc[i][j][2]), "+f"(acc[i][j][3])
                        : "r"(al[i][0]), "r"(al[i][1]), "r"(al[i][2]), "r"(al[i][3]),
                          "r"(bh0), "r"(bh1));
                }
            }
        }
        __syncthreads();
    }

    // ---- epilogue ----
    const int epi = args.epi[w];
    const float* bias = args.bias[w];
    float* out = args.out[w];
    const int emit = args.emit_split;
    const bool do_attn = (w == args.attn_w);
    float* asb = g_as + (size_t)args.attn_slot * NN;
    float* adb = g_ad + (size_t)args.attn_slot * NN;
    float ps[2] = {0.f, 0.f}, pd[2] = {0.f, 0.f};
    float ps2[2] = {0.f, 0.f}, pd2[2] = {0.f, 0.f};

#pragma unroll
    for (int i = 0; i < 2; i++) {
#pragma unroll
        for (int j = 0; j < 8; j++) {
            int cc = wn + j * 8 + ac * 2;
            float bx = 0.f, by = 0.f;
            if (epi >= 1) { bx = bias[cc]; by = bias[cc + 1]; }
            float c0 = acc[i][j][0] + bx, c1 = acc[i][j][1] + by;
            float c2 = acc[i][j][2] + bx, c3 = acc[i][j][3] + by;
            if (epi == 2) {
                c0 = fmaxf(c0, 0.f); c1 = fmaxf(c1, 0.f);
                c2 = fmaxf(c2, 0.f); c3 = fmaxf(c3, 0.f);
            }
            if (do_attn) {
                float a0 = args.attn_a[cc], a1 = args.attn_a[cc + 1];
                float d0 = args.attn_d[cc], d1 = args.attn_d[cc + 1];
                ps[i]  += c0 * a0 + c1 * a1;
                pd[i]  += c0 * d0 + c1 * d1;
                ps2[i] += c2 * a0 + c3 * a1;
                pd2[i] += c2 * d0 + c3 * d1;
            }
            int r0 = row0 + wm + i * 16 + ar;
            if (out) {
                if (r0 < NN)     *(float2*)&out[(size_t)r0 * DD + cc]       = make_float2(c0, c1);
                if (r0 + 8 < NN) *(float2*)&out[(size_t)(r0 + 8) * DD + cc] = make_float2(c2, c3);
            }
            if (emit) {
                uint32_t h0, l0, h1, l1;
                if (r0 < NN) {
                    bsplit(c0, h0, l0); bsplit(c1, h1, l1);
                    g_ah[(size_t)r0 * 64 + (cc >> 1)] = h0 | (h1 << 16);
                    g_al[(size_t)r0 * 64 + (cc >> 1)] = l0 | (l1 << 16);
                }
                if (r0 + 8 < NN) {
                    bsplit(c2, h0, l0); bsplit(c3, h1, l1);
                    g_ah[(size_t)(r0 + 8) * 64 + (cc >> 1)] = h0 | (h1 << 16);
                    g_al[(size_t)(r0 + 8) * 64 + (cc >> 1)] = l0 | (l1 << 16);
                }
            }
        }
    }

    if (do_attn) {
#pragma unroll
        for (int i = 0; i < 2; i++) {
#pragma unroll
            for (int o = 1; o <= 2; o <<= 1) {
                ps[i]  += __shfl_xor_sync(0xFFFFFFFFu, ps[i],  o);
                pd[i]  += __shfl_xor_sync(0xFFFFFFFFu, pd[i],  o);
                ps2[i] += __shfl_xor_sync(0xFFFFFFFFu, ps2[i], o);
                pd2[i] += __shfl_xor_sync(0xFFFFFFFFu, pd2[i], o);
            }
            if (ac == 0) {
                int r0 = row0 + wm + i * 16 + ar;
                if (r0 < NN) {
                    atomicAdd(&asb[r0], ps[i]);
                    atomicAdd(&adb[r0], pd[i]);
                }
                if (r0 + 8 < NN) {
                    atomicAdd(&asb[r0 + 8], ps2[i]);
                    atomicAdd(&adb[r0 + 8], pd2[i]);
                }
            }
        }
    }
}

// ---------------- small FFMA GEMM for the prediction head (NCOL=40) ----------------
template <int NCOL>
__global__ void gemm_small_k(const float* __restrict__ A, const float* __restrict__ W,
                             const float* __restrict__ bias, float* __restrict__ C) {
    constexpr int ROWS = 32;
    constexpr int KT   = 32;
    __shared__ float sA[ROWS][DD];
    __shared__ float sW[KT][NCOL];
    int tid  = threadIdx.x;
    int row0 = blockIdx.x * ROWS;

    {
        const float4* Af  = (const float4*)A;
        float4*       sAf = (float4*)sA;
#pragma unroll
        for (int i = 0; i < 4; i++) {
            int idx = tid + i * 256;
            int r = idx >> 5, c = idx & 31;
            float4 v = make_float4(0.f, 0.f, 0.f, 0.f);
            if (row0 + r < NN) v = Af[(size_t)(row0 + r) * 32 + c];
            sAf[idx] = v;
        }
    }

    int tx = tid & 31, ty = tid >> 5;
    const int col = tx * 4;
    float acc[4][4];
#pragma unroll
    for (int i = 0; i < 4; i++)
#pragma unroll
        for (int j = 0; j < 4; j++) acc[i][j] = 0.f;

    for (int kt = 0; kt < DD; kt += KT) {
        __syncthreads();
        {
            const float4* Wf  = (const float4*)(W + kt * NCOL);
            float4*       sWf = (float4*)sW;
            constexpr int T4 = KT * NCOL / 4;
            for (int i = tid; i < T4; i += 256) sWf[i] = Wf[i];
        }
        __syncthreads();
#pragma unroll
        for (int k = 0; k < KT; k++) {
            float4 wv = make_float4(0.f, 0.f, 0.f, 0.f);
            if (col < NCOL) wv = *(const float4*)&sW[k][col];
#pragma unroll
            for (int i = 0; i < 4; i++) {
                float a = sA[ty + i * 8][kt + k];
                acc[i][0] += a * wv.x;
                acc[i][1] += a * wv.y;
                acc[i][2] += a * wv.z;
                acc[i][3] += a * wv.w;
            }
        }
    }

    if (col < NCOL) {
        float4 bv = *(const float4*)&bias[col];
#pragma unroll
        for (int i = 0; i < 4; i++) {
            int row = row0 + ty + i * 8;
            if (row < NN) {
                float4 o;
                o.x = acc[i][0] + bv.x;
                o.y = acc[i][1] + bv.y;
                o.z = acc[i][2] + bv.z;
                o.w = acc[i][3] + bv.w;
                *(float4*)&C[(size_t)row * NCOL + col] = o;
            }
        }
    }
}

// ---------------- fused GAT aggregate + pointwise + emit split ----------------
__global__ void aggfuse_k(const float* __restrict__ xh,
                          const float* __restrict__ xlbuf, const float* __restrict__ hbuf,
                          const float* __restrict__ lng, const float* __restrict__ lnb,
                          const float* __restrict__ betas, int first, int slot) {
    int n    = (blockIdx.x * blockDim.x + threadIdx.x) >> 5;
    int lane = threadIdx.x & 31;
    if (n >= NN) return;
    const float* asb = g_as + (size_t)slot * NN;
    const float* adb = g_ad + (size_t)slot * NN;
    int s0 = g_rowptr[n], s1 = g_rowptr[n + 1];
    float adn = adb[n];

    // online softmax over this lane's strided edges; cache post-leaky logits
    float m = -1e30f, d = 0.f;
    for (int i = s0 + lane; i < s1; i += 32) {
        int s  = g_esrc[i];
        float e = asb[s] + adn;
        e = e > 0.f ? e : 0.2f * e;
        g_ew[i] = e;
        if (e > m) { d = d * __expf(m - e) + 1.f; m = e; }
        else       { d += __expf(e - m); }
    }
#pragma unroll
    for (int o = 16; o; o >>= 1) {
        float mo = __shfl_xor_sync(0xFFFFFFFFu, m, o);
        float do_ = __shfl_xor_sync(0xFFFFFFFFu, d, o);
        if (mo > m) { d = d * __expf(m - mo) + do_; m = mo; }
        else        { d += do_ * __expf(mo - m); }
    }
    float inv = 1.f / (d + 1e-16f);

    float4 ag = make_float4(0.f, 0.f, 0.f, 0.f);
    for (int base = s0; base < s1; base += 32) {
        int idx = base + lane;
        float w = 0.f;
        int   s = 0;
        if (idx < s1) {
            s = g_esrc[idx];
            w = __expf(g_ew[idx] - m) * inv;
        }
        int cnt = min(32, s1 - base);
        for (int j = 0; j < cnt; j++) {
            float wj = __shfl_sync(0xFFFFFFFFu, w, j);
            int   sj = __shfl_sync(0xFFFFFFFFu, s, j);
            float4 v = ((const float4*)(xh + (size_t)sj * DD))[lane];
            ag.x += wj * v.x; ag.y += wj * v.y;
            ag.z += wj * v.z; ag.w += wj * v.w;
        }
    }

    // ---- pointwise (agg stays in registers) ----
    size_t off = (size_t)n * DD;
    float4 xl = ((const float4*)(xlbuf + off))[lane];
    float4 xn;
    xn.x = fmaxf(ag.x + xl.x, 0.f);
    xn.y = fmaxf(ag.y + xl.y, 0.f);
    xn.z = fmaxf(ag.z + xl.z, 0.f);
    xn.w = fmaxf(ag.w + xl.w, 0.f);

    float4 hh = ((const float4*)(hbuf + off))[lane];
    float4 t;
    t.x = hh.x * xn.x; t.y = hh.y * xn.y; t.z = hh.z * xn.z; t.w = hh.w * xn.w;

    float sum = t.x + t.y + t.z + t.w;
#pragma unroll
    for (int o = 16; o; o >>= 1) sum += __shfl_xor_sync(0xFFFFFFFFu, sum, o);
    float mu = sum * (1.f / 128.f);

    float4 dc;
    dc.x = t.x - mu; dc.y = t.y - mu; dc.z = t.z - mu; dc.w = t.w - mu;
    float ss = dc.x * dc.x + dc.y * dc.y + dc.z * dc.z + dc.w * dc.w;
#pragma unroll
    for (int o = 16; o; o >>= 1) ss += __shfl_xor_sync(0xFFFFFFFFu, ss, o);
    float rs = rsqrtf(ss * (1.f / 128.f) + 1e-5f);

    float4 g  = ((const float4*)lng)[lane];
    float4 b  = ((const float4*)lnb)[lane];
    float4 be = ((const float4*)betas)[lane];
    be.x = 1.f / (1.f + __expf(-be.x));
    be.y = 1.f / (1.f + __expf(-be.y));
    be.z = 1.f / (1.f + __expf(-be.z));
    be.w = 1.f / (1.f + __expf(-be.w));

    float4 y;
    y.x = dc.x * rs * g.x + b.x;
    y.y = dc.y * rs * g.y + b.y;
    y.z = dc.z * rs * g.z + b.z;
    y.w = dc.w * rs * g.w + b.w;

    float4 xo;
    xo.x = (1.f - be.x) * y.x + be.x * xn.x;
    xo.y = (1.f - be.y) * y.y + be.y * xn.y;
    xo.z = (1.f - be.z) * y.z + be.z * xn.z;
    xo.w = (1.f - be.w) * y.w + be.w * xn.w;

    // emit bf16 split of new x
    {
        uint32_t hx, lx, hy, ly, hz, lz, hw, lw;
        bsplit(xo.x, hx, lx); bsplit(xo.y, hy, ly);
        bsplit(xo.z, hz, lz); bsplit(xo.w, hw, lw);
        size_t o2 = (size_t)n * 64 + 2 * lane;
        g_ah[o2]     = hx | (hy << 16);
        g_ah[o2 + 1] = hz | (hw << 16);
        g_al[o2]     = lx | (ly << 16);
        g_al[o2 + 1] = lz | (lw << 16);
    }

    if (first) {
        ((float4*)(g_xlocal + off))[lane] = xo;
    } else {
        float4 p = ((const float4*)(g_xlocal + off))[lane];
        p.x += xo.x; p.y += xo.y; p.z += xo.z; p.w += xo.w;
        ((float4*)(g_xlocal + off))[lane] = p;
    }

    // zero the OTHER attention slot (used by the next layer's GEMM)
    if (lane == 0) {
        int os = slot ^ 1;
        g_as[(size_t)os * NN + n] = 0.f;
        g_ad[(size_t)os * NN + n] = 0.f;
    }
}

// ---------------- host ----------------
extern "C" void kernel_launch(void* const* d_in, const int* in_sizes, int n_in,
                              void* d_out, int out_size) {
    const float* x       = (const float*)d_in[0];
    const int*   ei32    = (const int*)d_in[1];
    const float* W_in    = (const float*)d_in[2];
    const float* b_in    = (const float*)d_in[3];
    const float* W_h     = (const float*)d_in[4];
    const float* b_h     = (const float*)d_in[5];
    const float* W_gat   = (const float*)d_in[6];
    const float* att_src = (const float*)d_in[7];
    const float* att_dst = (const float*)d_in[8];
    const float* W_l     = (const float*)d_in[9];
    const float* b_l     = (const float*)d_in[10];
    const float* ln_g    = (const float*)d_in[11];
    const float* ln_b    = (const float*)d_in[12];
    const float* betas   = (const float*)d_in[13];
    const float* W_pred  = (const float*)d_in[14];
    const float* b_pred  = (const float*)d_in[15];
    float*       out     = (float*)d_out;

    float *ph, *pxh, *pxl, *pxloc;
    uint32_t *pinh, *pinl, *pah, *pal;
    cudaGetSymbolAddress((void**)&ph,    g_h);
    cudaGetSymbolAddress((void**)&pxh,   g_xh);
    cudaGetSymbolAddress((void**)&pxl,   g_xl);
    cudaGetSymbolAddress((void**)&pxloc, g_xlocal);
    cudaGetSymbolAddress((void**)&pinh,  g_inh);
    cudaGetSymbolAddress((void**)&pinl,  g_inl);
    cudaGetSymbolAddress((void**)&pah,   g_ah);
    cudaGetSymbolAddress((void**)&pal,   g_al);

    const int dynsmem = 2 * 4 * SZW * 4;   // 81920 bytes
    static cudaStream_t s_side = nullptr;
    static cudaEvent_t  ev_fork = nullptr, ev_join = nullptr;
    if (!s_side) {
        cudaFuncSetAttribute(mma_gemm_k, cudaFuncAttributeMaxDynamicSharedMemorySize, dynsmem);
        cudaStreamCreateWithFlags(&s_side, cudaStreamNonBlocking);
        cudaEventCreateWithFlags(&ev_fork, cudaEventDisableTiming);
        cudaEventCreateWithFlags(&ev_join, cudaEventDisableTiming);
    }

    dim3 gE((EE + 255) / 256);
    dim3 gN((NN + 255) / 256);
    dim3 gW((NN + 7) / 8);
    dim3 gG((NN + 31) / 32);
    dim3 gM((NN + 127) / 128, 1);
    dim3 gM3((NN + 127) / 128, 3);

    // zeroing on main (prereq for BOTH branches)
    zero_k<<<gN, 256>>>();

    // fork: CSR build on side stream
    cudaEventRecord(ev_fork, 0);
    cudaStreamWaitEvent(s_side, ev_fork, 0);
    decode_deg_k<<<gE, 256, 0, s_side>>>(ei32);
    pscan_k<<<NSB, SB, 0, s_side>>>();
    bscan_k<<<1, 128, 0, s_side>>>();
    addoff_k<<<gN, 256, 0, s_side>>>();
    scat_k<<<gE, 256, 0, s_side>>>();
    cudaEventRecord(ev_join, s_side);

    // main: splits + dense prologue (independent of CSR)
    split_w_k<<<(10 * 64 * 128 + 255) / 256, 256>>>(W_in, W_h, W_gat, W_l);
    split_x_k<<<(NN * 32 + 255) / 256, 256>>>(x);

    // input projection: x @ W_in + b_in -> split only
    {
        GemmArgs2 a{};
        a.wslot[0] = 0; a.bias[0] = b_in; a.out[0] = nullptr; a.epi[0] = 1;
        a.emit_split = 1; a.attn_w = -1;
        mma_gemm_k<<<gM, 256, dynsmem>>>(pinh, pinl, a);
    }

    // layer 0 GEMM is also CSR-independent
    {
        GemmArgs2 a{};
        a.wslot[0] = 1; a.bias[0] = b_h; a.out[0] = ph;  a.epi[0] = 2;
        a.wslot[1] = 2; a.bias[1] = nullptr; a.out[1] = pxh; a.epi[1] = 0;
        a.wslot[2] = 3; a.bias[2] = b_l; a.out[2] = pxl; a.epi[2] = 1;
        a.emit_split = 0;
        a.attn_w = 1; a.attn_slot = 0;
        a.attn_a = att_src; a.attn_d = att_dst;
        mma_gemm_k<<<gM3, 256, dynsmem>>>(pah, pal, a);
    }

    // join: aggfuse needs the CSR
    cudaStreamWaitEvent(0, ev_join, 0);

    for (int i = 0; i < LL; i++) {
        if (i > 0) {
            GemmArgs2 a{};
            a.wslot[0] = 1 + 3 * i;     a.bias[0] = b_h + i * DD; a.out[0] = ph;  a.epi[0] = 2;
            a.wslot[1] = 1 + 3 * i + 1; a.bias[1] = nullptr;      a.out[1] = pxh; a.epi[1] = 0;
            a.wslot[2] = 1 + 3 * i + 2; a.bias[2] = b_l + i * DD; a.out[2] = pxl; a.epi[2] = 1;
            a.emit_split = 0;
            a.attn_w = 1; a.attn_slot = i & 1;
            a.attn_a = att_src + i * DD; a.attn_d = att_dst + i * DD;
            mma_gemm_k<<<gM3, 256, dynsmem>>>(pah, pal, a);
        }

        aggfuse_k<<<gW, 256>>>(pxh, pxl, ph,
                               ln_g + i * DD, ln_b + i * DD, betas + i * DD,
                               i == 0, i & 1);
    }

    gemm_small_k<OUTD><<<gG, 256>>>(pxloc, W_pred, b_pred, out);
}